// round 1
// baseline (speedup 1.0000x reference)
#include <cuda_runtime.h>
#include <cstdint>
#include <math.h>

// Problem constants
constexpr int BATCH  = 2;
constexpr int SEQ    = 2048;
constexpr int HIDDEN = 2048;
constexpr int NHEADS = 16;
constexpr int NKVH   = 4;
constexpr int HDIM   = 128;
constexpr float QK_SCALE = 0.08838834764831845f; // 1/sqrt(128)

// Scratch (device globals: allocation-free rule)
__device__ float g_Q[BATCH * SEQ * HIDDEN];        // [B,S,16,128] flattened
__device__ float g_K[BATCH * SEQ * NKVH * HDIM];   // [B,S,4,128]
__device__ float g_V[BATCH * SEQ * NKVH * HDIM];
__device__ float g_ctx[BATCH * SEQ * HIDDEN];      // attention output [B,S,16,128]

// ---------------------------------------------------------------------------
// SGEMM: C[M,N] = A[M,K] @ Bm[K,N], all row-major. BM=BN=128, BK=16,
// 256 threads, 8x8 register microtile per thread. M,N,K multiples of 128/16.
// ---------------------------------------------------------------------------
__global__ __launch_bounds__(256, 2)
void sgemm128(const float* __restrict__ A, const float* __restrict__ Bm,
              float* __restrict__ C, int M, int N, int K) {
    __shared__ float As[16 * 128];   // transposed: As[k][m]
    __shared__ float Bs[16 * 128];   // Bs[k][n]

    const int tid = threadIdx.x;
    const int bx = blockIdx.x, by = blockIdx.y;
    const int ty = tid >> 4, tx = tid & 15;

    float acc[8][8];
#pragma unroll
    for (int i = 0; i < 8; i++)
#pragma unroll
        for (int j = 0; j < 8; j++) acc[i][j] = 0.f;

    const int ra = tid >> 1;           // 0..127  (A tile row)
    const int ka = (tid & 1) * 8;      // 0 or 8  (A k offset)
    const int kb = tid >> 4;           // 0..15   (B tile k)
    const int cb = (tid & 15) * 8;     // 0..120  (B tile col)

    const float* Aptr = A + (size_t)(by * 128 + ra) * K + ka;
    const float* Bptr = Bm + (size_t)kb * N + bx * 128 + cb;

    for (int k0 = 0; k0 < K; k0 += 16) {
        float4 a0 = *(const float4*)(Aptr + k0);
        float4 a1 = *(const float4*)(Aptr + k0 + 4);
        float4 b0 = *(const float4*)(Bptr + (size_t)k0 * N);
        float4 b1 = *(const float4*)(Bptr + (size_t)k0 * N + 4);

        As[(ka + 0) * 128 + ra] = a0.x;
        As[(ka + 1) * 128 + ra] = a0.y;
        As[(ka + 2) * 128 + ra] = a0.z;
        As[(ka + 3) * 128 + ra] = a0.w;
        As[(ka + 4) * 128 + ra] = a1.x;
        As[(ka + 5) * 128 + ra] = a1.y;
        As[(ka + 6) * 128 + ra] = a1.z;
        As[(ka + 7) * 128 + ra] = a1.w;
        *(float4*)&Bs[kb * 128 + cb]     = b0;
        *(float4*)&Bs[kb * 128 + cb + 4] = b1;
        __syncthreads();

#pragma unroll
        for (int kk = 0; kk < 16; kk++) {
            float a[8], b[8];
            *(float4*)&a[0] = *(const float4*)&As[kk * 128 + ty * 8];
            *(float4*)&a[4] = *(const float4*)&As[kk * 128 + ty * 8 + 4];
            *(float4*)&b[0] = *(const float4*)&Bs[kk * 128 + tx * 8];
            *(float4*)&b[4] = *(const float4*)&Bs[kk * 128 + tx * 8 + 4];
#pragma unroll
            for (int i = 0; i < 8; i++)
#pragma unroll
                for (int j = 0; j < 8; j++)
                    acc[i][j] = fmaf(a[i], b[j], acc[i][j]);
        }
        __syncthreads();
    }

    float* Cp = C + (size_t)(by * 128 + ty * 8) * N + bx * 128 + tx * 8;
#pragma unroll
    for (int i = 0; i < 8; i++) {
        *(float4*)(Cp + (size_t)i * N)     = make_float4(acc[i][0], acc[i][1], acc[i][2], acc[i][3]);
        *(float4*)(Cp + (size_t)i * N + 4) = make_float4(acc[i][4], acc[i][5], acc[i][6], acc[i][7]);
    }
}

// ---------------------------------------------------------------------------
// RoPE (in-place on Q and K); also folds 1/sqrt(Dh) into Q.
// One thread per (b, s, head, pair). pair p handles dims p and p+64.
// ---------------------------------------------------------------------------
__global__ void rope_kernel(float* __restrict__ Qb, float* __restrict__ Kb,
                            const int* __restrict__ pos) {
    const int total = BATCH * SEQ * (NHEADS + NKVH) * 64;
    int idx = blockIdx.x * blockDim.x + threadIdx.x;
    if (idx >= total) return;
    const int p = idx & 63;
    int rest = idx >> 6;
    const int hh = rest % (NHEADS + NKVH);
    const int bs = rest / (NHEADS + NKVH);

    const float fpos = (float)pos[bs];
    const float inv = powf(10000.f, -(float)p * (1.f / 64.f));
    const float ang = fpos * inv;
    float sn, c;
    sincosf(ang, &sn, &c);

    float* base;
    float scale;
    if (hh < NHEADS) {
        base = Qb + (size_t)bs * HIDDEN + hh * HDIM;
        scale = QK_SCALE;
    } else {
        base = Kb + (size_t)bs * (NKVH * HDIM) + (hh - NHEADS) * HDIM;
        scale = 1.f;
    }
    const float x1 = base[p], x2 = base[p + 64];
    base[p]      = (x1 * c - x2 * sn) * scale;
    base[p + 64] = (x2 * c + x1 * sn) * scale;
}

// ---------------------------------------------------------------------------
// Flash attention (causal, GQA). BQ=BK=64, Dh=128, 256 threads.
// Q,K staged transposed in smem (Qt/Kt[d][row]) for LDS.128 in the QK^T phase.
// Scores in smem (row stride 68). O accumulator in registers:
//   thread (r = tid/4, seg = tid&3) owns row r, columns {seg*4 + 16*m + i}.
// ---------------------------------------------------------------------------
constexpr int BQ = 64;
constexpr int BK = 64;
constexpr int SW = 68;
constexpr int ATTN_SMEM_FLOATS = 8192 * 3 + BQ * SW + 3 * BQ;

__global__ __launch_bounds__(256, 1)
void attn_kernel(const float* __restrict__ Qb, const float* __restrict__ Kb,
                 const float* __restrict__ Vb, float* __restrict__ ctx) {
    extern __shared__ float sm[];
    float* Qt   = sm;            // [128][64]
    float* Kt   = Qt + 8192;     // [128][64]
    float* Vs   = Kt + 8192;     // [64][128]
    float* Ssc  = Vs + 8192;     // [64][68]
    float* rowm = Ssc + BQ * SW; // [64]
    float* rowl = rowm + BQ;     // [64]
    float* rowa = rowl + BQ;     // [64]

    const int tid = threadIdx.x;
    const int qt = blockIdx.x, h = blockIdx.y, b = blockIdx.z;
    const int kvh = h >> 2;
    const int q0 = qt * BQ;

    const int r   = tid >> 2;   // 0..63
    const int seg = tid & 3;    // 0..3
    const int ty  = tid >> 4;   // 0..15
    const int tx  = tid & 15;   // 0..15

    // Load Q tile, transposed into Qt[d][r]
    {
        const int dseg = seg * 32;
        const float* src = Qb + (size_t)(b * SEQ + q0 + r) * HIDDEN + h * HDIM + dseg;
#pragma unroll
        for (int i = 0; i < 32; i += 4) {
            float4 v = *(const float4*)(src + i);
            Qt[(dseg + i + 0) * 64 + r] = v.x;
            Qt[(dseg + i + 1) * 64 + r] = v.y;
            Qt[(dseg + i + 2) * 64 + r] = v.z;
            Qt[(dseg + i + 3) * 64 + r] = v.w;
        }
    }
    if (tid < BQ) { rowm[tid] = -INFINITY; rowl[tid] = 0.f; }

    float o[8][4];
#pragma unroll
    for (int m = 0; m < 8; m++)
#pragma unroll
        for (int i = 0; i < 4; i++) o[m][i] = 0.f;
    __syncthreads();

    for (int kt = 0; kt <= qt; kt++) {
        const int k0 = kt * BK;
        // Load K (transposed) and V tiles
        {
            const int dseg = seg * 32;
            const float* ks = Kb + (size_t)(b * SEQ + k0 + r) * (NKVH * HDIM) + kvh * HDIM + dseg;
            const float* vs = Vb + (size_t)(b * SEQ + k0 + r) * (NKVH * HDIM) + kvh * HDIM + dseg;
#pragma unroll
            for (int i = 0; i < 32; i += 4) {
                float4 kv4 = *(const float4*)(ks + i);
                Kt[(dseg + i + 0) * 64 + r] = kv4.x;
                Kt[(dseg + i + 1) * 64 + r] = kv4.y;
                Kt[(dseg + i + 2) * 64 + r] = kv4.z;
                Kt[(dseg + i + 3) * 64 + r] = kv4.w;
                float4 vv4 = *(const float4*)(vs + i);
                *(float4*)&Vs[r * HDIM + dseg + i] = vv4;
            }
        }
        __syncthreads();

        // S = Q K^T (Q pre-scaled by 1/sqrt(Dh)); 4x4 microtile per thread
        float acc[4][4];
#pragma unroll
        for (int i = 0; i < 4; i++)
#pragma unroll
            for (int j = 0; j < 4; j++) acc[i][j] = 0.f;
#pragma unroll 4
        for (int d = 0; d < HDIM; d++) {
            float4 a  = *(const float4*)&Qt[d * 64 + ty * 4];
            float4 bb = *(const float4*)&Kt[d * 64 + tx * 4];
            float av[4] = {a.x, a.y, a.z, a.w};
            float bv[4] = {bb.x, bb.y, bb.z, bb.w};
#pragma unroll
            for (int i = 0; i < 4; i++)
#pragma unroll
                for (int j = 0; j < 4; j++)
                    acc[i][j] = fmaf(av[i], bv[j], acc[i][j]);
        }
        const bool diag = (kt == qt);
#pragma unroll
        for (int i = 0; i < 4; i++) {
            const int qi = ty * 4 + i;
#pragma unroll
            for (int j = 0; j < 4; j++) {
                const int kj = tx * 4 + j;
                float v = acc[i][j];
                if (diag && kj > qi) v = -INFINITY;
                Ssc[qi * SW + kj] = v;
            }
        }
        __syncthreads();

        // Online softmax update: 4 threads per row, 16 cols each
        {
            float* srow = &Ssc[r * SW + seg * 16];
            float mloc = -INFINITY;
#pragma unroll
            for (int j = 0; j < 16; j++) mloc = fmaxf(mloc, srow[j]);
            mloc = fmaxf(mloc, __shfl_xor_sync(0xffffffffu, mloc, 1));
            mloc = fmaxf(mloc, __shfl_xor_sync(0xffffffffu, mloc, 2));
            const float mold = rowm[r];
            const float mnew = fmaxf(mold, mloc);
            float lsum = 0.f;
#pragma unroll
            for (int j = 0; j < 16; j++) {
                float e = __expf(srow[j] - mnew);
                srow[j] = e;
                lsum += e;
            }
            lsum += __shfl_xor_sync(0xffffffffu, lsum, 1);
            lsum += __shfl_xor_sync(0xffffffffu, lsum, 2);
            if (seg == 0) {
                rowa[r] = __expf(mold - mnew);
                rowl[r] = rowl[r] * __expf(mold - mnew) + lsum;
                rowm[r] = mnew;
            }
        }
        __syncthreads();

        // O = alpha * O + P @ V
        {
            const float alpha = rowa[r];
#pragma unroll
            for (int m = 0; m < 8; m++)
#pragma unroll
                for (int i = 0; i < 4; i++) o[m][i] *= alpha;
            const float* srow = &Ssc[r * SW];
#pragma unroll 2
            for (int j = 0; j < BK; j++) {
                const float p = srow[j];
                const float* vrow = &Vs[j * HDIM + seg * 4];
#pragma unroll
                for (int m = 0; m < 8; m++) {
                    float4 v = *(const float4*)(vrow + m * 16);
                    o[m][0] = fmaf(p, v.x, o[m][0]);
                    o[m][1] = fmaf(p, v.y, o[m][1]);
                    o[m][2] = fmaf(p, v.z, o[m][2]);
                    o[m][3] = fmaf(p, v.w, o[m][3]);
                }
            }
        }
        __syncthreads();
    }

    const float invl = 1.f / rowl[r];
    float* dst = ctx + (size_t)(b * SEQ + q0 + r) * HIDDEN + h * HDIM + seg * 4;
#pragma unroll
    for (int m = 0; m < 8; m++) {
        float4 v = make_float4(o[m][0] * invl, o[m][1] * invl,
                               o[m][2] * invl, o[m][3] * invl);
        *(float4*)(dst + m * 16) = v;
    }
}

// ---------------------------------------------------------------------------
// Launch
// ---------------------------------------------------------------------------
extern "C" void kernel_launch(void* const* d_in, const int* in_sizes, int n_in,
                              void* d_out, int out_size) {
    const float* X   = (const float*)d_in[0];
    const int*   pos = (const int*)  d_in[1];
    const float* Wq  = (const float*)d_in[2];
    const float* Wk  = (const float*)d_in[3];
    const float* Wv  = (const float*)d_in[4];
    const float* Wo  = (const float*)d_in[5];
    float* out = (float*)d_out;

    float *Qp, *Kp, *Vp, *Cp;
    cudaGetSymbolAddress((void**)&Qp, g_Q);
    cudaGetSymbolAddress((void**)&Kp, g_K);
    cudaGetSymbolAddress((void**)&Vp, g_V);
    cudaGetSymbolAddress((void**)&Cp, g_ctx);

    const int M = BATCH * SEQ;  // 4096
    dim3 blk(256);

    // QKV projections
    sgemm128<<<dim3(HIDDEN / 128, M / 128), blk>>>(X, Wq, Qp, M, HIDDEN, HIDDEN);
    sgemm128<<<dim3((NKVH * HDIM) / 128, M / 128), blk>>>(X, Wk, Kp, M, NKVH * HDIM, HIDDEN);
    sgemm128<<<dim3((NKVH * HDIM) / 128, M / 128), blk>>>(X, Wv, Vp, M, NKVH * HDIM, HIDDEN);

    // RoPE (+ Q pre-scaling)
    const int rope_total = BATCH * SEQ * (NHEADS + NKVH) * 64;
    rope_kernel<<<(rope_total + 255) / 256, 256>>>(Qp, Kp, pos);

    // Flash attention
    const size_t attn_smem = (size_t)ATTN_SMEM_FLOATS * sizeof(float);
    cudaFuncSetAttribute(attn_kernel, cudaFuncAttributeMaxDynamicSharedMemorySize,
                         (int)attn_smem);
    attn_kernel<<<dim3(SEQ / BQ, NHEADS, BATCH), blk, attn_smem>>>(Qp, Kp, Vp, Cp);

    // Output projection
    sgemm128<<<dim3(HIDDEN / 128, M / 128), blk>>>(Cp, Wo, out, M, HIDDEN, HIDDEN);
}

// round 4
// speedup vs baseline: 1.4555x; 1.4555x over previous
#include <cuda_runtime.h>
#include <cuda_bf16.h>
#include <cstdint>
#include <math.h>

// Problem constants
constexpr int BATCH  = 2;
constexpr int SEQ    = 2048;
constexpr int HIDDEN = 2048;
constexpr int NHEADS = 16;
constexpr int NKVH   = 4;
constexpr int HDIM   = 128;
constexpr float QK_SCALE = 0.08838834764831845f; // 1/sqrt(128)

constexpr int MROWS = BATCH * SEQ;   // 4096
constexpr int KDIM  = HIDDEN;        // 2048

// ---------------------------------------------------------------------------
// Device-global scratch
// ---------------------------------------------------------------------------
__device__ float g_Q[MROWS * HIDDEN];
__device__ float g_K[MROWS * NKVH * HDIM];
__device__ float g_V[MROWS * NKVH * HDIM];
__device__ float g_ctx[MROWS * HIDDEN];

__device__ __align__(16) __nv_bfloat16 g_Xh[(size_t)MROWS * KDIM];
__device__ __align__(16) __nv_bfloat16 g_Xl[(size_t)MROWS * KDIM];
__device__ __align__(16) __nv_bfloat16 g_Ch[(size_t)MROWS * KDIM];
__device__ __align__(16) __nv_bfloat16 g_Cl[(size_t)MROWS * KDIM];
__device__ __align__(16) __nv_bfloat16 g_WqhT[(size_t)HIDDEN * KDIM];
__device__ __align__(16) __nv_bfloat16 g_WqlT[(size_t)HIDDEN * KDIM];
__device__ __align__(16) __nv_bfloat16 g_WkhT[(size_t)(NKVH * HDIM) * KDIM];
__device__ __align__(16) __nv_bfloat16 g_WklT[(size_t)(NKVH * HDIM) * KDIM];
__device__ __align__(16) __nv_bfloat16 g_WvhT[(size_t)(NKVH * HDIM) * KDIM];
__device__ __align__(16) __nv_bfloat16 g_WvlT[(size_t)(NKVH * HDIM) * KDIM];
__device__ __align__(16) __nv_bfloat16 g_WohT[(size_t)HIDDEN * KDIM];
__device__ __align__(16) __nv_bfloat16 g_WolT[(size_t)HIDDEN * KDIM];

// ---------------------------------------------------------------------------
// PTX helpers (baseline features only: cp.async, ldmatrix, mma.sync)
// ---------------------------------------------------------------------------
__device__ __forceinline__ uint32_t smem_u32(const void* p) {
    uint32_t a;
    asm("{ .reg .u64 t; cvta.to.shared.u64 t, %1; cvt.u32.u64 %0, t; }"
        : "=r"(a) : "l"(p));
    return a;
}

#define CP_ASYNC16(dst, src) \
    asm volatile("cp.async.cg.shared.global [%0], [%1], 16;" :: "r"(dst), "l"(src))
#define CP_COMMIT() asm volatile("cp.async.commit_group;" ::: "memory")
#define CP_WAIT(n)  asm volatile("cp.async.wait_group %0;" :: "n"(n) : "memory")

__device__ __forceinline__ void ldm_x4(uint32_t* r, uint32_t addr) {
    asm volatile("ldmatrix.sync.aligned.m8n8.x4.shared.b16 {%0,%1,%2,%3}, [%4];"
                 : "=r"(r[0]), "=r"(r[1]), "=r"(r[2]), "=r"(r[3]) : "r"(addr));
}
__device__ __forceinline__ void mma16816(float* d, const uint32_t* a, const uint32_t* b) {
    asm volatile("mma.sync.aligned.m16n8k16.row.col.f32.bf16.bf16.f32 "
                 "{%0,%1,%2,%3}, {%4,%5,%6,%7}, {%8,%9}, {%0,%1,%2,%3};"
                 : "+f"(d[0]), "+f"(d[1]), "+f"(d[2]), "+f"(d[3])
                 : "r"(a[0]), "r"(a[1]), "r"(a[2]), "r"(a[3]), "r"(b[0]), "r"(b[1]));
}

// ---------------------------------------------------------------------------
// Split conversion kernels (fp32 -> bf16 hi + bf16 lo)
// ---------------------------------------------------------------------------
__global__ void split_a2_kernel(const float* __restrict__ X,
                                __nv_bfloat16* __restrict__ H,
                                __nv_bfloat16* __restrict__ L, int total8) {
    int t = blockIdx.x * blockDim.x + threadIdx.x;
    if (t >= total8) return;
    const int base = t * 8;
    float4 x0 = *(const float4*)(X + base);
    float4 x1 = *(const float4*)(X + base + 4);
    float xs[8] = {x0.x, x0.y, x0.z, x0.w, x1.x, x1.y, x1.z, x1.w};
    __nv_bfloat16 hs[8], ls[8];
#pragma unroll
    for (int i = 0; i < 8; i++) {
        hs[i] = __float2bfloat16(xs[i]);
        ls[i] = __float2bfloat16(xs[i] - __bfloat162float(hs[i]));
    }
    *(uint4*)(H + base) = *(const uint4*)hs;
    *(uint4*)(L + base) = *(const uint4*)ls;
}

// W [K][N] fp32 -> WT hi/lo [N][K] bf16 (transpose)
__global__ void split_w2_kernel(const float* __restrict__ W,
                                __nv_bfloat16* __restrict__ HT,
                                __nv_bfloat16* __restrict__ LT, int N) {
    __shared__ float s[32][33];
    const int k0 = blockIdx.x * 32, n0 = blockIdx.y * 32;
    const int tx = threadIdx.x, ty = threadIdx.y;  // 32 x 8
#pragma unroll
    for (int i = 0; i < 4; i++)
        s[ty + 8 * i][tx] = W[(size_t)(k0 + ty + 8 * i) * N + n0 + tx];
    __syncthreads();
#pragma unroll
    for (int i = 0; i < 4; i++) {
        const int n = ty + 8 * i;
        float x = s[tx][n];
        __nv_bfloat16 hi = __float2bfloat16(x);
        __nv_bfloat16 lo = __float2bfloat16(x - __bfloat162float(hi));
        HT[(size_t)(n0 + n) * KDIM + k0 + tx] = hi;
        LT[(size_t)(n0 + n) * KDIM + k0 + tx] = lo;
    }
}

// ---------------------------------------------------------------------------
// Split-bf16 mma.sync GEMM: C[M][N] fp32 = A[M][K] @ Bt[N][K]^T
//   C ~= Ah Bh^T + Al Bh^T + Ah Bl^T
// CTA 128x128, BK=32, double-buffered cp.async, 8 warps (warp tile 64x32).
// ---------------------------------------------------------------------------
constexpr int GSTRIDE = 40;                       // bf16 row stride (padded)
constexpr int GTILE_B = 128 * GSTRIDE * 2;        // 10240 bytes per tile
constexpr int GSTAGE_B = 4 * GTILE_B;             // Ah|Al|Bh|Bl = 40960
constexpr int GEMM_SMEM = 2 * GSTAGE_B;           // 81920

__device__ __forceinline__ void gemm_load_stage(
    const __nv_bfloat16* __restrict__ Ah, const __nv_bfloat16* __restrict__ Al,
    const __nv_bfloat16* __restrict__ Bh, const __nv_bfloat16* __restrict__ Bl,
    uint32_t stageBase, int m0, int n0, int k0, int tid) {
#pragma unroll
    for (int i = 0; i < 8; i++) {
        const int idx = tid + i * 256;          // 0..2047
        const int tile = idx >> 9;              // 0..3
        const int c = idx & 511;
        const int row = c >> 2;
        const int kc = (c & 3) * 8;
        const __nv_bfloat16* src;
        if      (tile == 0) src = Ah + (size_t)(m0 + row) * KDIM + k0 + kc;
        else if (tile == 1) src = Al + (size_t)(m0 + row) * KDIM + k0 + kc;
        else if (tile == 2) src = Bh + (size_t)(n0 + row) * KDIM + k0 + kc;
        else                src = Bl + (size_t)(n0 + row) * KDIM + k0 + kc;
        const uint32_t dst = stageBase + tile * GTILE_B + (row * GSTRIDE + kc) * 2;
        CP_ASYNC16(dst, src);
    }
}

__global__ __launch_bounds__(256)
void mma_gemm(const __nv_bfloat16* __restrict__ Ah, const __nv_bfloat16* __restrict__ Al,
              const __nv_bfloat16* __restrict__ BhT, const __nv_bfloat16* __restrict__ BlT,
              float* __restrict__ C, int N) {
    extern __shared__ __align__(16) uint8_t smg[];
    const uint32_t sb = smem_u32(smg);
    const int tid = threadIdx.x;
    const int wid = tid >> 5, lane = tid & 31;
    const int m0 = blockIdx.y * 128, n0 = blockIdx.x * 128;
    const int mw = (wid & 1) * 64;          // warp m offset within CTA tile
    const int nw = (wid >> 1) * 32;         // warp n offset

    float acc[4][4][4];
#pragma unroll
    for (int i = 0; i < 4; i++)
#pragma unroll
        for (int j = 0; j < 4; j++)
#pragma unroll
            for (int q = 0; q < 4; q++) acc[i][j][q] = 0.f;

    // per-lane intra-tile byte offsets for ldmatrix
    const uint32_t laneA = ((lane & 15) * GSTRIDE + (lane >> 4) * 8) * 2;
    const uint32_t laneB = ((((lane >> 4) << 3) + (lane & 7)) * GSTRIDE
                           + ((lane >> 3) & 1) * 8) * 2;

    const int T = KDIM / 32;  // 64 stages
    gemm_load_stage(Ah, Al, BhT, BlT, sb, m0, n0, 0, tid);  CP_COMMIT();
    gemm_load_stage(Ah, Al, BhT, BlT, sb + GSTAGE_B, m0, n0, 32, tid); CP_COMMIT();

    for (int t = 0; t < T; t++) {
        const uint32_t stg = sb + (t & 1) * GSTAGE_B;
        if (t + 1 < T) { CP_WAIT(1); } else { CP_WAIT(0); }
        __syncthreads();

        const uint32_t aH = stg + 0 * GTILE_B + mw * GSTRIDE * 2 + laneA;
        const uint32_t aL = stg + 1 * GTILE_B + mw * GSTRIDE * 2 + laneA;
        const uint32_t bH = stg + 2 * GTILE_B + nw * GSTRIDE * 2 + laneB;
        const uint32_t bL = stg + 3 * GTILE_B + nw * GSTRIDE * 2 + laneB;

#pragma unroll
        for (int kk = 0; kk < 2; kk++) {
            const uint32_t ko = kk * 32;  // 16 bf16 = 32 bytes
            uint32_t fah[4][4], fal[4][4], fbh[2][4], fbl[2][4];
#pragma unroll
            for (int i = 0; i < 4; i++) {
                ldm_x4(fah[i], aH + i * 16 * GSTRIDE * 2 + ko);
                ldm_x4(fal[i], aL + i * 16 * GSTRIDE * 2 + ko);
            }
#pragma unroll
            for (int p = 0; p < 2; p++) {
                // B tiles stored [n][k] (col-major K x N): NON-trans ldmatrix
                ldm_x4(fbh[p], bH + p * 16 * GSTRIDE * 2 + ko);
                ldm_x4(fbl[p], bL + p * 16 * GSTRIDE * 2 + ko);
            }
#pragma unroll
            for (int i = 0; i < 4; i++) {
#pragma unroll
                for (int j = 0; j < 4; j++) {
                    const int p = j >> 1, h = (j & 1) * 2;
                    uint32_t bhf[2] = {fbh[p][h], fbh[p][h + 1]};
                    uint32_t blf[2] = {fbl[p][h], fbl[p][h + 1]};
                    mma16816(acc[i][j], fah[i], bhf);
                    mma16816(acc[i][j], fal[i], bhf);
                    mma16816(acc[i][j], fah[i], blf);
                }
            }
        }
        __syncthreads();
        if (t + 2 < T) {
            gemm_load_stage(Ah, Al, BhT, BlT, sb + (t & 1) * GSTAGE_B,
                            m0, n0, (t + 2) * 32, tid);
            CP_COMMIT();
        }
    }

    // Epilogue
    const int g = lane >> 2, tq = lane & 3;
#pragma unroll
    for (int i = 0; i < 4; i++) {
        const int r0 = m0 + mw + i * 16 + g;
#pragma unroll
        for (int j = 0; j < 4; j++) {
            const int col = n0 + nw + j * 8 + tq * 2;
            *(float2*)(C + (size_t)r0 * N + col)       = make_float2(acc[i][j][0], acc[i][j][1]);
            *(float2*)(C + (size_t)(r0 + 8) * N + col) = make_float2(acc[i][j][2], acc[i][j][3]);
        }
    }
}

// ---------------------------------------------------------------------------
// RoPE (folds 1/sqrt(Dh) into Q)
// ---------------------------------------------------------------------------
__global__ void rope_kernel(float* __restrict__ Qb, float* __restrict__ Kb,
                            const int* __restrict__ pos) {
    const int total = BATCH * SEQ * (NHEADS + NKVH) * 64;
    int idx = blockIdx.x * blockDim.x + threadIdx.x;
    if (idx >= total) return;
    const int p = idx & 63;
    int rest = idx >> 6;
    const int hh = rest % (NHEADS + NKVH);
    const int bs = rest / (NHEADS + NKVH);

    const float fpos = (float)pos[bs];
    const float inv = powf(10000.f, -(float)p * (1.f / 64.f));
    const float ang = fpos * inv;
    float sn, c;
    sincosf(ang, &sn, &c);

    float* base;
    float scale;
    if (hh < NHEADS) {
        base = Qb + (size_t)bs * HIDDEN + hh * HDIM;
        scale = QK_SCALE;
    } else {
        base = Kb + (size_t)bs * (NKVH * HDIM) + (hh - NHEADS) * HDIM;
        scale = 1.f;
    }
    const float x1 = base[p], x2 = base[p + 64];
    base[p]      = (x1 * c - x2 * sn) * scale;
    base[p + 64] = (x2 * c + x1 * sn) * scale;
}

// ---------------------------------------------------------------------------
// Flash attention (verified fp32 kernel from R1)
// ---------------------------------------------------------------------------
constexpr int BQ = 64;
constexpr int BK = 64;
constexpr int SW = 68;
constexpr int ATTN_SMEM_FLOATS = 8192 * 3 + BQ * SW + 3 * BQ;

__global__ __launch_bounds__(256, 1)
void attn_kernel(const float* __restrict__ Qb, const float* __restrict__ Kb,
                 const float* __restrict__ Vb, float* __restrict__ ctx) {
    extern __shared__ float sm[];
    float* Qt   = sm;
    float* Kt   = Qt + 8192;
    float* Vs   = Kt + 8192;
    float* Ssc  = Vs + 8192;
    float* rowm = Ssc + BQ * SW;
    float* rowl = rowm + BQ;
    float* rowa = rowl + BQ;

    const int tid = threadIdx.x;
    const int qt = blockIdx.x, h = blockIdx.y, b = blockIdx.z;
    const int kvh = h >> 2;
    const int q0 = qt * BQ;

    const int r   = tid >> 2;
    const int seg = tid & 3;
    const int ty  = tid >> 4;
    const int tx  = tid & 15;

    {
        const int dseg = seg * 32;
        const float* src = Qb + (size_t)(b * SEQ + q0 + r) * HIDDEN + h * HDIM + dseg;
#pragma unroll
        for (int i = 0; i < 32; i += 4) {
            float4 v = *(const float4*)(src + i);
            Qt[(dseg + i + 0) * 64 + r] = v.x;
            Qt[(dseg + i + 1) * 64 + r] = v.y;
            Qt[(dseg + i + 2) * 64 + r] = v.z;
            Qt[(dseg + i + 3) * 64 + r] = v.w;
        }
    }
    if (tid < BQ) { rowm[tid] = -INFINITY; rowl[tid] = 0.f; }

    float o[8][4];
#pragma unroll
    for (int m = 0; m < 8; m++)
#pragma unroll
        for (int i = 0; i < 4; i++) o[m][i] = 0.f;
    __syncthreads();

    for (int kt = 0; kt <= qt; kt++) {
        const int k0 = kt * BK;
        {
            const int dseg = seg * 32;
            const float* ks = Kb + (size_t)(b * SEQ + k0 + r) * (NKVH * HDIM) + kvh * HDIM + dseg;
            const float* vs = Vb + (size_t)(b * SEQ + k0 + r) * (NKVH * HDIM) + kvh * HDIM + dseg;
#pragma unroll
            for (int i = 0; i < 32; i += 4) {
                float4 kv4 = *(const float4*)(ks + i);
                Kt[(dseg + i + 0) * 64 + r] = kv4.x;
                Kt[(dseg + i + 1) * 64 + r] = kv4.y;
                Kt[(dseg + i + 2) * 64 + r] = kv4.z;
                Kt[(dseg + i + 3) * 64 + r] = kv4.w;
                float4 vv4 = *(const float4*)(vs + i);
                *(float4*)&Vs[r * HDIM + dseg + i] = vv4;
            }
        }
        __syncthreads();

        float acc[4][4];
#pragma unroll
        for (int i = 0; i < 4; i++)
#pragma unroll
            for (int j = 0; j < 4; j++) acc[i][j] = 0.f;
#pragma unroll 4
        for (int d = 0; d < HDIM; d++) {
            float4 a  = *(const float4*)&Qt[d * 64 + ty * 4];
            float4 bb = *(const float4*)&Kt[d * 64 + tx * 4];
            float av[4] = {a.x, a.y, a.z, a.w};
            float bv[4] = {bb.x, bb.y, bb.z, bb.w};
#pragma unroll
            for (int i = 0; i < 4; i++)
#pragma unroll
                for (int j = 0; j < 4; j++)
                    acc[i][j] = fmaf(av[i], bv[j], acc[i][j]);
        }
        const bool diag = (kt == qt);
#pragma unroll
        for (int i = 0; i < 4; i++) {
            const int qi = ty * 4 + i;
#pragma unroll
            for (int j = 0; j < 4; j++) {
                const int kj = tx * 4 + j;
                float v = acc[i][j];
                if (diag && kj > qi) v = -INFINITY;
                Ssc[qi * SW + kj] = v;
            }
        }
        __syncthreads();

        {
            float* srow = &Ssc[r * SW + seg * 16];
            float mloc = -INFINITY;
#pragma unroll
            for (int j = 0; j < 16; j++) mloc = fmaxf(mloc, srow[j]);
            mloc = fmaxf(mloc, __shfl_xor_sync(0xffffffffu, mloc, 1));
            mloc = fmaxf(mloc, __shfl_xor_sync(0xffffffffu, mloc, 2));
            const float mold = rowm[r];
            const float mnew = fmaxf(mold, mloc);
            float lsum = 0.f;
#pragma unroll
            for (int j = 0; j < 16; j++) {
                float e = __expf(srow[j] - mnew);
                srow[j] = e;
                lsum += e;
            }
            lsum += __shfl_xor_sync(0xffffffffu, lsum, 1);
            lsum += __shfl_xor_sync(0xffffffffu, lsum, 2);
            if (seg == 0) {
                rowa[r] = __expf(mold - mnew);
                rowl[r] = rowl[r] * __expf(mold - mnew) + lsum;
                rowm[r] = mnew;
            }
        }
        __syncthreads();

        {
            const float alpha = rowa[r];
#pragma unroll
            for (int m = 0; m < 8; m++)
#pragma unroll
                for (int i = 0; i < 4; i++) o[m][i] *= alpha;
            const float* srow = &Ssc[r * SW];
#pragma unroll 2
            for (int j = 0; j < BK; j++) {
                const float p = srow[j];
                const float* vrow = &Vs[j * HDIM + seg * 4];
#pragma unroll
                for (int m = 0; m < 8; m++) {
                    float4 v = *(const float4*)(vrow + m * 16);
                    o[m][0] = fmaf(p, v.x, o[m][0]);
                    o[m][1] = fmaf(p, v.y, o[m][1]);
                    o[m][2] = fmaf(p, v.z, o[m][2]);
                    o[m][3] = fmaf(p, v.w, o[m][3]);
                }
            }
        }
        __syncthreads();
    }

    const float invl = 1.f / rowl[r];
    float* dst = ctx + (size_t)(b * SEQ + q0 + r) * HIDDEN + h * HDIM + seg * 4;
#pragma unroll
    for (int m = 0; m < 8; m++) {
        float4 v = make_float4(o[m][0] * invl, o[m][1] * invl,
                               o[m][2] * invl, o[m][3] * invl);
        *(float4*)(dst + m * 16) = v;
    }
}

// ---------------------------------------------------------------------------
// Launch
// ---------------------------------------------------------------------------
extern "C" void kernel_launch(void* const* d_in, const int* in_sizes, int n_in,
                              void* d_out, int out_size) {
    const float* X   = (const float*)d_in[0];
    const int*   pos = (const int*)  d_in[1];
    const float* Wq  = (const float*)d_in[2];
    const float* Wk  = (const float*)d_in[3];
    const float* Wv  = (const float*)d_in[4];
    const float* Wo  = (const float*)d_in[5];
    float* out = (float*)d_out;

    float *Qp, *Kp, *Vp, *Cp;
    __nv_bfloat16 *Xh, *Xl, *Ch, *Cl;
    __nv_bfloat16 *Wqh, *Wql, *Wkh, *Wkl, *Wvh, *Wvl, *Woh, *Wol;
    cudaGetSymbolAddress((void**)&Qp, g_Q);
    cudaGetSymbolAddress((void**)&Kp, g_K);
    cudaGetSymbolAddress((void**)&Vp, g_V);
    cudaGetSymbolAddress((void**)&Cp, g_ctx);
    cudaGetSymbolAddress((void**)&Xh, g_Xh);
    cudaGetSymbolAddress((void**)&Xl, g_Xl);
    cudaGetSymbolAddress((void**)&Ch, g_Ch);
    cudaGetSymbolAddress((void**)&Cl, g_Cl);
    cudaGetSymbolAddress((void**)&Wqh, g_WqhT);
    cudaGetSymbolAddress((void**)&Wql, g_WqlT);
    cudaGetSymbolAddress((void**)&Wkh, g_WkhT);
    cudaGetSymbolAddress((void**)&Wkl, g_WklT);
    cudaGetSymbolAddress((void**)&Wvh, g_WvhT);
    cudaGetSymbolAddress((void**)&Wvl, g_WvlT);
    cudaGetSymbolAddress((void**)&Woh, g_WohT);
    cudaGetSymbolAddress((void**)&Wol, g_WolT);

    // Split / transpose conversions
    const int total8 = MROWS * KDIM / 8;
    split_a2_kernel<<<(total8 + 255) / 256, 256>>>(X, Xh, Xl, total8);
    split_w2_kernel<<<dim3(64, 64), dim3(32, 8)>>>(Wq, Wqh, Wql, 2048);
    split_w2_kernel<<<dim3(64, 16), dim3(32, 8)>>>(Wk, Wkh, Wkl, 512);
    split_w2_kernel<<<dim3(64, 16), dim3(32, 8)>>>(Wv, Wvh, Wvl, 512);
    split_w2_kernel<<<dim3(64, 64), dim3(32, 8)>>>(Wo, Woh, Wol, 2048);

    cudaFuncSetAttribute(mma_gemm, cudaFuncAttributeMaxDynamicSharedMemorySize, GEMM_SMEM);

    // QKV projections (split-bf16 tensor cores)
    mma_gemm<<<dim3(16, 32), 256, GEMM_SMEM>>>(Xh, Xl, Wqh, Wql, Qp, 2048);
    mma_gemm<<<dim3(4, 32), 256, GEMM_SMEM>>>(Xh, Xl, Wkh, Wkl, Kp, 512);
    mma_gemm<<<dim3(4, 32), 256, GEMM_SMEM>>>(Xh, Xl, Wvh, Wvl, Vp, 512);

    // RoPE (+ Q pre-scaling)
    const int rope_total = BATCH * SEQ * (NHEADS + NKVH) * 64;
    rope_kernel<<<(rope_total + 255) / 256, 256>>>(Qp, Kp, pos);

    // Flash attention (fp32)
    const size_t attn_smem = (size_t)ATTN_SMEM_FLOATS * sizeof(float);
    cudaFuncSetAttribute(attn_kernel, cudaFuncAttributeMaxDynamicSharedMemorySize,
                         (int)attn_smem);
    attn_kernel<<<dim3(SEQ / BQ, NHEADS, BATCH), 256, attn_smem>>>(Qp, Kp, Vp, Cp);

    // Output projection
    split_a2_kernel<<<(total8 + 255) / 256, 256>>>(Cp, Ch, Cl, total8);
    mma_gemm<<<dim3(16, 32), 256, GEMM_SMEM>>>(Ch, Cl, Woh, Wol, out, 2048);
}

// round 5
// speedup vs baseline: 3.7038x; 2.5447x over previous
#include <cuda_runtime.h>
#include <cuda_bf16.h>
#include <cstdint>
#include <math.h>

// Problem constants
constexpr int BATCH  = 2;
constexpr int SEQ    = 2048;
constexpr int HIDDEN = 2048;
constexpr int NHEADS = 16;
constexpr int NKVH   = 4;
constexpr int HDIM   = 128;
constexpr float QK_SCALE = 0.08838834764831845f; // 1/sqrt(128)

constexpr int MROWS = BATCH * SEQ;   // 4096
constexpr int KDIM  = HIDDEN;        // 2048

// ---------------------------------------------------------------------------
// Device-global scratch
// ---------------------------------------------------------------------------
__device__ float g_Q[MROWS * HIDDEN];
__device__ float g_K[MROWS * NKVH * HDIM];
__device__ float g_V[MROWS * NKVH * HDIM];
__device__ float g_ctx[MROWS * HIDDEN];

__device__ __align__(16) __nv_bfloat16 g_Xh[(size_t)MROWS * KDIM];
__device__ __align__(16) __nv_bfloat16 g_Xl[(size_t)MROWS * KDIM];
__device__ __align__(16) __nv_bfloat16 g_Ch[(size_t)MROWS * KDIM];
__device__ __align__(16) __nv_bfloat16 g_Cl[(size_t)MROWS * KDIM];
__device__ __align__(16) __nv_bfloat16 g_WqhT[(size_t)HIDDEN * KDIM];
__device__ __align__(16) __nv_bfloat16 g_WqlT[(size_t)HIDDEN * KDIM];
__device__ __align__(16) __nv_bfloat16 g_WkhT[(size_t)(NKVH * HDIM) * KDIM];
__device__ __align__(16) __nv_bfloat16 g_WklT[(size_t)(NKVH * HDIM) * KDIM];
__device__ __align__(16) __nv_bfloat16 g_WvhT[(size_t)(NKVH * HDIM) * KDIM];
__device__ __align__(16) __nv_bfloat16 g_WvlT[(size_t)(NKVH * HDIM) * KDIM];
__device__ __align__(16) __nv_bfloat16 g_WohT[(size_t)HIDDEN * KDIM];
__device__ __align__(16) __nv_bfloat16 g_WolT[(size_t)HIDDEN * KDIM];

// Attention operands (bf16 hi/lo)
__device__ __align__(16) __nv_bfloat16 g_Qbh[(size_t)BATCH * NHEADS * SEQ * HDIM];
__device__ __align__(16) __nv_bfloat16 g_Qbl[(size_t)BATCH * NHEADS * SEQ * HDIM];
__device__ __align__(16) __nv_bfloat16 g_Kbh[(size_t)BATCH * NKVH * SEQ * HDIM];
__device__ __align__(16) __nv_bfloat16 g_Kbl[(size_t)BATCH * NKVH * SEQ * HDIM];
__device__ __align__(16) __nv_bfloat16 g_Vth[(size_t)BATCH * NKVH * HDIM * SEQ];
__device__ __align__(16) __nv_bfloat16 g_Vtl[(size_t)BATCH * NKVH * HDIM * SEQ];

// ---------------------------------------------------------------------------
// PTX helpers
// ---------------------------------------------------------------------------
__device__ __forceinline__ uint32_t smem_u32(const void* p) {
    uint32_t a;
    asm("{ .reg .u64 t; cvta.to.shared.u64 t, %1; cvt.u32.u64 %0, t; }"
        : "=r"(a) : "l"(p));
    return a;
}

#define CP_ASYNC16(dst, src) \
    asm volatile("cp.async.cg.shared.global [%0], [%1], 16;" :: "r"(dst), "l"(src))
#define CP_COMMIT() asm volatile("cp.async.commit_group;" ::: "memory")
#define CP_WAIT(n)  asm volatile("cp.async.wait_group %0;" :: "n"(n) : "memory")

__device__ __forceinline__ void ldm_x4(uint32_t* r, uint32_t addr) {
    asm volatile("ldmatrix.sync.aligned.m8n8.x4.shared.b16 {%0,%1,%2,%3}, [%4];"
                 : "=r"(r[0]), "=r"(r[1]), "=r"(r[2]), "=r"(r[3]) : "r"(addr));
}
__device__ __forceinline__ void mma16816(float* d, const uint32_t* a, const uint32_t* b) {
    asm volatile("mma.sync.aligned.m16n8k16.row.col.f32.bf16.bf16.f32 "
                 "{%0,%1,%2,%3}, {%4,%5,%6,%7}, {%8,%9}, {%0,%1,%2,%3};"
                 : "+f"(d[0]), "+f"(d[1]), "+f"(d[2]), "+f"(d[3])
                 : "r"(a[0]), "r"(a[1]), "r"(a[2]), "r"(a[3]), "r"(b[0]), "r"(b[1]));
}
__device__ __forceinline__ uint32_t packbf(float lo, float hi) {
    __nv_bfloat162 t = __floats2bfloat162_rn(lo, hi);
    return *(uint32_t*)&t;
}

// ---------------------------------------------------------------------------
// Split conversion kernels (fp32 -> bf16 hi + lo)
// ---------------------------------------------------------------------------
__global__ void split_a2_kernel(const float* __restrict__ X,
                                __nv_bfloat16* __restrict__ H,
                                __nv_bfloat16* __restrict__ L, int total8) {
    int t = blockIdx.x * blockDim.x + threadIdx.x;
    if (t >= total8) return;
    const int base = t * 8;
    float4 x0 = *(const float4*)(X + base);
    float4 x1 = *(const float4*)(X + base + 4);
    float xs[8] = {x0.x, x0.y, x0.z, x0.w, x1.x, x1.y, x1.z, x1.w};
    __nv_bfloat16 hs[8], ls[8];
#pragma unroll
    for (int i = 0; i < 8; i++) {
        hs[i] = __float2bfloat16(xs[i]);
        ls[i] = __float2bfloat16(xs[i] - __bfloat162float(hs[i]));
    }
    *(uint4*)(H + base) = *(const uint4*)hs;
    *(uint4*)(L + base) = *(const uint4*)ls;
}

__global__ void split_w2_kernel(const float* __restrict__ W,
                                __nv_bfloat16* __restrict__ HT,
                                __nv_bfloat16* __restrict__ LT, int N) {
    __shared__ float s[32][33];
    const int k0 = blockIdx.x * 32, n0 = blockIdx.y * 32;
    const int tx = threadIdx.x, ty = threadIdx.y;  // 32 x 8
#pragma unroll
    for (int i = 0; i < 4; i++)
        s[ty + 8 * i][tx] = W[(size_t)(k0 + ty + 8 * i) * N + n0 + tx];
    __syncthreads();
#pragma unroll
    for (int i = 0; i < 4; i++) {
        const int n = ty + 8 * i;
        float x = s[tx][n];
        __nv_bfloat16 hi = __float2bfloat16(x);
        __nv_bfloat16 lo = __float2bfloat16(x - __bfloat162float(hi));
        HT[(size_t)(n0 + n) * KDIM + k0 + tx] = hi;
        LT[(size_t)(n0 + n) * KDIM + k0 + tx] = lo;
    }
}

// ---------------------------------------------------------------------------
// Split-bf16 mma.sync GEMM (verified in R4) — unchanged
// ---------------------------------------------------------------------------
constexpr int GSTRIDE = 40;
constexpr int GTILE_B = 128 * GSTRIDE * 2;
constexpr int GSTAGE_B = 4 * GTILE_B;
constexpr int GEMM_SMEM = 2 * GSTAGE_B;

__device__ __forceinline__ void gemm_load_stage(
    const __nv_bfloat16* __restrict__ Ah, const __nv_bfloat16* __restrict__ Al,
    const __nv_bfloat16* __restrict__ Bh, const __nv_bfloat16* __restrict__ Bl,
    uint32_t stageBase, int m0, int n0, int k0, int tid) {
#pragma unroll
    for (int i = 0; i < 8; i++) {
        const int idx = tid + i * 256;
        const int tile = idx >> 9;
        const int c = idx & 511;
        const int row = c >> 2;
        const int kc = (c & 3) * 8;
        const __nv_bfloat16* src;
        if      (tile == 0) src = Ah + (size_t)(m0 + row) * KDIM + k0 + kc;
        else if (tile == 1) src = Al + (size_t)(m0 + row) * KDIM + k0 + kc;
        else if (tile == 2) src = Bh + (size_t)(n0 + row) * KDIM + k0 + kc;
        else                src = Bl + (size_t)(n0 + row) * KDIM + k0 + kc;
        const uint32_t dst = stageBase + tile * GTILE_B + (row * GSTRIDE + kc) * 2;
        CP_ASYNC16(dst, src);
    }
}

__global__ __launch_bounds__(256)
void mma_gemm(const __nv_bfloat16* __restrict__ Ah, const __nv_bfloat16* __restrict__ Al,
              const __nv_bfloat16* __restrict__ BhT, const __nv_bfloat16* __restrict__ BlT,
              float* __restrict__ C, int N) {
    extern __shared__ __align__(16) uint8_t smg[];
    const uint32_t sb = smem_u32(smg);
    const int tid = threadIdx.x;
    const int wid = tid >> 5, lane = tid & 31;
    const int m0 = blockIdx.y * 128, n0 = blockIdx.x * 128;
    const int mw = (wid & 1) * 64;
    const int nw = (wid >> 1) * 32;

    float acc[4][4][4];
#pragma unroll
    for (int i = 0; i < 4; i++)
#pragma unroll
        for (int j = 0; j < 4; j++)
#pragma unroll
            for (int q = 0; q < 4; q++) acc[i][j][q] = 0.f;

    const uint32_t laneA = ((lane & 15) * GSTRIDE + (lane >> 4) * 8) * 2;
    const uint32_t laneB = ((((lane >> 4) << 3) + (lane & 7)) * GSTRIDE
                           + ((lane >> 3) & 1) * 8) * 2;

    const int T = KDIM / 32;
    gemm_load_stage(Ah, Al, BhT, BlT, sb, m0, n0, 0, tid);  CP_COMMIT();
    gemm_load_stage(Ah, Al, BhT, BlT, sb + GSTAGE_B, m0, n0, 32, tid); CP_COMMIT();

    for (int t = 0; t < T; t++) {
        const uint32_t stg = sb + (t & 1) * GSTAGE_B;
        if (t + 1 < T) { CP_WAIT(1); } else { CP_WAIT(0); }
        __syncthreads();

        const uint32_t aH = stg + 0 * GTILE_B + mw * GSTRIDE * 2 + laneA;
        const uint32_t aL = stg + 1 * GTILE_B + mw * GSTRIDE * 2 + laneA;
        const uint32_t bH = stg + 2 * GTILE_B + nw * GSTRIDE * 2 + laneB;
        const uint32_t bL = stg + 3 * GTILE_B + nw * GSTRIDE * 2 + laneB;

#pragma unroll
        for (int kk = 0; kk < 2; kk++) {
            const uint32_t ko = kk * 32;
            uint32_t fah[4][4], fal[4][4], fbh[2][4], fbl[2][4];
#pragma unroll
            for (int i = 0; i < 4; i++) {
                ldm_x4(fah[i], aH + i * 16 * GSTRIDE * 2 + ko);
                ldm_x4(fal[i], aL + i * 16 * GSTRIDE * 2 + ko);
            }
#pragma unroll
            for (int p = 0; p < 2; p++) {
                ldm_x4(fbh[p], bH + p * 16 * GSTRIDE * 2 + ko);
                ldm_x4(fbl[p], bL + p * 16 * GSTRIDE * 2 + ko);
            }
#pragma unroll
            for (int i = 0; i < 4; i++) {
#pragma unroll
                for (int j = 0; j < 4; j++) {
                    const int p = j >> 1, h = (j & 1) * 2;
                    uint32_t bhf[2] = {fbh[p][h], fbh[p][h + 1]};
                    uint32_t blf[2] = {fbl[p][h], fbl[p][h + 1]};
                    mma16816(acc[i][j], fah[i], bhf);
                    mma16816(acc[i][j], fal[i], bhf);
                    mma16816(acc[i][j], fah[i], blf);
                }
            }
        }
        __syncthreads();
        if (t + 2 < T) {
            gemm_load_stage(Ah, Al, BhT, BlT, sb + (t & 1) * GSTAGE_B,
                            m0, n0, (t + 2) * 32, tid);
            CP_COMMIT();
        }
    }

    const int g = lane >> 2, tq = lane & 3;
#pragma unroll
    for (int i = 0; i < 4; i++) {
        const int r0 = m0 + mw + i * 16 + g;
#pragma unroll
        for (int j = 0; j < 4; j++) {
            const int col = n0 + nw + j * 8 + tq * 2;
            *(float2*)(C + (size_t)r0 * N + col)       = make_float2(acc[i][j][0], acc[i][j][1]);
            *(float2*)(C + (size_t)(r0 + 8) * N + col) = make_float2(acc[i][j][2], acc[i][j][3]);
        }
    }
}

// ---------------------------------------------------------------------------
// RoPE + split + head-major relayout:
//   Qf [B,S,16,128] -> Qbh/Qbl [B,H,S,D]  (Q pre-scaled by 1/sqrt(Dh))
//   Kf [B,S,4,128]  -> Kbh/Kbl [B,kvh,S,D]
// ---------------------------------------------------------------------------
__global__ void rope_split_kernel(const float* __restrict__ Qf, const float* __restrict__ Kf,
                                  const int* __restrict__ pos,
                                  __nv_bfloat16* __restrict__ Qh, __nv_bfloat16* __restrict__ Ql,
                                  __nv_bfloat16* __restrict__ Kh, __nv_bfloat16* __restrict__ Kl) {
    const int total = BATCH * SEQ * (NHEADS + NKVH) * 64;
    int idx = blockIdx.x * blockDim.x + threadIdx.x;
    if (idx >= total) return;
    const int p = idx & 63;
    int rest = idx >> 6;
    const int hh = rest % (NHEADS + NKVH);
    const int bs = rest / (NHEADS + NKVH);
    const int b = bs >> 11, s = bs & 2047;

    const float fpos = (float)pos[bs];
    const float inv = powf(10000.f, -(float)p * (1.f / 64.f));
    const float ang = fpos * inv;
    float sn, c;
    sincosf(ang, &sn, &c);

    float x1, x2, scale;
    size_t obase;
    __nv_bfloat16 *H, *L;
    if (hh < NHEADS) {
        const float* src = Qf + (size_t)bs * HIDDEN + hh * HDIM;
        x1 = src[p]; x2 = src[p + 64];
        scale = QK_SCALE;
        obase = ((size_t)(b * NHEADS + hh) * SEQ + s) * HDIM;
        H = Qh; L = Ql;
    } else {
        const int kv = hh - NHEADS;
        const float* src = Kf + (size_t)bs * (NKVH * HDIM) + kv * HDIM;
        x1 = src[p]; x2 = src[p + 64];
        scale = 1.f;
        obase = ((size_t)(b * NKVH + kv) * SEQ + s) * HDIM;
        H = Kh; L = Kl;
    }
    const float y1 = (x1 * c - x2 * sn) * scale;
    const float y2 = (x2 * c + x1 * sn) * scale;
    __nv_bfloat16 h1 = __float2bfloat16(y1);
    __nv_bfloat16 h2 = __float2bfloat16(y2);
    H[obase + p]      = h1;
    H[obase + p + 64] = h2;
    L[obase + p]      = __float2bfloat16(y1 - __bfloat162float(h1));
    L[obase + p + 64] = __float2bfloat16(y2 - __bfloat162float(h2));
}

// V [B,S,4,128] fp32 -> Vth/Vtl [B,kvh,D,S] bf16 (transpose + split)
__global__ void vt_split_kernel(const float* __restrict__ V,
                                __nv_bfloat16* __restrict__ TH,
                                __nv_bfloat16* __restrict__ TL) {
    __shared__ float s[32][33];
    const int s0 = blockIdx.x * 32, d0 = blockIdx.y * 32;
    const int b = blockIdx.z >> 2, kv = blockIdx.z & 3;
    const int tx = threadIdx.x, ty = threadIdx.y;   // 32 x 8
#pragma unroll
    for (int i = 0; i < 4; i++) {
        const int ss = s0 + ty + 8 * i;
        s[ty + 8 * i][tx] = V[((size_t)(b * SEQ + ss) * (NKVH * HDIM)) + kv * HDIM + d0 + tx];
    }
    __syncthreads();
#pragma unroll
    for (int i = 0; i < 4; i++) {
        const int d = ty + 8 * i;
        float x = s[tx][d];
        __nv_bfloat16 hi = __float2bfloat16(x);
        __nv_bfloat16 lo = __float2bfloat16(x - __bfloat162float(hi));
        const size_t o = ((size_t)(b * NKVH + kv) * HDIM + d0 + d) * SEQ + s0 + tx;
        TH[o] = hi;
        TL[o] = lo;
    }
}

// ---------------------------------------------------------------------------
// Tensor-core flash attention (causal, GQA, split-bf16).
// BQ=128, BK=64, 256 threads (8 warps x 16 rows). Double-buffered cp.async KV.
// ---------------------------------------------------------------------------
constexpr int ASTR = 136;   // Q/K smem row stride in bf16 (Dh=128 + pad)
constexpr int VSTR = 72;    // Vt smem row stride in bf16 (BK=64 + pad)
constexpr int AQ_H = 0;
constexpr int AQ_L = 128 * ASTR * 2;                 // 34816
constexpr int AKV0 = 2 * 128 * ASTR * 2;             // 69632
constexpr int AK_H = 0;
constexpr int AK_L = 64 * ASTR * 2;                  // 17408
constexpr int AV_H = 2 * 64 * ASTR * 2;              // 34816
constexpr int AV_L = AV_H + 128 * VSTR * 2;          // 53248
constexpr int KVBUF = AV_L + 128 * VSTR * 2;         // 71680
constexpr int ATTN_SMEM = AKV0 + 2 * KVBUF;          // 212992

__device__ __forceinline__ void attn_load_kv(
    const __nv_bfloat16* __restrict__ Kh, const __nv_bfloat16* __restrict__ Kl,
    const __nv_bfloat16* __restrict__ Vth, const __nv_bfloat16* __restrict__ Vtl,
    uint32_t bufBase, size_t kbase, size_t vtbase, int k0, int tid) {
#pragma unroll
    for (int i = 0; i < 16; i++) {
        const int idx = tid + i * 256;   // 0..4095
        if (idx < 2048) {                // K tiles
            const int half = idx >> 10;
            const int j = idx & 1023;
            const int row = j >> 4, c = j & 15;
            const __nv_bfloat16* src = (half ? Kl : Kh) + kbase + (size_t)(k0 + row) * HDIM + c * 8;
            const uint32_t dst = bufBase + (half ? AK_L : AK_H) + (row * ASTR + c * 8) * 2;
            CP_ASYNC16(dst, src);
        } else {                         // Vt tiles
            const int v = idx - 2048;
            const int half = v >> 10;
            const int j = v & 1023;
            const int row = j >> 3, c = j & 7;
            const __nv_bfloat16* src = (half ? Vtl : Vth) + vtbase + (size_t)row * SEQ + k0 + c * 8;
            const uint32_t dst = bufBase + (half ? AV_L : AV_H) + (row * VSTR + c * 8) * 2;
            CP_ASYNC16(dst, src);
        }
    }
}

__global__ __launch_bounds__(256, 1)
void attn_mma_kernel(const __nv_bfloat16* __restrict__ Qh, const __nv_bfloat16* __restrict__ Ql,
                     const __nv_bfloat16* __restrict__ Kh, const __nv_bfloat16* __restrict__ Kl,
                     const __nv_bfloat16* __restrict__ Vth, const __nv_bfloat16* __restrict__ Vtl,
                     float* __restrict__ ctx) {
    extern __shared__ __align__(16) uint8_t smb[];
    const uint32_t sb = smem_u32(smb);
    const int tid = threadIdx.x;
    const int wid = tid >> 5, lane = tid & 31;
    const int g = lane >> 2, tq = lane & 3;

    const int qt = gridDim.x - 1 - blockIdx.x;   // long rows first
    const int h = blockIdx.y, b = blockIdx.z;
    const int kvh = h >> 2;
    const int q0 = qt * 128;
    const int nkt = 2 * qt + 2;

    const size_t qbase  = ((size_t)(b * NHEADS + h) * SEQ + q0) * HDIM;
    const size_t kbase  = ((size_t)(b * NKVH + kvh) * SEQ) * HDIM;
    const size_t vtbase = ((size_t)(b * NKVH + kvh) * HDIM) * SEQ;

    // Prologue: Q (group 1), KV tile0 (group 2), KV tile1 (group 3)
#pragma unroll
    for (int i = 0; i < 16; i++) {
        const int idx = tid + i * 256;   // 0..4095
        const int half = idx >> 11;
        const int j = idx & 2047;
        const int row = j >> 4, c = j & 15;
        const __nv_bfloat16* src = (half ? Ql : Qh) + qbase + (size_t)row * HDIM + c * 8;
        const uint32_t dst = sb + (half ? AQ_L : AQ_H) + (row * ASTR + c * 8) * 2;
        CP_ASYNC16(dst, src);
    }
    CP_COMMIT();
    attn_load_kv(Kh, Kl, Vth, Vtl, sb + AKV0,          kbase, vtbase, 0,  tid); CP_COMMIT();
    attn_load_kv(Kh, Kl, Vth, Vtl, sb + AKV0 + KVBUF,  kbase, vtbase, 64, tid); CP_COMMIT();

    // Q fragments (resident): 8 k-steps x 4 regs, hi + lo
    CP_WAIT(2);
    __syncthreads();
    uint32_t qfh[8][4], qfl[8][4];
    {
        const uint32_t la = ((wid * 16 + (lane & 15)) * ASTR + (lane >> 4) * 8) * 2;
#pragma unroll
        for (int kk = 0; kk < 8; kk++) {
            ldm_x4(qfh[kk], sb + AQ_H + la + kk * 32);
            ldm_x4(qfl[kk], sb + AQ_L + la + kk * 32);
        }
    }

    float o[16][4];
#pragma unroll
    for (int jj = 0; jj < 16; jj++)
#pragma unroll
        for (int q = 0; q < 4; q++) o[jj][q] = 0.f;
    float m0 = -1e30f, m1 = -1e30f, l0 = 0.f, l1 = 0.f;

    const int r0 = q0 + wid * 16 + g;
    const uint32_t laneNK = ((lane >> 4) * 8 + (lane & 7));
    const uint32_t laneKhi = ((lane >> 3) & 1) * 8;

    for (int kt = 0; kt < nkt; kt++) {
        const int k0 = kt * 64;
        const uint32_t buf = sb + AKV0 + (kt & 1) * KVBUF;
        if (kt + 1 < nkt) { CP_WAIT(1); } else { CP_WAIT(0); }
        __syncthreads();

        // ---- S = Q K^T ----
        float sacc[8][4];
#pragma unroll
        for (int j = 0; j < 8; j++)
#pragma unroll
            for (int q = 0; q < 4; q++) sacc[j][q] = 0.f;

#pragma unroll
        for (int kk = 0; kk < 8; kk++) {
#pragma unroll
            for (int p = 0; p < 4; p++) {
                const uint32_t off = ((p * 16 + laneNK) * ASTR + laneKhi) * 2 + kk * 32;
                uint32_t fkh[4], fkl[4];
                ldm_x4(fkh, buf + AK_H + off);
                ldm_x4(fkl, buf + AK_L + off);
                uint32_t b0h[2] = {fkh[0], fkh[1]}, b1h[2] = {fkh[2], fkh[3]};
                uint32_t b0l[2] = {fkl[0], fkl[1]}, b1l[2] = {fkl[2], fkl[3]};
                mma16816(sacc[2 * p],     qfh[kk], b0h);
                mma16816(sacc[2 * p + 1], qfh[kk], b1h);
                mma16816(sacc[2 * p],     qfl[kk], b0h);
                mma16816(sacc[2 * p + 1], qfl[kk], b1h);
                mma16816(sacc[2 * p],     qfh[kk], b0l);
                mma16816(sacc[2 * p + 1], qfh[kk], b1l);
            }
        }

        // ---- causal mask (diag tiles only) ----
        if (kt >= nkt - 2) {
#pragma unroll
            for (int j = 0; j < 8; j++) {
#pragma unroll
                for (int e = 0; e < 2; e++) {
                    const int col = k0 + j * 8 + tq * 2 + e;
                    if (col > r0)     sacc[j][e]     = -1e30f;
                    if (col > r0 + 8) sacc[j][2 + e] = -1e30f;
                }
            }
        }

        // ---- online softmax (per-warp, quad shfl) ----
        float mt0 = -1e30f, mt1 = -1e30f;
#pragma unroll
        for (int j = 0; j < 8; j++) {
            mt0 = fmaxf(mt0, fmaxf(sacc[j][0], sacc[j][1]));
            mt1 = fmaxf(mt1, fmaxf(sacc[j][2], sacc[j][3]));
        }
        mt0 = fmaxf(mt0, __shfl_xor_sync(0xffffffffu, mt0, 1));
        mt0 = fmaxf(mt0, __shfl_xor_sync(0xffffffffu, mt0, 2));
        mt1 = fmaxf(mt1, __shfl_xor_sync(0xffffffffu, mt1, 1));
        mt1 = fmaxf(mt1, __shfl_xor_sync(0xffffffffu, mt1, 2));
        const float mn0 = fmaxf(m0, mt0), mn1 = fmaxf(m1, mt1);
        const float al0 = __expf(m0 - mn0), al1 = __expf(m1 - mn1);
        float s0 = 0.f, s1 = 0.f;
#pragma unroll
        for (int j = 0; j < 8; j++) {
            sacc[j][0] = __expf(sacc[j][0] - mn0);
            sacc[j][1] = __expf(sacc[j][1] - mn0);
            sacc[j][2] = __expf(sacc[j][2] - mn1);
            sacc[j][3] = __expf(sacc[j][3] - mn1);
            s0 += sacc[j][0] + sacc[j][1];
            s1 += sacc[j][2] + sacc[j][3];
        }
        s0 += __shfl_xor_sync(0xffffffffu, s0, 1);
        s0 += __shfl_xor_sync(0xffffffffu, s0, 2);
        s1 += __shfl_xor_sync(0xffffffffu, s1, 1);
        s1 += __shfl_xor_sync(0xffffffffu, s1, 2);
        l0 = l0 * al0 + s0;  l1 = l1 * al1 + s1;
        m0 = mn0;            m1 = mn1;
#pragma unroll
        for (int jj = 0; jj < 16; jj++) {
            o[jj][0] *= al0; o[jj][1] *= al0;
            o[jj][2] *= al1; o[jj][3] *= al1;
        }

        // ---- P fragments (hi + residual lo), registers only ----
        uint32_t ph[4][4], pl[4][4];
#pragma unroll
        for (int kk2 = 0; kk2 < 4; kk2++) {
            const int j0 = 2 * kk2, j1 = j0 + 1;
            ph[kk2][0] = packbf(sacc[j0][0], sacc[j0][1]);
            ph[kk2][1] = packbf(sacc[j0][2], sacc[j0][3]);
            ph[kk2][2] = packbf(sacc[j1][0], sacc[j1][1]);
            ph[kk2][3] = packbf(sacc[j1][2], sacc[j1][3]);
            __nv_bfloat162 h0 = *(__nv_bfloat162*)&ph[kk2][0];
            __nv_bfloat162 h1 = *(__nv_bfloat162*)&ph[kk2][1];
            __nv_bfloat162 h2 = *(__nv_bfloat162*)&ph[kk2][2];
            __nv_bfloat162 h3 = *(__nv_bfloat162*)&ph[kk2][3];
            pl[kk2][0] = packbf(sacc[j0][0] - __bfloat162float(h0.x),
                                sacc[j0][1] - __bfloat162float(h0.y));
            pl[kk2][1] = packbf(sacc[j0][2] - __bfloat162float(h1.x),
                                sacc[j0][3] - __bfloat162float(h1.y));
            pl[kk2][2] = packbf(sacc[j1][0] - __bfloat162float(h2.x),
                                sacc[j1][1] - __bfloat162float(h2.y));
            pl[kk2][3] = packbf(sacc[j1][2] - __bfloat162float(h3.x),
                                sacc[j1][3] - __bfloat162float(h3.y));
        }

        // ---- O += P V ----
#pragma unroll
        for (int kk2 = 0; kk2 < 4; kk2++) {
#pragma unroll
            for (int p = 0; p < 8; p++) {
                const uint32_t off = ((p * 16 + laneNK) * VSTR + laneKhi + kk2 * 16) * 2;
                uint32_t fvh[4], fvl[4];
                ldm_x4(fvh, buf + AV_H + off);
                ldm_x4(fvl, buf + AV_L + off);
                uint32_t b0h[2] = {fvh[0], fvh[1]}, b1h[2] = {fvh[2], fvh[3]};
                uint32_t b0l[2] = {fvl[0], fvl[1]}, b1l[2] = {fvl[2], fvl[3]};
                mma16816(o[2 * p],     ph[kk2], b0h);
                mma16816(o[2 * p + 1], ph[kk2], b1h);
                mma16816(o[2 * p],     pl[kk2], b0h);
                mma16816(o[2 * p + 1], pl[kk2], b1h);
                mma16816(o[2 * p],     ph[kk2], b0l);
                mma16816(o[2 * p + 1], ph[kk2], b1l);
            }
        }

        __syncthreads();
        if (kt + 2 < nkt) {
            attn_load_kv(Kh, Kl, Vth, Vtl, sb + AKV0 + (kt & 1) * KVBUF,
                         kbase, vtbase, (kt + 2) * 64, tid);
            CP_COMMIT();
        }
    }

    // ---- epilogue ----
    const float inv0 = 1.f / l0, inv1 = 1.f / l1;
#pragma unroll
    for (int jj = 0; jj < 16; jj++) {
        const int d = jj * 8 + tq * 2;
        float* dst0 = ctx + ((size_t)(b * SEQ + r0) * HIDDEN) + h * HDIM + d;
        float* dst1 = ctx + ((size_t)(b * SEQ + r0 + 8) * HIDDEN) + h * HDIM + d;
        *(float2*)dst0 = make_float2(o[jj][0] * inv0, o[jj][1] * inv0);
        *(float2*)dst1 = make_float2(o[jj][2] * inv1, o[jj][3] * inv1);
    }
}

// ---------------------------------------------------------------------------
// Launch
// ---------------------------------------------------------------------------
extern "C" void kernel_launch(void* const* d_in, const int* in_sizes, int n_in,
                              void* d_out, int out_size) {
    const float* X   = (const float*)d_in[0];
    const int*   pos = (const int*)  d_in[1];
    const float* Wq  = (const float*)d_in[2];
    const float* Wk  = (const float*)d_in[3];
    const float* Wv  = (const float*)d_in[4];
    const float* Wo  = (const float*)d_in[5];
    float* out = (float*)d_out;

    float *Qp, *Kp, *Vp, *Cp;
    __nv_bfloat16 *Xh, *Xl, *Ch, *Cl;
    __nv_bfloat16 *Wqh, *Wql, *Wkh, *Wkl, *Wvh, *Wvl, *Woh, *Wol;
    __nv_bfloat16 *Qbh, *Qbl, *Kbh, *Kbl, *Vth, *Vtl;
    cudaGetSymbolAddress((void**)&Qp, g_Q);
    cudaGetSymbolAddress((void**)&Kp, g_K);
    cudaGetSymbolAddress((void**)&Vp, g_V);
    cudaGetSymbolAddress((void**)&Cp, g_ctx);
    cudaGetSymbolAddress((void**)&Xh, g_Xh);
    cudaGetSymbolAddress((void**)&Xl, g_Xl);
    cudaGetSymbolAddress((void**)&Ch, g_Ch);
    cudaGetSymbolAddress((void**)&Cl, g_Cl);
    cudaGetSymbolAddress((void**)&Wqh, g_WqhT);
    cudaGetSymbolAddress((void**)&Wql, g_WqlT);
    cudaGetSymbolAddress((void**)&Wkh, g_WkhT);
    cudaGetSymbolAddress((void**)&Wkl, g_WklT);
    cudaGetSymbolAddress((void**)&Wvh, g_WvhT);
    cudaGetSymbolAddress((void**)&Wvl, g_WvlT);
    cudaGetSymbolAddress((void**)&Woh, g_WohT);
    cudaGetSymbolAddress((void**)&Wol, g_WolT);
    cudaGetSymbolAddress((void**)&Qbh, g_Qbh);
    cudaGetSymbolAddress((void**)&Qbl, g_Qbl);
    cudaGetSymbolAddress((void**)&Kbh, g_Kbh);
    cudaGetSymbolAddress((void**)&Kbl, g_Kbl);
    cudaGetSymbolAddress((void**)&Vth, g_Vth);
    cudaGetSymbolAddress((void**)&Vtl, g_Vtl);

    // Split / transpose conversions
    const int total8 = MROWS * KDIM / 8;
    split_a2_kernel<<<(total8 + 255) / 256, 256>>>(X, Xh, Xl, total8);
    split_w2_kernel<<<dim3(64, 64), dim3(32, 8)>>>(Wq, Wqh, Wql, 2048);
    split_w2_kernel<<<dim3(64, 16), dim3(32, 8)>>>(Wk, Wkh, Wkl, 512);
    split_w2_kernel<<<dim3(64, 16), dim3(32, 8)>>>(Wv, Wvh, Wvl, 512);
    split_w2_kernel<<<dim3(64, 64), dim3(32, 8)>>>(Wo, Woh, Wol, 2048);

    cudaFuncSetAttribute(mma_gemm, cudaFuncAttributeMaxDynamicSharedMemorySize, GEMM_SMEM);

    // QKV projections
    mma_gemm<<<dim3(16, 32), 256, GEMM_SMEM>>>(Xh, Xl, Wqh, Wql, Qp, 2048);
    mma_gemm<<<dim3(4, 32), 256, GEMM_SMEM>>>(Xh, Xl, Wkh, Wkl, Kp, 512);
    mma_gemm<<<dim3(4, 32), 256, GEMM_SMEM>>>(Xh, Xl, Wvh, Wvl, Vp, 512);

    // RoPE + split to attention layouts
    const int rope_total = BATCH * SEQ * (NHEADS + NKVH) * 64;
    rope_split_kernel<<<(rope_total + 255) / 256, 256>>>(Qp, Kp, pos, Qbh, Qbl, Kbh, Kbl);
    vt_split_kernel<<<dim3(64, 4, 8), dim3(32, 8)>>>(Vp, Vth, Vtl);

    // Tensor-core flash attention
    cudaFuncSetAttribute(attn_mma_kernel, cudaFuncAttributeMaxDynamicSharedMemorySize, ATTN_SMEM);
    attn_mma_kernel<<<dim3(SEQ / 128, NHEADS, BATCH), 256, ATTN_SMEM>>>(
        Qbh, Qbl, Kbh, Kbl, Vth, Vtl, Cp);

    // Output projection
    split_a2_kernel<<<(total8 + 255) / 256, 256>>>(Cp, Ch, Cl, total8);
    mma_gemm<<<dim3(16, 32), 256, GEMM_SMEM>>>(Ch, Cl, Woh, Wol, out, 2048);
}

// round 7
// speedup vs baseline: 3.7991x; 1.0257x over previous
#include <cuda_runtime.h>
#include <cuda_bf16.h>
#include <cstdint>
#include <math.h>

// Problem constants
constexpr int BATCH  = 2;
constexpr int SEQ    = 2048;
constexpr int HIDDEN = 2048;
constexpr int NHEADS = 16;
constexpr int NKVH   = 4;
constexpr int HDIM   = 128;
constexpr float QK_SCALE = 0.08838834764831845f; // 1/sqrt(128)

constexpr int MROWS = BATCH * SEQ;   // 4096
constexpr int KDIM  = HIDDEN;        // 2048
constexpr int N_QKV = HIDDEN + 2 * NKVH * HDIM;  // 3072

// ---------------------------------------------------------------------------
// Device-global scratch
// ---------------------------------------------------------------------------
__device__ float g_QKV[(size_t)MROWS * N_QKV];    // fused Q|K|V fp32

__device__ __align__(16) __nv_bfloat16 g_Xh[(size_t)MROWS * KDIM];
__device__ __align__(16) __nv_bfloat16 g_Xl[(size_t)MROWS * KDIM];
__device__ __align__(16) __nv_bfloat16 g_Ch[(size_t)MROWS * KDIM];
__device__ __align__(16) __nv_bfloat16 g_Cl[(size_t)MROWS * KDIM];
__device__ __align__(16) __nv_bfloat16 g_W3hT[(size_t)N_QKV * KDIM];   // Wq|Wk|Wv ^T
__device__ __align__(16) __nv_bfloat16 g_W3lT[(size_t)N_QKV * KDIM];
__device__ __align__(16) __nv_bfloat16 g_WohT[(size_t)HIDDEN * KDIM];
__device__ __align__(16) __nv_bfloat16 g_WolT[(size_t)HIDDEN * KDIM];

// Attention operands (bf16 hi/lo)
__device__ __align__(16) __nv_bfloat16 g_Qbh[(size_t)BATCH * NHEADS * SEQ * HDIM];
__device__ __align__(16) __nv_bfloat16 g_Qbl[(size_t)BATCH * NHEADS * SEQ * HDIM];
__device__ __align__(16) __nv_bfloat16 g_Kbh[(size_t)BATCH * NKVH * SEQ * HDIM];
__device__ __align__(16) __nv_bfloat16 g_Kbl[(size_t)BATCH * NKVH * SEQ * HDIM];
__device__ __align__(16) __nv_bfloat16 g_Vth[(size_t)BATCH * NKVH * HDIM * SEQ];
__device__ __align__(16) __nv_bfloat16 g_Vtl[(size_t)BATCH * NKVH * HDIM * SEQ];

// ---------------------------------------------------------------------------
// PTX helpers
// ---------------------------------------------------------------------------
__device__ __forceinline__ uint32_t smem_u32(const void* p) {
    uint32_t a;
    asm("{ .reg .u64 t; cvta.to.shared.u64 t, %1; cvt.u32.u64 %0, t; }"
        : "=r"(a) : "l"(p));
    return a;
}

#define CP_ASYNC16(dst, src) \
    asm volatile("cp.async.cg.shared.global [%0], [%1], 16;" :: "r"(dst), "l"(src))
#define CP_COMMIT() asm volatile("cp.async.commit_group;" ::: "memory")
#define CP_WAIT(n)  asm volatile("cp.async.wait_group %0;" :: "n"(n) : "memory")

__device__ __forceinline__ void ldm_x4(uint32_t* r, uint32_t addr) {
    asm volatile("ldmatrix.sync.aligned.m8n8.x4.shared.b16 {%0,%1,%2,%3}, [%4];"
                 : "=r"(r[0]), "=r"(r[1]), "=r"(r[2]), "=r"(r[3]) : "r"(addr));
}
__device__ __forceinline__ void mma16816(float* d, const uint32_t* a, const uint32_t* b) {
    asm volatile("mma.sync.aligned.m16n8k16.row.col.f32.bf16.bf16.f32 "
                 "{%0,%1,%2,%3}, {%4,%5,%6,%7}, {%8,%9}, {%0,%1,%2,%3};"
                 : "+f"(d[0]), "+f"(d[1]), "+f"(d[2]), "+f"(d[3])
                 : "r"(a[0]), "r"(a[1]), "r"(a[2]), "r"(a[3]), "r"(b[0]), "r"(b[1]));
}
__device__ __forceinline__ uint32_t packbf(float lo, float hi) {
    __nv_bfloat162 t = __floats2bfloat162_rn(lo, hi);
    return *(uint32_t*)&t;
}

// ---------------------------------------------------------------------------
// Split conversion kernels (fp32 -> bf16 hi + lo)
// ---------------------------------------------------------------------------
__global__ void split_a2_kernel(const float* __restrict__ X,
                                __nv_bfloat16* __restrict__ H,
                                __nv_bfloat16* __restrict__ L, int total8) {
    int t = blockIdx.x * blockDim.x + threadIdx.x;
    if (t >= total8) return;
    const int base = t * 8;
    float4 x0 = *(const float4*)(X + base);
    float4 x1 = *(const float4*)(X + base + 4);
    float xs[8] = {x0.x, x0.y, x0.z, x0.w, x1.x, x1.y, x1.z, x1.w};
    __nv_bfloat16 hs[8], ls[8];
#pragma unroll
    for (int i = 0; i < 8; i++) {
        hs[i] = __float2bfloat16(xs[i]);
        ls[i] = __float2bfloat16(xs[i] - __bfloat162float(hs[i]));
    }
    *(uint4*)(H + base) = *(const uint4*)hs;
    *(uint4*)(L + base) = *(const uint4*)ls;
}

// W [K][N] fp32 -> WT hi/lo [N][K] bf16 (transpose). Caller offsets HT/LT.
__global__ void split_w2_kernel(const float* __restrict__ W,
                                __nv_bfloat16* __restrict__ HT,
                                __nv_bfloat16* __restrict__ LT, int N) {
    __shared__ float s[32][33];
    const int k0 = blockIdx.x * 32, n0 = blockIdx.y * 32;
    const int tx = threadIdx.x, ty = threadIdx.y;  // 32 x 8
#pragma unroll
    for (int i = 0; i < 4; i++)
        s[ty + 8 * i][tx] = W[(size_t)(k0 + ty + 8 * i) * N + n0 + tx];
    __syncthreads();
#pragma unroll
    for (int i = 0; i < 4; i++) {
        const int n = ty + 8 * i;
        float x = s[tx][n];
        __nv_bfloat16 hi = __float2bfloat16(x);
        __nv_bfloat16 lo = __float2bfloat16(x - __bfloat162float(hi));
        HT[(size_t)(n0 + n) * KDIM + k0 + tx] = hi;
        LT[(size_t)(n0 + n) * KDIM + k0 + tx] = lo;
    }
}

// ---------------------------------------------------------------------------
// Split-bf16 mma.sync GEMM. CTA 128x128, BK=32, double-buffered cp.async,
// 8 warps (64x32 warp tile). Restructured for <=~100 regs -> 2 CTAs/SM.
// ---------------------------------------------------------------------------
constexpr int GSTRIDE = 40;
constexpr int GTILE_B = 128 * GSTRIDE * 2;
constexpr int GSTAGE_B = 4 * GTILE_B;
constexpr int GEMM_SMEM = 2 * GSTAGE_B;   // 81920

__device__ __forceinline__ void gemm_load_stage(
    const __nv_bfloat16* __restrict__ Ah, const __nv_bfloat16* __restrict__ Al,
    const __nv_bfloat16* __restrict__ Bh, const __nv_bfloat16* __restrict__ Bl,
    uint32_t stageBase, int m0, int n0, int k0, int tid) {
#pragma unroll
    for (int i = 0; i < 8; i++) {
        const int idx = tid + i * 256;
        const int tile = idx >> 9;
        const int c = idx & 511;
        const int row = c >> 2;
        const int kc = (c & 3) * 8;
        const __nv_bfloat16* src;
        if      (tile == 0) src = Ah + (size_t)(m0 + row) * KDIM + k0 + kc;
        else if (tile == 1) src = Al + (size_t)(m0 + row) * KDIM + k0 + kc;
        else if (tile == 2) src = Bh + (size_t)(n0 + row) * KDIM + k0 + kc;
        else                src = Bl + (size_t)(n0 + row) * KDIM + k0 + kc;
        const uint32_t dst = stageBase + tile * GTILE_B + (row * GSTRIDE + kc) * 2;
        CP_ASYNC16(dst, src);
    }
}

__global__ __launch_bounds__(256, 2)
void mma_gemm(const __nv_bfloat16* __restrict__ Ah, const __nv_bfloat16* __restrict__ Al,
              const __nv_bfloat16* __restrict__ BhT, const __nv_bfloat16* __restrict__ BlT,
              float* __restrict__ C, int N) {
    extern __shared__ __align__(16) uint8_t smg[];
    const uint32_t sb = smem_u32(smg);
    const int tid = threadIdx.x;
    const int wid = tid >> 5, lane = tid & 31;
    const int m0 = blockIdx.y * 128, n0 = blockIdx.x * 128;
    const int mw = (wid & 1) * 64;
    const int nw = (wid >> 1) * 32;

    float acc[4][4][4];
#pragma unroll
    for (int i = 0; i < 4; i++)
#pragma unroll
        for (int j = 0; j < 4; j++)
#pragma unroll
            for (int q = 0; q < 4; q++) acc[i][j][q] = 0.f;

    const uint32_t laneA = ((lane & 15) * GSTRIDE + (lane >> 4) * 8) * 2;
    const uint32_t laneB = ((((lane >> 4) << 3) + (lane & 7)) * GSTRIDE
                           + ((lane >> 3) & 1) * 8) * 2;

    const int T = KDIM / 32;
    gemm_load_stage(Ah, Al, BhT, BlT, sb, m0, n0, 0, tid);  CP_COMMIT();
    gemm_load_stage(Ah, Al, BhT, BlT, sb + GSTAGE_B, m0, n0, 32, tid); CP_COMMIT();

    for (int t = 0; t < T; t++) {
        const uint32_t stg = sb + (t & 1) * GSTAGE_B;
        if (t + 1 < T) { CP_WAIT(1); } else { CP_WAIT(0); }
        __syncthreads();

        const uint32_t aH = stg + 0 * GTILE_B + mw * GSTRIDE * 2 + laneA;
        const uint32_t aL = stg + 1 * GTILE_B + mw * GSTRIDE * 2 + laneA;
        const uint32_t bH = stg + 2 * GTILE_B + nw * GSTRIDE * 2 + laneB;
        const uint32_t bL = stg + 3 * GTILE_B + nw * GSTRIDE * 2 + laneB;

#pragma unroll
        for (int kk = 0; kk < 2; kk++) {
            const uint32_t ko = kk * 32;
            uint32_t fbh[2][4], fbl[2][4];
#pragma unroll
            for (int p = 0; p < 2; p++) {
                ldm_x4(fbh[p], bH + p * 16 * GSTRIDE * 2 + ko);
                ldm_x4(fbl[p], bL + p * 16 * GSTRIDE * 2 + ko);
            }
#pragma unroll
            for (int i = 0; i < 4; i++) {
                uint32_t fah[4], fal[4];
                ldm_x4(fah, aH + i * 16 * GSTRIDE * 2 + ko);
                ldm_x4(fal, aL + i * 16 * GSTRIDE * 2 + ko);
#pragma unroll
                for (int j = 0; j < 4; j++) {
                    const int p = j >> 1, h = (j & 1) * 2;
                    uint32_t bhf[2] = {fbh[p][h], fbh[p][h + 1]};
                    uint32_t blf[2] = {fbl[p][h], fbl[p][h + 1]};
                    mma16816(acc[i][j], fah, bhf);
                    mma16816(acc[i][j], fal, bhf);
                    mma16816(acc[i][j], fah, blf);
                }
            }
        }
        __syncthreads();
        if (t + 2 < T) {
            gemm_load_stage(Ah, Al, BhT, BlT, sb + (t & 1) * GSTAGE_B,
                            m0, n0, (t + 2) * 32, tid);
            CP_COMMIT();
        }
    }

    const int g = lane >> 2, tq = lane & 3;
#pragma unroll
    for (int i = 0; i < 4; i++) {
        const int r0 = m0 + mw + i * 16 + g;
#pragma unroll
        for (int j = 0; j < 4; j++) {
            const int col = n0 + nw + j * 8 + tq * 2;
            *(float2*)(C + (size_t)r0 * N + col)       = make_float2(acc[i][j][0], acc[i][j][1]);
            *(float2*)(C + (size_t)(r0 + 8) * N + col) = make_float2(acc[i][j][2], acc[i][j][3]);
        }
    }
}

// ---------------------------------------------------------------------------
// RoPE + split + head-major relayout from fused QKV [4096][3072]:
//   Q cols [0,2048)   -> Qbh/Qbl [B,H,S,D] (pre-scaled by 1/sqrt(Dh))
//   K cols [2048,2560)-> Kbh/Kbl [B,kvh,S,D]
// ---------------------------------------------------------------------------
__global__ void rope_split_kernel(const float* __restrict__ QKV,
                                  const int* __restrict__ pos,
                                  __nv_bfloat16* __restrict__ Qh, __nv_bfloat16* __restrict__ Ql,
                                  __nv_bfloat16* __restrict__ Kh, __nv_bfloat16* __restrict__ Kl) {
    const int total = BATCH * SEQ * (NHEADS + NKVH) * 64;
    int idx = blockIdx.x * blockDim.x + threadIdx.x;
    if (idx >= total) return;
    const int p = idx & 63;
    int rest = idx >> 6;
    const int hh = rest % (NHEADS + NKVH);
    const int bs = rest / (NHEADS + NKVH);
    const int b = bs >> 11, s = bs & 2047;

    const float fpos = (float)pos[bs];
    const float inv = powf(10000.f, -(float)p * (1.f / 64.f));
    const float ang = fpos * inv;
    float sn, c;
    sincosf(ang, &sn, &c);

    float x1, x2, scale;
    size_t obase;
    __nv_bfloat16 *H, *L;
    if (hh < NHEADS) {
        const float* src = QKV + (size_t)bs * N_QKV + hh * HDIM;
        x1 = src[p]; x2 = src[p + 64];
        scale = QK_SCALE;
        obase = ((size_t)(b * NHEADS + hh) * SEQ + s) * HDIM;
        H = Qh; L = Ql;
    } else {
        const int kv = hh - NHEADS;
        const float* src = QKV + (size_t)bs * N_QKV + HIDDEN + kv * HDIM;
        x1 = src[p]; x2 = src[p + 64];
        scale = 1.f;
        obase = ((size_t)(b * NKVH + kv) * SEQ + s) * HDIM;
        H = Kh; L = Kl;
    }
    const float y1 = (x1 * c - x2 * sn) * scale;
    const float y2 = (x2 * c + x1 * sn) * scale;
    __nv_bfloat16 h1 = __float2bfloat16(y1);
    __nv_bfloat16 h2 = __float2bfloat16(y2);
    H[obase + p]      = h1;
    H[obase + p + 64] = h2;
    L[obase + p]      = __float2bfloat16(y1 - __bfloat162float(h1));
    L[obase + p + 64] = __float2bfloat16(y2 - __bfloat162float(h2));
}

// V (QKV cols [2560,3072)) -> Vth/Vtl [B,kvh,D,S] bf16 (transpose + split)
__global__ void vt_split_kernel(const float* __restrict__ QKV,
                                __nv_bfloat16* __restrict__ TH,
                                __nv_bfloat16* __restrict__ TL) {
    __shared__ float s[32][33];
    const int s0 = blockIdx.x * 32, d0 = blockIdx.y * 32;
    const int b = blockIdx.z >> 2, kv = blockIdx.z & 3;
    const int tx = threadIdx.x, ty = threadIdx.y;   // 32 x 8
#pragma unroll
    for (int i = 0; i < 4; i++) {
        const int ss = s0 + ty + 8 * i;
        s[ty + 8 * i][tx] =
            QKV[(size_t)(b * SEQ + ss) * N_QKV + HIDDEN + NKVH * HDIM + kv * HDIM + d0 + tx];
    }
    __syncthreads();
#pragma unroll
    for (int i = 0; i < 4; i++) {
        const int d = ty + 8 * i;
        float x = s[tx][d];
        __nv_bfloat16 hi = __float2bfloat16(x);
        __nv_bfloat16 lo = __float2bfloat16(x - __bfloat162float(hi));
        const size_t o = ((size_t)(b * NKVH + kv) * HDIM + d0 + d) * SEQ + s0 + tx;
        TH[o] = hi;
        TL[o] = lo;
    }
}

// ---------------------------------------------------------------------------
// Tensor-core flash attention (causal, GQA, split-bf16).
// BQ=128, BK=64, 256 threads. Epilogue emits ctx as bf16 hi/lo directly.
// ---------------------------------------------------------------------------
constexpr int ASTR = 136;
constexpr int VSTR = 72;
constexpr int AQ_H = 0;
constexpr int AQ_L = 128 * ASTR * 2;
constexpr int AKV0 = 2 * 128 * ASTR * 2;
constexpr int AK_H = 0;
constexpr int AK_L = 64 * ASTR * 2;
constexpr int AV_H = 2 * 64 * ASTR * 2;
constexpr int AV_L = AV_H + 128 * VSTR * 2;
constexpr int KVBUF = AV_L + 128 * VSTR * 2;
constexpr int ATTN_SMEM = AKV0 + 2 * KVBUF;   // 212992

__device__ __forceinline__ void attn_load_kv(
    const __nv_bfloat16* __restrict__ Kh, const __nv_bfloat16* __restrict__ Kl,
    const __nv_bfloat16* __restrict__ Vth, const __nv_bfloat16* __restrict__ Vtl,
    uint32_t bufBase, size_t kbase, size_t vtbase, int k0, int tid) {
#pragma unroll
    for (int i = 0; i < 16; i++) {
        const int idx = tid + i * 256;
        if (idx < 2048) {
            const int half = idx >> 10;
            const int j = idx & 1023;
            const int row = j >> 4, c = j & 15;
            const __nv_bfloat16* src = (half ? Kl : Kh) + kbase + (size_t)(k0 + row) * HDIM + c * 8;
            const uint32_t dst = bufBase + (half ? AK_L : AK_H) + (row * ASTR + c * 8) * 2;
            CP_ASYNC16(dst, src);
        } else {
            const int v = idx - 2048;
            const int half = v >> 10;
            const int j = v & 1023;
            const int row = j >> 3, c = j & 7;
            const __nv_bfloat16* src = (half ? Vtl : Vth) + vtbase + (size_t)row * SEQ + k0 + c * 8;
            const uint32_t dst = bufBase + (half ? AV_L : AV_H) + (row * VSTR + c * 8) * 2;
            CP_ASYNC16(dst, src);
        }
    }
}

__global__ __launch_bounds__(256, 1)
void attn_mma_kernel(const __nv_bfloat16* __restrict__ Qh, const __nv_bfloat16* __restrict__ Ql,
                     const __nv_bfloat16* __restrict__ Kh, const __nv_bfloat16* __restrict__ Kl,
                     const __nv_bfloat16* __restrict__ Vth, const __nv_bfloat16* __restrict__ Vtl,
                     __nv_bfloat16* __restrict__ Ch, __nv_bfloat16* __restrict__ Cl) {
    extern __shared__ __align__(16) uint8_t smb[];
    const uint32_t sb = smem_u32(smb);
    const int tid = threadIdx.x;
    const int wid = tid >> 5, lane = tid & 31;
    const int g = lane >> 2, tq = lane & 3;

    const int qt = gridDim.x - 1 - blockIdx.x;
    const int h = blockIdx.y, b = blockIdx.z;
    const int kvh = h >> 2;
    const int q0 = qt * 128;
    const int nkt = 2 * qt + 2;

    const size_t qbase  = ((size_t)(b * NHEADS + h) * SEQ + q0) * HDIM;
    const size_t kbase  = ((size_t)(b * NKVH + kvh) * SEQ) * HDIM;
    const size_t vtbase = ((size_t)(b * NKVH + kvh) * HDIM) * SEQ;

#pragma unroll
    for (int i = 0; i < 16; i++) {
        const int idx = tid + i * 256;
        const int half = idx >> 11;
        const int j = idx & 2047;
        const int row = j >> 4, c = j & 15;
        const __nv_bfloat16* src = (half ? Ql : Qh) + qbase + (size_t)row * HDIM + c * 8;
        const uint32_t dst = sb + (half ? AQ_L : AQ_H) + (row * ASTR + c * 8) * 2;
        CP_ASYNC16(dst, src);
    }
    CP_COMMIT();
    attn_load_kv(Kh, Kl, Vth, Vtl, sb + AKV0,          kbase, vtbase, 0,  tid); CP_COMMIT();
    attn_load_kv(Kh, Kl, Vth, Vtl, sb + AKV0 + KVBUF,  kbase, vtbase, 64, tid); CP_COMMIT();

    CP_WAIT(2);
    __syncthreads();
    uint32_t qfh[8][4], qfl[8][4];
    {
        const uint32_t la = ((wid * 16 + (lane & 15)) * ASTR + (lane >> 4) * 8) * 2;
#pragma unroll
        for (int kk = 0; kk < 8; kk++) {
            ldm_x4(qfh[kk], sb + AQ_H + la + kk * 32);
            ldm_x4(qfl[kk], sb + AQ_L + la + kk * 32);
        }
    }

    float o[16][4];
#pragma unroll
    for (int jj = 0; jj < 16; jj++)
#pragma unroll
        for (int q = 0; q < 4; q++) o[jj][q] = 0.f;
    float m0 = -1e30f, m1 = -1e30f, sl0 = 0.f, sl1 = 0.f;

    const int r0 = q0 + wid * 16 + g;
    const uint32_t laneNK = ((lane >> 4) * 8 + (lane & 7));
    const uint32_t laneKhi = ((lane >> 3) & 1) * 8;

    for (int kt = 0; kt < nkt; kt++) {
        const int k0 = kt * 64;
        const uint32_t buf = sb + AKV0 + (kt & 1) * KVBUF;
        if (kt + 1 < nkt) { CP_WAIT(1); } else { CP_WAIT(0); }
        __syncthreads();

        // ---- S = Q K^T ----
        float sacc[8][4];
#pragma unroll
        for (int j = 0; j < 8; j++)
#pragma unroll
            for (int q = 0; q < 4; q++) sacc[j][q] = 0.f;

#pragma unroll
        for (int kk = 0; kk < 8; kk++) {
#pragma unroll
            for (int p = 0; p < 4; p++) {
                const uint32_t off = ((p * 16 + laneNK) * ASTR + laneKhi) * 2 + kk * 32;
                uint32_t fkh[4], fkl[4];
                ldm_x4(fkh, buf + AK_H + off);
                ldm_x4(fkl, buf + AK_L + off);
                uint32_t b0h[2] = {fkh[0], fkh[1]}, b1h[2] = {fkh[2], fkh[3]};
                uint32_t b0l[2] = {fkl[0], fkl[1]}, b1l[2] = {fkl[2], fkl[3]};
                mma16816(sacc[2 * p],     qfh[kk], b0h);
                mma16816(sacc[2 * p + 1], qfh[kk], b1h);
                mma16816(sacc[2 * p],     qfl[kk], b0h);
                mma16816(sacc[2 * p + 1], qfl[kk], b1h);
                mma16816(sacc[2 * p],     qfh[kk], b0l);
                mma16816(sacc[2 * p + 1], qfh[kk], b1l);
            }
        }

        // ---- causal mask ----
        if (kt >= nkt - 2) {
#pragma unroll
            for (int j = 0; j < 8; j++) {
#pragma unroll
                for (int e = 0; e < 2; e++) {
                    const int col = k0 + j * 8 + tq * 2 + e;
                    if (col > r0)     sacc[j][e]     = -1e30f;
                    if (col > r0 + 8) sacc[j][2 + e] = -1e30f;
                }
            }
        }

        // ---- online softmax ----
        float mt0 = -1e30f, mt1 = -1e30f;
#pragma unroll
        for (int j = 0; j < 8; j++) {
            mt0 = fmaxf(mt0, fmaxf(sacc[j][0], sacc[j][1]));
            mt1 = fmaxf(mt1, fmaxf(sacc[j][2], sacc[j][3]));
        }
        mt0 = fmaxf(mt0, __shfl_xor_sync(0xffffffffu, mt0, 1));
        mt0 = fmaxf(mt0, __shfl_xor_sync(0xffffffffu, mt0, 2));
        mt1 = fmaxf(mt1, __shfl_xor_sync(0xffffffffu, mt1, 1));
        mt1 = fmaxf(mt1, __shfl_xor_sync(0xffffffffu, mt1, 2));
        const float mn0 = fmaxf(m0, mt0), mn1 = fmaxf(m1, mt1);
        const float al0 = __expf(m0 - mn0), al1 = __expf(m1 - mn1);
        float s0 = 0.f, s1 = 0.f;
#pragma unroll
        for (int j = 0; j < 8; j++) {
            sacc[j][0] = __expf(sacc[j][0] - mn0);
            sacc[j][1] = __expf(sacc[j][1] - mn0);
            sacc[j][2] = __expf(sacc[j][2] - mn1);
            sacc[j][3] = __expf(sacc[j][3] - mn1);
            s0 += sacc[j][0] + sacc[j][1];
            s1 += sacc[j][2] + sacc[j][3];
        }
        s0 += __shfl_xor_sync(0xffffffffu, s0, 1);
        s0 += __shfl_xor_sync(0xffffffffu, s0, 2);
        s1 += __shfl_xor_sync(0xffffffffu, s1, 1);
        s1 += __shfl_xor_sync(0xffffffffu, s1, 2);
        sl0 = sl0 * al0 + s0;  sl1 = sl1 * al1 + s1;
        m0 = mn0;              m1 = mn1;
#pragma unroll
        for (int jj = 0; jj < 16; jj++) {
            o[jj][0] *= al0; o[jj][1] *= al0;
            o[jj][2] *= al1; o[jj][3] *= al1;
        }

        // ---- P fragments (hi + residual lo) ----
        uint32_t ph[4][4], pl[4][4];
#pragma unroll
        for (int kk2 = 0; kk2 < 4; kk2++) {
            const int j0 = 2 * kk2, j1 = j0 + 1;
            ph[kk2][0] = packbf(sacc[j0][0], sacc[j0][1]);
            ph[kk2][1] = packbf(sacc[j0][2], sacc[j0][3]);
            ph[kk2][2] = packbf(sacc[j1][0], sacc[j1][1]);
            ph[kk2][3] = packbf(sacc[j1][2], sacc[j1][3]);
            __nv_bfloat162 h0 = *(__nv_bfloat162*)&ph[kk2][0];
            __nv_bfloat162 h1 = *(__nv_bfloat162*)&ph[kk2][1];
            __nv_bfloat162 h2 = *(__nv_bfloat162*)&ph[kk2][2];
            __nv_bfloat162 h3 = *(__nv_bfloat162*)&ph[kk2][3];
            pl[kk2][0] = packbf(sacc[j0][0] - __bfloat162float(h0.x),
                                sacc[j0][1] - __bfloat162float(h0.y));
            pl[kk2][1] = packbf(sacc[j0][2] - __bfloat162float(h1.x),
                                sacc[j0][3] - __bfloat162float(h1.y));
            pl[kk2][2] = packbf(sacc[j1][0] - __bfloat162float(h2.x),
                                sacc[j1][1] - __bfloat162float(h2.y));
            pl[kk2][3] = packbf(sacc[j1][2] - __bfloat162float(h3.x),
                                sacc[j1][3] - __bfloat162float(h3.y));
        }

        // ---- O += P V ----
#pragma unroll
        for (int kk2 = 0; kk2 < 4; kk2++) {
#pragma unroll
            for (int p = 0; p < 8; p++) {
                const uint32_t off = ((p * 16 + laneNK) * VSTR + laneKhi + kk2 * 16) * 2;
                uint32_t fvh[4], fvl[4];
                ldm_x4(fvh, buf + AV_H + off);
                ldm_x4(fvl, buf + AV_L + off);
                uint32_t b0h[2] = {fvh[0], fvh[1]}, b1h[2] = {fvh[2], fvh[3]};
                uint32_t b0l[2] = {fvl[0], fvl[1]}, b1l[2] = {fvl[2], fvl[3]};
                mma16816(o[2 * p],     ph[kk2], b0h);
                mma16816(o[2 * p + 1], ph[kk2], b1h);
                mma16816(o[2 * p],     pl[kk2], b0h);
                mma16816(o[2 * p + 1], pl[kk2], b1h);
                mma16816(o[2 * p],     ph[kk2], b0l);
                mma16816(o[2 * p + 1], ph[kk2], b1l);
            }
        }

        __syncthreads();
        if (kt + 2 < nkt) {
            attn_load_kv(Kh, Kl, Vth, Vtl, sb + AKV0 + (kt & 1) * KVBUF,
                         kbase, vtbase, (kt + 2) * 64, tid);
            CP_COMMIT();
        }
    }

    // ---- epilogue: write ctx directly as bf16 hi/lo ----
    const float inv0 = 1.f / sl0, inv1 = 1.f / sl1;
#pragma unroll
    for (int jj = 0; jj < 16; jj++) {
        const int d = jj * 8 + tq * 2;
        const size_t o0 = (size_t)(b * SEQ + r0) * HIDDEN + h * HDIM + d;
        const size_t o1 = o0 + (size_t)8 * HIDDEN;
        const float v00 = o[jj][0] * inv0, v01 = o[jj][1] * inv0;
        const float v10 = o[jj][2] * inv1, v11 = o[jj][3] * inv1;
        uint32_t h0w = packbf(v00, v01);
        uint32_t h1w = packbf(v10, v11);
        __nv_bfloat162 hb0 = *(__nv_bfloat162*)&h0w;
        __nv_bfloat162 hb1 = *(__nv_bfloat162*)&h1w;
        uint32_t l0w = packbf(v00 - __bfloat162float(hb0.x), v01 - __bfloat162float(hb0.y));
        uint32_t l1w = packbf(v10 - __bfloat162float(hb1.x), v11 - __bfloat162float(hb1.y));
        *(uint32_t*)(Ch + o0) = h0w;
        *(uint32_t*)(Cl + o0) = l0w;
        *(uint32_t*)(Ch + o1) = h1w;
        *(uint32_t*)(Cl + o1) = l1w;
    }
}

// ---------------------------------------------------------------------------
// Launch
// ---------------------------------------------------------------------------
extern "C" void kernel_launch(void* const* d_in, const int* in_sizes, int n_in,
                              void* d_out, int out_size) {
    const float* X   = (const float*)d_in[0];
    const int*   pos = (const int*)  d_in[1];
    const float* Wq  = (const float*)d_in[2];
    const float* Wk  = (const float*)d_in[3];
    const float* Wv  = (const float*)d_in[4];
    const float* Wo  = (const float*)d_in[5];
    float* out = (float*)d_out;

    float* QKV;
    __nv_bfloat16 *Xh, *Xl, *Ch, *Cl, *W3h, *W3l, *Woh, *Wol;
    __nv_bfloat16 *Qbh, *Qbl, *Kbh, *Kbl, *Vth, *Vtl;
    cudaGetSymbolAddress((void**)&QKV, g_QKV);
    cudaGetSymbolAddress((void**)&Xh, g_Xh);
    cudaGetSymbolAddress((void**)&Xl, g_Xl);
    cudaGetSymbolAddress((void**)&Ch, g_Ch);
    cudaGetSymbolAddress((void**)&Cl, g_Cl);
    cudaGetSymbolAddress((void**)&W3h, g_W3hT);
    cudaGetSymbolAddress((void**)&W3l, g_W3lT);
    cudaGetSymbolAddress((void**)&Woh, g_WohT);
    cudaGetSymbolAddress((void**)&Wol, g_WolT);
    cudaGetSymbolAddress((void**)&Qbh, g_Qbh);
    cudaGetSymbolAddress((void**)&Qbl, g_Qbl);
    cudaGetSymbolAddress((void**)&Kbh, g_Kbh);
    cudaGetSymbolAddress((void**)&Kbl, g_Kbl);
    cudaGetSymbolAddress((void**)&Vth, g_Vth);
    cudaGetSymbolAddress((void**)&Vtl, g_Vtl);

    // Split / transpose conversions
    const int total8 = MROWS * KDIM / 8;
    split_a2_kernel<<<(total8 + 255) / 256, 256>>>(X, Xh, Xl, total8);
    split_w2_kernel<<<dim3(64, 64), dim3(32, 8)>>>(Wq, W3h, W3l, 2048);
    split_w2_kernel<<<dim3(64, 16), dim3(32, 8)>>>(Wk, W3h + (size_t)HIDDEN * KDIM,
                                                   W3l + (size_t)HIDDEN * KDIM, 512);
    split_w2_kernel<<<dim3(64, 16), dim3(32, 8)>>>(
        Wv, W3h + (size_t)(HIDDEN + NKVH * HDIM) * KDIM,
        W3l + (size_t)(HIDDEN + NKVH * HDIM) * KDIM, 512);
    split_w2_kernel<<<dim3(64, 64), dim3(32, 8)>>>(Wo, Woh, Wol, 2048);

    cudaFuncSetAttribute(mma_gemm, cudaFuncAttributeMaxDynamicSharedMemorySize, GEMM_SMEM);

    // Fused QKV projection (N=3072)
    mma_gemm<<<dim3(N_QKV / 128, 32), 256, GEMM_SMEM>>>(Xh, Xl, W3h, W3l, QKV, N_QKV);

    // RoPE + split to attention layouts
    const int rope_total = BATCH * SEQ * (NHEADS + NKVH) * 64;
    rope_split_kernel<<<(rope_total + 255) / 256, 256>>>(QKV, pos, Qbh, Qbl, Kbh, Kbl);
    vt_split_kernel<<<dim3(64, 4, 8), dim3(32, 8)>>>(QKV, Vth, Vtl);

    // Tensor-core flash attention (emits Ch/Cl bf16 hi/lo)
    cudaFuncSetAttribute(attn_mma_kernel, cudaFuncAttributeMaxDynamicSharedMemorySize, ATTN_SMEM);
    attn_mma_kernel<<<dim3(SEQ / 128, NHEADS, BATCH), 256, ATTN_SMEM>>>(
        Qbh, Qbl, Kbh, Kbl, Vth, Vtl, Ch, Cl);

    // Output projection
    mma_gemm<<<dim3(16, 32), 256, GEMM_SMEM>>>(Ch, Cl, Woh, Wol, out, 2048);
}

// round 9
// speedup vs baseline: 5.5016x; 1.4481x over previous
#include <cuda_runtime.h>
#include <cuda_fp16.h>
#include <cstdint>
#include <math.h>

// Problem constants
constexpr int BATCH  = 2;
constexpr int SEQ    = 2048;
constexpr int HIDDEN = 2048;
constexpr int NHEADS = 16;
constexpr int NKVH   = 4;
constexpr int HDIM   = 128;
constexpr float QK_SCALE = 0.08838834764831845f; // 1/sqrt(128)

constexpr int MROWS = BATCH * SEQ;   // 4096
constexpr int KDIM  = HIDDEN;        // 2048
constexpr int N_QKV = HIDDEN + 2 * NKVH * HDIM;  // 3072

// ---------------------------------------------------------------------------
// Device-global scratch
// ---------------------------------------------------------------------------
__device__ float g_QKV[(size_t)MROWS * N_QKV];    // fused Q|K|V fp32

__device__ __align__(16) __half g_Xh[(size_t)MROWS * KDIM];
__device__ __align__(16) __half g_Xl[(size_t)MROWS * KDIM];
__device__ __align__(16) __half g_Ch[(size_t)MROWS * KDIM];
__device__ __align__(16) __half g_Cl[(size_t)MROWS * KDIM];
__device__ __align__(16) __half g_W3T[(size_t)N_QKV * KDIM];   // Wq|Wk|Wv ^T (hi only)
__device__ __align__(16) __half g_WoT[(size_t)HIDDEN * KDIM];  // Wo^T (hi only)

// Attention operands
__device__ __align__(16) __half g_Qbh[(size_t)BATCH * NHEADS * SEQ * HDIM];
__device__ __align__(16) __half g_Qbl[(size_t)BATCH * NHEADS * SEQ * HDIM];
__device__ __align__(16) __half g_Kbh[(size_t)BATCH * NKVH * SEQ * HDIM];
__device__ __align__(16) __half g_Vth[(size_t)BATCH * NKVH * HDIM * SEQ];

// ---------------------------------------------------------------------------
// PTX helpers
// ---------------------------------------------------------------------------
__device__ __forceinline__ uint32_t smem_u32(const void* p) {
    uint32_t a;
    asm("{ .reg .u64 t; cvta.to.shared.u64 t, %1; cvt.u32.u64 %0, t; }"
        : "=r"(a) : "l"(p));
    return a;
}

#define CP_ASYNC16(dst, src) \
    asm volatile("cp.async.cg.shared.global [%0], [%1], 16;" :: "r"(dst), "l"(src))
#define CP_COMMIT() asm volatile("cp.async.commit_group;" ::: "memory")
#define CP_WAIT(n)  asm volatile("cp.async.wait_group %0;" :: "n"(n) : "memory")

__device__ __forceinline__ void ldm_x4(uint32_t* r, uint32_t addr) {
    asm volatile("ldmatrix.sync.aligned.m8n8.x4.shared.b16 {%0,%1,%2,%3}, [%4];"
                 : "=r"(r[0]), "=r"(r[1]), "=r"(r[2]), "=r"(r[3]) : "r"(addr));
}
__device__ __forceinline__ void mma16816(float* d, const uint32_t* a, const uint32_t* b) {
    asm volatile("mma.sync.aligned.m16n8k16.row.col.f32.f16.f16.f32 "
                 "{%0,%1,%2,%3}, {%4,%5,%6,%7}, {%8,%9}, {%0,%1,%2,%3};"
                 : "+f"(d[0]), "+f"(d[1]), "+f"(d[2]), "+f"(d[3])
                 : "r"(a[0]), "r"(a[1]), "r"(a[2]), "r"(a[3]), "r"(b[0]), "r"(b[1]));
}
__device__ __forceinline__ uint32_t packh(float lo, float hi) {
    __half2 t = __floats2half2_rn(lo, hi);
    return *(uint32_t*)&t;
}

// ---------------------------------------------------------------------------
// Conversions
// ---------------------------------------------------------------------------
// fp32 -> fp16 hi + lo (A-side 2-term)
__global__ void split_a2_kernel(const float* __restrict__ X,
                                __half* __restrict__ H,
                                __half* __restrict__ L, int total8) {
    int t = blockIdx.x * blockDim.x + threadIdx.x;
    if (t >= total8) return;
    const int base = t * 8;
    float4 x0 = *(const float4*)(X + base);
    float4 x1 = *(const float4*)(X + base + 4);
    float xs[8] = {x0.x, x0.y, x0.z, x0.w, x1.x, x1.y, x1.z, x1.w};
    __half hs[8], ls[8];
#pragma unroll
    for (int i = 0; i < 8; i++) {
        hs[i] = __float2half_rn(xs[i]);
        ls[i] = __float2half_rn(xs[i] - __half2float(hs[i]));
    }
    *(uint4*)(H + base) = *(const uint4*)hs;
    *(uint4*)(L + base) = *(const uint4*)ls;
}

// All 4 weights: W [K][N] fp32 -> WT [N][K] fp16 (hi only), one launch.
__global__ void split_w_all_kernel(const float* __restrict__ Wq, const float* __restrict__ Wk,
                                   const float* __restrict__ Wv, const float* __restrict__ Wo,
                                   __half* __restrict__ W3T, __half* __restrict__ WoT) {
    __shared__ float s[32][33];
    const int z = blockIdx.z;
    const float* W;
    __half* dst;
    int N, rowoff;
    if      (z == 0) { W = Wq; dst = W3T; N = 2048; rowoff = 0;    }
    else if (z == 1) { W = Wk; dst = W3T; N = 512;  rowoff = 2048; }
    else if (z == 2) { W = Wv; dst = W3T; N = 512;  rowoff = 2560; }
    else             { W = Wo; dst = WoT; N = 2048; rowoff = 0;    }
    const int n0 = blockIdx.y * 32;
    if (n0 >= N) return;
    const int k0 = blockIdx.x * 32;
    const int tx = threadIdx.x, ty = threadIdx.y;  // 32 x 8
#pragma unroll
    for (int i = 0; i < 4; i++)
        s[ty + 8 * i][tx] = W[(size_t)(k0 + ty + 8 * i) * N + n0 + tx];
    __syncthreads();
#pragma unroll
    for (int i = 0; i < 4; i++) {
        const int n = ty + 8 * i;
        dst[(size_t)(rowoff + n0 + n) * KDIM + k0 + tx] = __float2half_rn(s[tx][n]);
    }
}

// ---------------------------------------------------------------------------
// fp16 mma.sync GEMM: C = (Ah + Al) @ B^T, 2 mma terms.
// CTA 128x128, BK=32, 3-stage cp.async pipeline, 8 warps (64x32 warp tile).
// ---------------------------------------------------------------------------
constexpr int GSTRIDE = 40;                 // halfs per row (32 + pad)
constexpr int GTILE_B = 128 * GSTRIDE * 2;  // 10240 bytes
constexpr int GSTAGE_B = 3 * GTILE_B;       // Ah|Al|B = 30720
constexpr int GEMM_SMEM = 3 * GSTAGE_B;     // 92160 (3 stages)

__device__ __forceinline__ void gemm_load_stage(
    const __half* __restrict__ Ah, const __half* __restrict__ Al,
    const __half* __restrict__ Bt,
    uint32_t stageBase, int m0, int n0, int k0, int tid) {
#pragma unroll
    for (int i = 0; i < 6; i++) {
        const int idx = tid + i * 256;      // 0..1535
        const int tile = idx >> 9;          // 0..2
        const int c = idx & 511;
        const int row = c >> 2;
        const int kc = (c & 3) * 8;
        const __half* src;
        if      (tile == 0) src = Ah + (size_t)(m0 + row) * KDIM + k0 + kc;
        else if (tile == 1) src = Al + (size_t)(m0 + row) * KDIM + k0 + kc;
        else                src = Bt + (size_t)(n0 + row) * KDIM + k0 + kc;
        const uint32_t dst = stageBase + tile * GTILE_B + (row * GSTRIDE + kc) * 2;
        CP_ASYNC16(dst, src);
    }
}

__global__ __launch_bounds__(256, 2)
void mma_gemm(const __half* __restrict__ Ah, const __half* __restrict__ Al,
              const __half* __restrict__ Bt, float* __restrict__ C, int N) {
    extern __shared__ __align__(16) uint8_t smg[];
    const uint32_t sb = smem_u32(smg);
    const int tid = threadIdx.x;
    const int wid = tid >> 5, lane = tid & 31;
    const int m0 = blockIdx.y * 128, n0 = blockIdx.x * 128;
    const int mw = (wid & 1) * 64;
    const int nw = (wid >> 1) * 32;

    float acc[4][4][4];
#pragma unroll
    for (int i = 0; i < 4; i++)
#pragma unroll
        for (int j = 0; j < 4; j++)
#pragma unroll
            for (int q = 0; q < 4; q++) acc[i][j][q] = 0.f;

    const uint32_t laneA = ((lane & 15) * GSTRIDE + (lane >> 4) * 8) * 2;
    const uint32_t laneB = ((((lane >> 4) << 3) + (lane & 7)) * GSTRIDE
                           + ((lane >> 3) & 1) * 8) * 2;

    const int T = KDIM / 32;   // 64
    gemm_load_stage(Ah, Al, Bt, sb, m0, n0, 0, tid);             CP_COMMIT();
    gemm_load_stage(Ah, Al, Bt, sb + GSTAGE_B, m0, n0, 32, tid); CP_COMMIT();

    for (int t = 0; t < T; t++) {
        const uint32_t stg = sb + (t % 3) * GSTAGE_B;
        if (t + 1 < T) { CP_WAIT(1); } else { CP_WAIT(0); }
        __syncthreads();

        const uint32_t aH = stg + 0 * GTILE_B + mw * GSTRIDE * 2 + laneA;
        const uint32_t aL = stg + 1 * GTILE_B + mw * GSTRIDE * 2 + laneA;
        const uint32_t bB = stg + 2 * GTILE_B + nw * GSTRIDE * 2 + laneB;

#pragma unroll
        for (int kk = 0; kk < 2; kk++) {
            const uint32_t ko = kk * 32;
            uint32_t fb[2][4];
#pragma unroll
            for (int p = 0; p < 2; p++)
                ldm_x4(fb[p], bB + p * 16 * GSTRIDE * 2 + ko);
#pragma unroll
            for (int i = 0; i < 4; i++) {
                uint32_t fah[4], fal[4];
                ldm_x4(fah, aH + i * 16 * GSTRIDE * 2 + ko);
                ldm_x4(fal, aL + i * 16 * GSTRIDE * 2 + ko);
#pragma unroll
                for (int j = 0; j < 4; j++) {
                    const int p = j >> 1, h = (j & 1) * 2;
                    uint32_t bf[2] = {fb[p][h], fb[p][h + 1]};
                    mma16816(acc[i][j], fah, bf);
                    mma16816(acc[i][j], fal, bf);
                }
            }
        }
        __syncthreads();
        if (t + 2 < T) {
            gemm_load_stage(Ah, Al, Bt, sb + ((t + 2) % 3) * GSTAGE_B,
                            m0, n0, (t + 2) * 32, tid);
            CP_COMMIT();
        }
    }

    const int g = lane >> 2, tq = lane & 3;
#pragma unroll
    for (int i = 0; i < 4; i++) {
        const int r0 = m0 + mw + i * 16 + g;
#pragma unroll
        for (int j = 0; j < 4; j++) {
            const int col = n0 + nw + j * 8 + tq * 2;
            *(float2*)(C + (size_t)r0 * N + col)       = make_float2(acc[i][j][0], acc[i][j][1]);
            *(float2*)(C + (size_t)(r0 + 8) * N + col) = make_float2(acc[i][j][2], acc[i][j][3]);
        }
    }
}

// ---------------------------------------------------------------------------
// RoPE + split + head-major relayout from fused QKV [4096][3072]:
//   Q -> Qbh/Qbl fp16 hi/lo [B,H,S,D] (pre-scaled); K -> Kbh fp16 [B,kvh,S,D]
// ---------------------------------------------------------------------------
__global__ void rope_split_kernel(const float* __restrict__ QKV,
                                  const int* __restrict__ pos,
                                  __half* __restrict__ Qh, __half* __restrict__ Ql,
                                  __half* __restrict__ Kh) {
    const int total = BATCH * SEQ * (NHEADS + NKVH) * 64;
    int idx = blockIdx.x * blockDim.x + threadIdx.x;
    if (idx >= total) return;
    const int p = idx & 63;
    int rest = idx >> 6;
    const int hh = rest % (NHEADS + NKVH);
    const int bs = rest / (NHEADS + NKVH);
    const int b = bs >> 11, s = bs & 2047;

    const float fpos = (float)pos[bs];
    const float inv = powf(10000.f, -(float)p * (1.f / 64.f));
    const float ang = fpos * inv;
    float sn, c;
    sincosf(ang, &sn, &c);

    if (hh < NHEADS) {
        const float* src = QKV + (size_t)bs * N_QKV + hh * HDIM;
        const float x1 = src[p], x2 = src[p + 64];
        const float y1 = (x1 * c - x2 * sn) * QK_SCALE;
        const float y2 = (x2 * c + x1 * sn) * QK_SCALE;
        const size_t obase = ((size_t)(b * NHEADS + hh) * SEQ + s) * HDIM;
        __half h1 = __float2half_rn(y1);
        __half h2 = __float2half_rn(y2);
        Qh[obase + p]      = h1;
        Qh[obase + p + 64] = h2;
        Ql[obase + p]      = __float2half_rn(y1 - __half2float(h1));
        Ql[obase + p + 64] = __float2half_rn(y2 - __half2float(h2));
    } else {
        const int kv = hh - NHEADS;
        const float* src = QKV + (size_t)bs * N_QKV + HIDDEN + kv * HDIM;
        const float x1 = src[p], x2 = src[p + 64];
        const size_t obase = ((size_t)(b * NKVH + kv) * SEQ + s) * HDIM;
        Kh[obase + p]      = __float2half_rn(x1 * c - x2 * sn);
        Kh[obase + p + 64] = __float2half_rn(x2 * c + x1 * sn);
    }
}

// V (QKV cols [2560,3072)) -> Vth fp16 [B,kvh,D,S] (transpose, hi only)
__global__ void vt_split_kernel(const float* __restrict__ QKV,
                                __half* __restrict__ TH) {
    __shared__ float s[32][33];
    const int s0 = blockIdx.x * 32, d0 = blockIdx.y * 32;
    const int b = blockIdx.z >> 2, kv = blockIdx.z & 3;
    const int tx = threadIdx.x, ty = threadIdx.y;   // 32 x 8
#pragma unroll
    for (int i = 0; i < 4; i++) {
        const int ss = s0 + ty + 8 * i;
        s[ty + 8 * i][tx] =
            QKV[(size_t)(b * SEQ + ss) * N_QKV + HIDDEN + NKVH * HDIM + kv * HDIM + d0 + tx];
    }
    __syncthreads();
#pragma unroll
    for (int i = 0; i < 4; i++) {
        const int d = ty + 8 * i;
        const size_t o = ((size_t)(b * NKVH + kv) * HDIM + d0 + d) * SEQ + s0 + tx;
        TH[o] = __float2half_rn(s[tx][d]);
    }
}

// ---------------------------------------------------------------------------
// Tensor-core flash attention (causal, GQA, fp16: Q 2-term, K/V/P 1-term).
// BQ=128, BK=64, 256 threads, double-buffered cp.async KV.
// ---------------------------------------------------------------------------
constexpr int ASTR = 136;
constexpr int VSTR = 72;
constexpr int AQ_H = 0;
constexpr int AQ_L = 128 * ASTR * 2;                 // 34816
constexpr int AKV0 = 2 * 128 * ASTR * 2;             // 69632
constexpr int AK_H = 0;
constexpr int AV_H = 64 * ASTR * 2;                  // 17408
constexpr int KVBUF = AV_H + 128 * VSTR * 2;         // 35840
constexpr int ATTN_SMEM = AKV0 + 2 * KVBUF;          // 141312

__device__ __forceinline__ void attn_load_kv(
    const __half* __restrict__ Kh, const __half* __restrict__ Vth,
    uint32_t bufBase, size_t kbase, size_t vtbase, int k0, int tid) {
#pragma unroll
    for (int i = 0; i < 8; i++) {
        const int idx = tid + i * 256;   // 0..2047
        if (idx < 1024) {                // K tile: 64 rows x 16 chunks
            const int row = idx >> 4, c = idx & 15;
            const __half* src = Kh + kbase + (size_t)(k0 + row) * HDIM + c * 8;
            const uint32_t dst = bufBase + AK_H + (row * ASTR + c * 8) * 2;
            CP_ASYNC16(dst, src);
        } else {                         // V tile: 128 rows x 8 chunks
            const int v = idx - 1024;
            const int row = v >> 3, c = v & 7;
            const __half* src = Vth + vtbase + (size_t)row * SEQ + k0 + c * 8;
            const uint32_t dst = bufBase + AV_H + (row * VSTR + c * 8) * 2;
            CP_ASYNC16(dst, src);
        }
    }
}

__global__ __launch_bounds__(256, 1)
void attn_mma_kernel(const __half* __restrict__ Qh, const __half* __restrict__ Ql,
                     const __half* __restrict__ Kh, const __half* __restrict__ Vth,
                     __half* __restrict__ Ch, __half* __restrict__ Cl) {
    extern __shared__ __align__(16) uint8_t smb[];
    const uint32_t sb = smem_u32(smb);
    const int tid = threadIdx.x;
    const int wid = tid >> 5, lane = tid & 31;
    const int g = lane >> 2, tq = lane & 3;

    const int qt = gridDim.x - 1 - blockIdx.x;
    const int h = blockIdx.y, b = blockIdx.z;
    const int kvh = h >> 2;
    const int q0 = qt * 128;
    const int nkt = 2 * qt + 2;

    const size_t qbase  = ((size_t)(b * NHEADS + h) * SEQ + q0) * HDIM;
    const size_t kbase  = ((size_t)(b * NKVH + kvh) * SEQ) * HDIM;
    const size_t vtbase = ((size_t)(b * NKVH + kvh) * HDIM) * SEQ;

#pragma unroll
    for (int i = 0; i < 16; i++) {
        const int idx = tid + i * 256;
        const int half_ = idx >> 11;
        const int j = idx & 2047;
        const int row = j >> 4, c = j & 15;
        const __half* src = (half_ ? Ql : Qh) + qbase + (size_t)row * HDIM + c * 8;
        const uint32_t dst = sb + (half_ ? AQ_L : AQ_H) + (row * ASTR + c * 8) * 2;
        CP_ASYNC16(dst, src);
    }
    CP_COMMIT();
    attn_load_kv(Kh, Vth, sb + AKV0,         kbase, vtbase, 0,  tid); CP_COMMIT();
    attn_load_kv(Kh, Vth, sb + AKV0 + KVBUF, kbase, vtbase, 64, tid); CP_COMMIT();

    CP_WAIT(2);
    __syncthreads();
    uint32_t qfh[8][4], qfl[8][4];
    {
        const uint32_t la = ((wid * 16 + (lane & 15)) * ASTR + (lane >> 4) * 8) * 2;
#pragma unroll
        for (int kk = 0; kk < 8; kk++) {
            ldm_x4(qfh[kk], sb + AQ_H + la + kk * 32);
            ldm_x4(qfl[kk], sb + AQ_L + la + kk * 32);
        }
    }

    float o[16][4];
#pragma unroll
    for (int jj = 0; jj < 16; jj++)
#pragma unroll
        for (int q = 0; q < 4; q++) o[jj][q] = 0.f;
    float m0 = -1e30f, m1 = -1e30f, sl0 = 0.f, sl1 = 0.f;

    const int r0 = q0 + wid * 16 + g;
    const uint32_t laneNK = ((lane >> 4) * 8 + (lane & 7));
    const uint32_t laneKhi = ((lane >> 3) & 1) * 8;

    for (int kt = 0; kt < nkt; kt++) {
        const int k0 = kt * 64;
        const uint32_t buf = sb + AKV0 + (kt & 1) * KVBUF;
        if (kt + 1 < nkt) { CP_WAIT(1); } else { CP_WAIT(0); }
        __syncthreads();

        // ---- S = Q K^T (Q 2-term, K 1-term) ----
        float sacc[8][4];
#pragma unroll
        for (int j = 0; j < 8; j++)
#pragma unroll
            for (int q = 0; q < 4; q++) sacc[j][q] = 0.f;

#pragma unroll
        for (int kk = 0; kk < 8; kk++) {
#pragma unroll
            for (int p = 0; p < 4; p++) {
                const uint32_t off = ((p * 16 + laneNK) * ASTR + laneKhi) * 2 + kk * 32;
                uint32_t fk[4];
                ldm_x4(fk, buf + AK_H + off);
                uint32_t b0[2] = {fk[0], fk[1]}, b1[2] = {fk[2], fk[3]};
                mma16816(sacc[2 * p],     qfh[kk], b0);
                mma16816(sacc[2 * p + 1], qfh[kk], b1);
                mma16816(sacc[2 * p],     qfl[kk], b0);
                mma16816(sacc[2 * p + 1], qfl[kk], b1);
            }
        }

        // ---- causal mask ----
        if (kt >= nkt - 2) {
#pragma unroll
            for (int j = 0; j < 8; j++) {
#pragma unroll
                for (int e = 0; e < 2; e++) {
                    const int col = k0 + j * 8 + tq * 2 + e;
                    if (col > r0)     sacc[j][e]     = -1e30f;
                    if (col > r0 + 8) sacc[j][2 + e] = -1e30f;
                }
            }
        }

        // ---- online softmax ----
        float mt0 = -1e30f, mt1 = -1e30f;
#pragma unroll
        for (int j = 0; j < 8; j++) {
            mt0 = fmaxf(mt0, fmaxf(sacc[j][0], sacc[j][1]));
            mt1 = fmaxf(mt1, fmaxf(sacc[j][2], sacc[j][3]));
        }
        mt0 = fmaxf(mt0, __shfl_xor_sync(0xffffffffu, mt0, 1));
        mt0 = fmaxf(mt0, __shfl_xor_sync(0xffffffffu, mt0, 2));
        mt1 = fmaxf(mt1, __shfl_xor_sync(0xffffffffu, mt1, 1));
        mt1 = fmaxf(mt1, __shfl_xor_sync(0xffffffffu, mt1, 2));
        const float mn0 = fmaxf(m0, mt0), mn1 = fmaxf(m1, mt1);
        const float al0 = __expf(m0 - mn0), al1 = __expf(m1 - mn1);
        float s0 = 0.f, s1 = 0.f;
#pragma unroll
        for (int j = 0; j < 8; j++) {
            sacc[j][0] = __expf(sacc[j][0] - mn0);
            sacc[j][1] = __expf(sacc[j][1] - mn0);
            sacc[j][2] = __expf(sacc[j][2] - mn1);
            sacc[j][3] = __expf(sacc[j][3] - mn1);
            s0 += sacc[j][0] + sacc[j][1];
            s1 += sacc[j][2] + sacc[j][3];
        }
        s0 += __shfl_xor_sync(0xffffffffu, s0, 1);
        s0 += __shfl_xor_sync(0xffffffffu, s0, 2);
        s1 += __shfl_xor_sync(0xffffffffu, s1, 1);
        s1 += __shfl_xor_sync(0xffffffffu, s1, 2);
        sl0 = sl0 * al0 + s0;  sl1 = sl1 * al1 + s1;
        m0 = mn0;              m1 = mn1;
#pragma unroll
        for (int jj = 0; jj < 16; jj++) {
            o[jj][0] *= al0; o[jj][1] *= al0;
            o[jj][2] *= al1; o[jj][3] *= al1;
        }

        // ---- P fragments (single fp16 term) ----
        uint32_t ph[4][4];
#pragma unroll
        for (int kk2 = 0; kk2 < 4; kk2++) {
            const int j0 = 2 * kk2, j1 = j0 + 1;
            ph[kk2][0] = packh(sacc[j0][0], sacc[j0][1]);
            ph[kk2][1] = packh(sacc[j0][2], sacc[j0][3]);
            ph[kk2][2] = packh(sacc[j1][0], sacc[j1][1]);
            ph[kk2][3] = packh(sacc[j1][2], sacc[j1][3]);
        }

        // ---- O += P V ----
#pragma unroll
        for (int kk2 = 0; kk2 < 4; kk2++) {
#pragma unroll
            for (int p = 0; p < 8; p++) {
                const uint32_t off = ((p * 16 + laneNK) * VSTR + laneKhi + kk2 * 16) * 2;
                uint32_t fv[4];
                ldm_x4(fv, buf + AV_H + off);
                uint32_t b0[2] = {fv[0], fv[1]}, b1[2] = {fv[2], fv[3]};
                mma16816(o[2 * p],     ph[kk2], b0);
                mma16816(o[2 * p + 1], ph[kk2], b1);
            }
        }

        __syncthreads();
        if (kt + 2 < nkt) {
            attn_load_kv(Kh, Vth, sb + AKV0 + (kt & 1) * KVBUF,
                         kbase, vtbase, (kt + 2) * 64, tid);
            CP_COMMIT();
        }
    }

    // ---- epilogue: ctx as fp16 hi/lo ----
    const float inv0 = 1.f / sl0, inv1 = 1.f / sl1;
#pragma unroll
    for (int jj = 0; jj < 16; jj++) {
        const int d = jj * 8 + tq * 2;
        const size_t o0 = (size_t)(b * SEQ + r0) * HIDDEN + h * HDIM + d;
        const size_t o1 = o0 + (size_t)8 * HIDDEN;
        const float v00 = o[jj][0] * inv0, v01 = o[jj][1] * inv0;
        const float v10 = o[jj][2] * inv1, v11 = o[jj][3] * inv1;
        uint32_t h0w = packh(v00, v01);
        uint32_t h1w = packh(v10, v11);
        __half2 hb0 = *(__half2*)&h0w;
        __half2 hb1 = *(__half2*)&h1w;
        uint32_t l0w = packh(v00 - __half2float(hb0.x), v01 - __half2float(hb0.y));
        uint32_t l1w = packh(v10 - __half2float(hb1.x), v11 - __half2float(hb1.y));
        *(uint32_t*)(Ch + o0) = h0w;
        *(uint32_t*)(Cl + o0) = l0w;
        *(uint32_t*)(Ch + o1) = h1w;
        *(uint32_t*)(Cl + o1) = l1w;
    }
}

// ---------------------------------------------------------------------------
// Launch (order chosen so ncu -s 5 -c 1 captures attn_mma_kernel)
// ---------------------------------------------------------------------------
extern "C" void kernel_launch(void* const* d_in, const int* in_sizes, int n_in,
                              void* d_out, int out_size) {
    const float* X   = (const float*)d_in[0];
    const int*   pos = (const int*)  d_in[1];
    const float* Wq  = (const float*)d_in[2];
    const float* Wk  = (const float*)d_in[3];
    const float* Wv  = (const float*)d_in[4];
    const float* Wo  = (const float*)d_in[5];
    float* out = (float*)d_out;

    float* QKV;
    __half *Xh, *Xl, *Ch, *Cl, *W3, *WoT;
    __half *Qbh, *Qbl, *Kbh, *Vth;
    cudaGetSymbolAddress((void**)&QKV, g_QKV);
    cudaGetSymbolAddress((void**)&Xh, g_Xh);
    cudaGetSymbolAddress((void**)&Xl, g_Xl);
    cudaGetSymbolAddress((void**)&Ch, g_Ch);
    cudaGetSymbolAddress((void**)&Cl, g_Cl);
    cudaGetSymbolAddress((void**)&W3, g_W3T);
    cudaGetSymbolAddress((void**)&WoT, g_WoT);
    cudaGetSymbolAddress((void**)&Qbh, g_Qbh);
    cudaGetSymbolAddress((void**)&Qbl, g_Qbl);
    cudaGetSymbolAddress((void**)&Kbh, g_Kbh);
    cudaGetSymbolAddress((void**)&Vth, g_Vth);

    // 1: activation split, 2: all weight splits
    const int total8 = MROWS * KDIM / 8;
    split_a2_kernel<<<(total8 + 255) / 256, 256>>>(X, Xh, Xl, total8);
    split_w_all_kernel<<<dim3(64, 64, 4), dim3(32, 8)>>>(Wq, Wk, Wv, Wo, W3, WoT);

    cudaFuncSetAttribute(mma_gemm, cudaFuncAttributeMaxDynamicSharedMemorySize, GEMM_SMEM);

    // 3: fused QKV projection (N=3072)
    mma_gemm<<<dim3(N_QKV / 128, 32), 256, GEMM_SMEM>>>(Xh, Xl, W3, QKV, N_QKV);

    // 4-5: RoPE + V transpose
    const int rope_total = BATCH * SEQ * (NHEADS + NKVH) * 64;
    rope_split_kernel<<<(rope_total + 255) / 256, 256>>>(QKV, pos, Qbh, Qbl, Kbh);
    vt_split_kernel<<<dim3(64, 4, 8), dim3(32, 8)>>>(QKV, Vth);

    // 6: flash attention
    cudaFuncSetAttribute(attn_mma_kernel, cudaFuncAttributeMaxDynamicSharedMemorySize, ATTN_SMEM);
    attn_mma_kernel<<<dim3(SEQ / 128, NHEADS, BATCH), 256, ATTN_SMEM>>>(
        Qbh, Qbl, Kbh, Vth, Ch, Cl);

    // 7: output projection
    mma_gemm<<<dim3(16, 32), 256, GEMM_SMEM>>>(Ch, Cl, WoT, out, 2048);
}

// round 10
// speedup vs baseline: 6.3087x; 1.1467x over previous
#include <cuda_runtime.h>
#include <cuda_fp16.h>
#include <cstdint>
#include <math.h>

// Problem constants
constexpr int BATCH  = 2;
constexpr int SEQ    = 2048;
constexpr int HIDDEN = 2048;
constexpr int NHEADS = 16;
constexpr int NKVH   = 4;
constexpr int HDIM   = 128;
constexpr float QK_SCALE = 0.08838834764831845f; // 1/sqrt(128)

constexpr int MROWS = BATCH * SEQ;   // 4096
constexpr int KDIM  = HIDDEN;        // 2048
constexpr int N_QKV = HIDDEN + 2 * NKVH * HDIM;  // 3072

// ---------------------------------------------------------------------------
// Device-global scratch
// ---------------------------------------------------------------------------
__device__ float g_QKV[(size_t)MROWS * N_QKV];    // fused Q|K|V fp32

__device__ __align__(16) __half g_Xh[(size_t)MROWS * KDIM];
__device__ __align__(16) __half g_Xl[(size_t)MROWS * KDIM];
__device__ __align__(16) __half g_Ch[(size_t)MROWS * KDIM];   // ctx fp16 (single term)
__device__ __align__(16) __half g_W3T[(size_t)N_QKV * KDIM];  // Wq|Wk|Wv ^T
__device__ __align__(16) __half g_WoT[(size_t)HIDDEN * KDIM]; // Wo^T

// Attention operands
__device__ __align__(16) __half g_Qbh[(size_t)BATCH * NHEADS * SEQ * HDIM];
__device__ __align__(16) __half g_Qbl[(size_t)BATCH * NHEADS * SEQ * HDIM];
__device__ __align__(16) __half g_Kbh[(size_t)BATCH * NKVH * SEQ * HDIM];
__device__ __align__(16) __half g_Vth[(size_t)BATCH * NKVH * HDIM * SEQ];

// ---------------------------------------------------------------------------
// PTX helpers
// ---------------------------------------------------------------------------
__device__ __forceinline__ uint32_t smem_u32(const void* p) {
    uint32_t a;
    asm("{ .reg .u64 t; cvta.to.shared.u64 t, %1; cvt.u32.u64 %0, t; }"
        : "=r"(a) : "l"(p));
    return a;
}

#define CP_ASYNC16(dst, src) \
    asm volatile("cp.async.cg.shared.global [%0], [%1], 16;" :: "r"(dst), "l"(src))
#define CP_COMMIT() asm volatile("cp.async.commit_group;" ::: "memory")
#define CP_WAIT(n)  asm volatile("cp.async.wait_group %0;" :: "n"(n) : "memory")

__device__ __forceinline__ void ldm_x4(uint32_t* r, uint32_t addr) {
    asm volatile("ldmatrix.sync.aligned.m8n8.x4.shared.b16 {%0,%1,%2,%3}, [%4];"
                 : "=r"(r[0]), "=r"(r[1]), "=r"(r[2]), "=r"(r[3]) : "r"(addr));
}
__device__ __forceinline__ void mma16816(float* d, const uint32_t* a, const uint32_t* b) {
    asm volatile("mma.sync.aligned.m16n8k16.row.col.f32.f16.f16.f32 "
                 "{%0,%1,%2,%3}, {%4,%5,%6,%7}, {%8,%9}, {%0,%1,%2,%3};"
                 : "+f"(d[0]), "+f"(d[1]), "+f"(d[2]), "+f"(d[3])
                 : "r"(a[0]), "r"(a[1]), "r"(a[2]), "r"(a[3]), "r"(b[0]), "r"(b[1]));
}
__device__ __forceinline__ uint32_t packh(float lo, float hi) {
    __half2 t = __floats2half2_rn(lo, hi);
    return *(uint32_t*)&t;
}

// ---------------------------------------------------------------------------
// Conversions
// ---------------------------------------------------------------------------
__global__ void split_a2_kernel(const float* __restrict__ X,
                                __half* __restrict__ H,
                                __half* __restrict__ L, int total8) {
    int t = blockIdx.x * blockDim.x + threadIdx.x;
    if (t >= total8) return;
    const int base = t * 8;
    float4 x0 = *(const float4*)(X + base);
    float4 x1 = *(const float4*)(X + base + 4);
    float xs[8] = {x0.x, x0.y, x0.z, x0.w, x1.x, x1.y, x1.z, x1.w};
    __half hs[8], ls[8];
#pragma unroll
    for (int i = 0; i < 8; i++) {
        hs[i] = __float2half_rn(xs[i]);
        ls[i] = __float2half_rn(xs[i] - __half2float(hs[i]));
    }
    *(uint4*)(H + base) = *(const uint4*)hs;
    *(uint4*)(L + base) = *(const uint4*)ls;
}

// All 4 weights: W [K][N] fp32 -> WT [N][K] fp16 (hi only), one launch.
__global__ void split_w_all_kernel(const float* __restrict__ Wq, const float* __restrict__ Wk,
                                   const float* __restrict__ Wv, const float* __restrict__ Wo,
                                   __half* __restrict__ W3T, __half* __restrict__ WoT) {
    __shared__ float s[32][33];
    const int z = blockIdx.z;
    const float* W;
    __half* dst;
    int N, rowoff;
    if      (z == 0) { W = Wq; dst = W3T; N = 2048; rowoff = 0;    }
    else if (z == 1) { W = Wk; dst = W3T; N = 512;  rowoff = 2048; }
    else if (z == 2) { W = Wv; dst = W3T; N = 512;  rowoff = 2560; }
    else             { W = Wo; dst = WoT; N = 2048; rowoff = 0;    }
    const int n0 = blockIdx.y * 32;
    if (n0 >= N) return;
    const int k0 = blockIdx.x * 32;
    const int tx = threadIdx.x, ty = threadIdx.y;  // 32 x 8
#pragma unroll
    for (int i = 0; i < 4; i++)
        s[ty + 8 * i][tx] = W[(size_t)(k0 + ty + 8 * i) * N + n0 + tx];
    __syncthreads();
#pragma unroll
    for (int i = 0; i < 4; i++) {
        const int n = ty + 8 * i;
        dst[(size_t)(rowoff + n0 + n) * KDIM + k0 + tx] = __float2half_rn(s[tx][n]);
    }
}

// ---------------------------------------------------------------------------
// fp16 mma.sync GEMM, 2-term A (QKV projection).
// CTA 128x128, BK=32, 3-stage cp.async, 8 warps (64x32 warp tile).
// ---------------------------------------------------------------------------
constexpr int GSTRIDE = 40;
constexpr int GTILE_B = 128 * GSTRIDE * 2;  // 10240 bytes
constexpr int GSTAGE_B = 3 * GTILE_B;       // Ah|Al|B = 30720
constexpr int GEMM_SMEM = 3 * GSTAGE_B;     // 92160

__device__ __forceinline__ void gemm_load_stage(
    const __half* __restrict__ Ah, const __half* __restrict__ Al,
    const __half* __restrict__ Bt,
    uint32_t stageBase, int m0, int n0, int k0, int tid) {
#pragma unroll
    for (int i = 0; i < 6; i++) {
        const int idx = tid + i * 256;      // 0..1535
        const int tile = idx >> 9;
        const int c = idx & 511;
        const int row = c >> 2;
        const int kc = (c & 3) * 8;
        const __half* src;
        if      (tile == 0) src = Ah + (size_t)(m0 + row) * KDIM + k0 + kc;
        else if (tile == 1) src = Al + (size_t)(m0 + row) * KDIM + k0 + kc;
        else                src = Bt + (size_t)(n0 + row) * KDIM + k0 + kc;
        const uint32_t dst = stageBase + tile * GTILE_B + (row * GSTRIDE + kc) * 2;
        CP_ASYNC16(dst, src);
    }
}

__global__ __launch_bounds__(256, 2)
void mma_gemm(const __half* __restrict__ Ah, const __half* __restrict__ Al,
              const __half* __restrict__ Bt, float* __restrict__ C, int N) {
    extern __shared__ __align__(16) uint8_t smg[];
    const uint32_t sb = smem_u32(smg);
    const int tid = threadIdx.x;
    const int wid = tid >> 5, lane = tid & 31;
    const int m0 = blockIdx.y * 128, n0 = blockIdx.x * 128;
    const int mw = (wid & 1) * 64;
    const int nw = (wid >> 1) * 32;

    float acc[4][4][4];
#pragma unroll
    for (int i = 0; i < 4; i++)
#pragma unroll
        for (int j = 0; j < 4; j++)
#pragma unroll
            for (int q = 0; q < 4; q++) acc[i][j][q] = 0.f;

    const uint32_t laneA = ((lane & 15) * GSTRIDE + (lane >> 4) * 8) * 2;
    const uint32_t laneB = ((((lane >> 4) << 3) + (lane & 7)) * GSTRIDE
                           + ((lane >> 3) & 1) * 8) * 2;

    const int T = KDIM / 32;   // 64
    gemm_load_stage(Ah, Al, Bt, sb, m0, n0, 0, tid);             CP_COMMIT();
    gemm_load_stage(Ah, Al, Bt, sb + GSTAGE_B, m0, n0, 32, tid); CP_COMMIT();

    for (int t = 0; t < T; t++) {
        const uint32_t stg = sb + (t % 3) * GSTAGE_B;
        if (t + 1 < T) { CP_WAIT(1); } else { CP_WAIT(0); }
        __syncthreads();

        const uint32_t aH = stg + 0 * GTILE_B + mw * GSTRIDE * 2 + laneA;
        const uint32_t aL = stg + 1 * GTILE_B + mw * GSTRIDE * 2 + laneA;
        const uint32_t bB = stg + 2 * GTILE_B + nw * GSTRIDE * 2 + laneB;

#pragma unroll
        for (int kk = 0; kk < 2; kk++) {
            const uint32_t ko = kk * 32;
            uint32_t fb[2][4];
#pragma unroll
            for (int p = 0; p < 2; p++)
                ldm_x4(fb[p], bB + p * 16 * GSTRIDE * 2 + ko);
#pragma unroll
            for (int i = 0; i < 4; i++) {
                uint32_t fah[4], fal[4];
                ldm_x4(fah, aH + i * 16 * GSTRIDE * 2 + ko);
                ldm_x4(fal, aL + i * 16 * GSTRIDE * 2 + ko);
#pragma unroll
                for (int j = 0; j < 4; j++) {
                    const int p = j >> 1, h = (j & 1) * 2;
                    uint32_t bf[2] = {fb[p][h], fb[p][h + 1]};
                    mma16816(acc[i][j], fah, bf);
                    mma16816(acc[i][j], fal, bf);
                }
            }
        }
        __syncthreads();
        if (t + 2 < T) {
            gemm_load_stage(Ah, Al, Bt, sb + ((t + 2) % 3) * GSTAGE_B,
                            m0, n0, (t + 2) * 32, tid);
            CP_COMMIT();
        }
    }

    const int g = lane >> 2, tq = lane & 3;
#pragma unroll
    for (int i = 0; i < 4; i++) {
        const int r0 = m0 + mw + i * 16 + g;
#pragma unroll
        for (int j = 0; j < 4; j++) {
            const int col = n0 + nw + j * 8 + tq * 2;
            *(float2*)(C + (size_t)r0 * N + col)       = make_float2(acc[i][j][0], acc[i][j][1]);
            *(float2*)(C + (size_t)(r0 + 8) * N + col) = make_float2(acc[i][j][2], acc[i][j][3]);
        }
    }
}

// ---------------------------------------------------------------------------
// fp16 mma.sync GEMM, 1-term A (output projection).
// Same tiling; stage = A|B (2 tiles), 3-stage pipeline.
// ---------------------------------------------------------------------------
constexpr int G1STAGE_B = 2 * GTILE_B;       // 20480
constexpr int GEMM1_SMEM = 3 * G1STAGE_B;    // 61440

__device__ __forceinline__ void gemm1_load_stage(
    const __half* __restrict__ A, const __half* __restrict__ Bt,
    uint32_t stageBase, int m0, int n0, int k0, int tid) {
#pragma unroll
    for (int i = 0; i < 4; i++) {
        const int idx = tid + i * 256;      // 0..1023
        const int tile = idx >> 9;          // 0..1
        const int c = idx & 511;
        const int row = c >> 2;
        const int kc = (c & 3) * 8;
        const __half* src = (tile == 0)
            ? A  + (size_t)(m0 + row) * KDIM + k0 + kc
            : Bt + (size_t)(n0 + row) * KDIM + k0 + kc;
        const uint32_t dst = stageBase + tile * GTILE_B + (row * GSTRIDE + kc) * 2;
        CP_ASYNC16(dst, src);
    }
}

__global__ __launch_bounds__(256, 2)
void mma_gemm1(const __half* __restrict__ A, const __half* __restrict__ Bt,
               float* __restrict__ C, int N) {
    extern __shared__ __align__(16) uint8_t smg[];
    const uint32_t sb = smem_u32(smg);
    const int tid = threadIdx.x;
    const int wid = tid >> 5, lane = tid & 31;
    const int m0 = blockIdx.y * 128, n0 = blockIdx.x * 128;
    const int mw = (wid & 1) * 64;
    const int nw = (wid >> 1) * 32;

    float acc[4][4][4];
#pragma unroll
    for (int i = 0; i < 4; i++)
#pragma unroll
        for (int j = 0; j < 4; j++)
#pragma unroll
            for (int q = 0; q < 4; q++) acc[i][j][q] = 0.f;

    const uint32_t laneA = ((lane & 15) * GSTRIDE + (lane >> 4) * 8) * 2;
    const uint32_t laneB = ((((lane >> 4) << 3) + (lane & 7)) * GSTRIDE
                           + ((lane >> 3) & 1) * 8) * 2;

    const int T = KDIM / 32;
    gemm1_load_stage(A, Bt, sb, m0, n0, 0, tid);              CP_COMMIT();
    gemm1_load_stage(A, Bt, sb + G1STAGE_B, m0, n0, 32, tid); CP_COMMIT();

    for (int t = 0; t < T; t++) {
        const uint32_t stg = sb + (t % 3) * G1STAGE_B;
        if (t + 1 < T) { CP_WAIT(1); } else { CP_WAIT(0); }
        __syncthreads();

        const uint32_t aA = stg + 0 * GTILE_B + mw * GSTRIDE * 2 + laneA;
        const uint32_t bB = stg + 1 * GTILE_B + nw * GSTRIDE * 2 + laneB;

#pragma unroll
        for (int kk = 0; kk < 2; kk++) {
            const uint32_t ko = kk * 32;
            uint32_t fb[2][4];
#pragma unroll
            for (int p = 0; p < 2; p++)
                ldm_x4(fb[p], bB + p * 16 * GSTRIDE * 2 + ko);
#pragma unroll
            for (int i = 0; i < 4; i++) {
                uint32_t fa[4];
                ldm_x4(fa, aA + i * 16 * GSTRIDE * 2 + ko);
#pragma unroll
                for (int j = 0; j < 4; j++) {
                    const int p = j >> 1, h = (j & 1) * 2;
                    uint32_t bf[2] = {fb[p][h], fb[p][h + 1]};
                    mma16816(acc[i][j], fa, bf);
                }
            }
        }
        __syncthreads();
        if (t + 2 < T) {
            gemm1_load_stage(A, Bt, sb + ((t + 2) % 3) * G1STAGE_B,
                             m0, n0, (t + 2) * 32, tid);
            CP_COMMIT();
        }
    }

    const int g = lane >> 2, tq = lane & 3;
#pragma unroll
    for (int i = 0; i < 4; i++) {
        const int r0 = m0 + mw + i * 16 + g;
#pragma unroll
        for (int j = 0; j < 4; j++) {
            const int col = n0 + nw + j * 8 + tq * 2;
            *(float2*)(C + (size_t)r0 * N + col)       = make_float2(acc[i][j][0], acc[i][j][1]);
            *(float2*)(C + (size_t)(r0 + 8) * N + col) = make_float2(acc[i][j][2], acc[i][j][3]);
        }
    }
}

// ---------------------------------------------------------------------------
// RoPE + split + head-major relayout from fused QKV [4096][3072]
// ---------------------------------------------------------------------------
__global__ void rope_split_kernel(const float* __restrict__ QKV,
                                  const int* __restrict__ pos,
                                  __half* __restrict__ Qh, __half* __restrict__ Ql,
                                  __half* __restrict__ Kh) {
    const int total = BATCH * SEQ * (NHEADS + NKVH) * 64;
    int idx = blockIdx.x * blockDim.x + threadIdx.x;
    if (idx >= total) return;
    const int p = idx & 63;
    int rest = idx >> 6;
    const int hh = rest % (NHEADS + NKVH);
    const int bs = rest / (NHEADS + NKVH);
    const int b = bs >> 11, s = bs & 2047;

    const float fpos = (float)pos[bs];
    const float inv = powf(10000.f, -(float)p * (1.f / 64.f));
    const float ang = fpos * inv;
    float sn, c;
    sincosf(ang, &sn, &c);

    if (hh < NHEADS) {
        const float* src = QKV + (size_t)bs * N_QKV + hh * HDIM;
        const float x1 = src[p], x2 = src[p + 64];
        const float y1 = (x1 * c - x2 * sn) * QK_SCALE;
        const float y2 = (x2 * c + x1 * sn) * QK_SCALE;
        const size_t obase = ((size_t)(b * NHEADS + hh) * SEQ + s) * HDIM;
        __half h1 = __float2half_rn(y1);
        __half h2 = __float2half_rn(y2);
        Qh[obase + p]      = h1;
        Qh[obase + p + 64] = h2;
        Ql[obase + p]      = __float2half_rn(y1 - __half2float(h1));
        Ql[obase + p + 64] = __float2half_rn(y2 - __half2float(h2));
    } else {
        const int kv = hh - NHEADS;
        const float* src = QKV + (size_t)bs * N_QKV + HIDDEN + kv * HDIM;
        const float x1 = src[p], x2 = src[p + 64];
        const size_t obase = ((size_t)(b * NKVH + kv) * SEQ + s) * HDIM;
        Kh[obase + p]      = __float2half_rn(x1 * c - x2 * sn);
        Kh[obase + p + 64] = __float2half_rn(x2 * c + x1 * sn);
    }
}

// V -> Vth fp16 [B,kvh,D,S]
__global__ void vt_split_kernel(const float* __restrict__ QKV,
                                __half* __restrict__ TH) {
    __shared__ float s[32][33];
    const int s0 = blockIdx.x * 32, d0 = blockIdx.y * 32;
    const int b = blockIdx.z >> 2, kv = blockIdx.z & 3;
    const int tx = threadIdx.x, ty = threadIdx.y;
#pragma unroll
    for (int i = 0; i < 4; i++) {
        const int ss = s0 + ty + 8 * i;
        s[ty + 8 * i][tx] =
            QKV[(size_t)(b * SEQ + ss) * N_QKV + HIDDEN + NKVH * HDIM + kv * HDIM + d0 + tx];
    }
    __syncthreads();
#pragma unroll
    for (int i = 0; i < 4; i++) {
        const int d = ty + 8 * i;
        const size_t o = ((size_t)(b * NKVH + kv) * HDIM + d0 + d) * SEQ + s0 + tx;
        TH[o] = __float2half_rn(s[tx][d]);
    }
}

// ---------------------------------------------------------------------------
// Tensor-core flash attention (causal, GQA; Q 2-term, K/V/P 1-term fp16).
// Epilogue writes single-fp16 ctx (Ch only).
// ---------------------------------------------------------------------------
constexpr int ASTR = 136;
constexpr int VSTR = 72;
constexpr int AQ_H = 0;
constexpr int AQ_L = 128 * ASTR * 2;
constexpr int AKV0 = 2 * 128 * ASTR * 2;
constexpr int AK_H = 0;
constexpr int AV_H = 64 * ASTR * 2;
constexpr int KVBUF = AV_H + 128 * VSTR * 2;         // 35840
constexpr int ATTN_SMEM = AKV0 + 2 * KVBUF;          // 141312

__device__ __forceinline__ void attn_load_kv(
    const __half* __restrict__ Kh, const __half* __restrict__ Vth,
    uint32_t bufBase, size_t kbase, size_t vtbase, int k0, int tid) {
#pragma unroll
    for (int i = 0; i < 8; i++) {
        const int idx = tid + i * 256;
        if (idx < 1024) {
            const int row = idx >> 4, c = idx & 15;
            const __half* src = Kh + kbase + (size_t)(k0 + row) * HDIM + c * 8;
            const uint32_t dst = bufBase + AK_H + (row * ASTR + c * 8) * 2;
            CP_ASYNC16(dst, src);
        } else {
            const int v = idx - 1024;
            const int row = v >> 3, c = v & 7;
            const __half* src = Vth + vtbase + (size_t)row * SEQ + k0 + c * 8;
            const uint32_t dst = bufBase + AV_H + (row * VSTR + c * 8) * 2;
            CP_ASYNC16(dst, src);
        }
    }
}

__global__ __launch_bounds__(256, 1)
void attn_mma_kernel(const __half* __restrict__ Qh, const __half* __restrict__ Ql,
                     const __half* __restrict__ Kh, const __half* __restrict__ Vth,
                     __half* __restrict__ Ch) {
    extern __shared__ __align__(16) uint8_t smb[];
    const uint32_t sb = smem_u32(smb);
    const int tid = threadIdx.x;
    const int wid = tid >> 5, lane = tid & 31;
    const int g = lane >> 2, tq = lane & 3;

    const int qt = gridDim.x - 1 - blockIdx.x;
    const int h = blockIdx.y, b = blockIdx.z;
    const int kvh = h >> 2;
    const int q0 = qt * 128;
    const int nkt = 2 * qt + 2;

    const size_t qbase  = ((size_t)(b * NHEADS + h) * SEQ + q0) * HDIM;
    const size_t kbase  = ((size_t)(b * NKVH + kvh) * SEQ) * HDIM;
    const size_t vtbase = ((size_t)(b * NKVH + kvh) * HDIM) * SEQ;

#pragma unroll
    for (int i = 0; i < 16; i++) {
        const int idx = tid + i * 256;
        const int half_ = idx >> 11;
        const int j = idx & 2047;
        const int row = j >> 4, c = j & 15;
        const __half* src = (half_ ? Ql : Qh) + qbase + (size_t)row * HDIM + c * 8;
        const uint32_t dst = sb + (half_ ? AQ_L : AQ_H) + (row * ASTR + c * 8) * 2;
        CP_ASYNC16(dst, src);
    }
    CP_COMMIT();
    attn_load_kv(Kh, Vth, sb + AKV0,         kbase, vtbase, 0,  tid); CP_COMMIT();
    attn_load_kv(Kh, Vth, sb + AKV0 + KVBUF, kbase, vtbase, 64, tid); CP_COMMIT();

    CP_WAIT(2);
    __syncthreads();
    uint32_t qfh[8][4], qfl[8][4];
    {
        const uint32_t la = ((wid * 16 + (lane & 15)) * ASTR + (lane >> 4) * 8) * 2;
#pragma unroll
        for (int kk = 0; kk < 8; kk++) {
            ldm_x4(qfh[kk], sb + AQ_H + la + kk * 32);
            ldm_x4(qfl[kk], sb + AQ_L + la + kk * 32);
        }
    }

    float o[16][4];
#pragma unroll
    for (int jj = 0; jj < 16; jj++)
#pragma unroll
        for (int q = 0; q < 4; q++) o[jj][q] = 0.f;
    float m0 = -1e30f, m1 = -1e30f, sl0 = 0.f, sl1 = 0.f;

    const int r0 = q0 + wid * 16 + g;
    const uint32_t laneNK = ((lane >> 4) * 8 + (lane & 7));
    const uint32_t laneKhi = ((lane >> 3) & 1) * 8;

    for (int kt = 0; kt < nkt; kt++) {
        const int k0 = kt * 64;
        const uint32_t buf = sb + AKV0 + (kt & 1) * KVBUF;
        if (kt + 1 < nkt) { CP_WAIT(1); } else { CP_WAIT(0); }
        __syncthreads();

        // ---- S = Q K^T ----
        float sacc[8][4];
#pragma unroll
        for (int j = 0; j < 8; j++)
#pragma unroll
            for (int q = 0; q < 4; q++) sacc[j][q] = 0.f;

#pragma unroll
        for (int kk = 0; kk < 8; kk++) {
#pragma unroll
            for (int p = 0; p < 4; p++) {
                const uint32_t off = ((p * 16 + laneNK) * ASTR + laneKhi) * 2 + kk * 32;
                uint32_t fk[4];
                ldm_x4(fk, buf + AK_H + off);
                uint32_t b0[2] = {fk[0], fk[1]}, b1[2] = {fk[2], fk[3]};
                mma16816(sacc[2 * p],     qfh[kk], b0);
                mma16816(sacc[2 * p + 1], qfh[kk], b1);
                mma16816(sacc[2 * p],     qfl[kk], b0);
                mma16816(sacc[2 * p + 1], qfl[kk], b1);
            }
        }

        // ---- causal mask ----
        if (kt >= nkt - 2) {
#pragma unroll
            for (int j = 0; j < 8; j++) {
#pragma unroll
                for (int e = 0; e < 2; e++) {
                    const int col = k0 + j * 8 + tq * 2 + e;
                    if (col > r0)     sacc[j][e]     = -1e30f;
                    if (col > r0 + 8) sacc[j][2 + e] = -1e30f;
                }
            }
        }

        // ---- online softmax ----
        float mt0 = -1e30f, mt1 = -1e30f;
#pragma unroll
        for (int j = 0; j < 8; j++) {
            mt0 = fmaxf(mt0, fmaxf(sacc[j][0], sacc[j][1]));
            mt1 = fmaxf(mt1, fmaxf(sacc[j][2], sacc[j][3]));
        }
        mt0 = fmaxf(mt0, __shfl_xor_sync(0xffffffffu, mt0, 1));
        mt0 = fmaxf(mt0, __shfl_xor_sync(0xffffffffu, mt0, 2));
        mt1 = fmaxf(mt1, __shfl_xor_sync(0xffffffffu, mt1, 1));
        mt1 = fmaxf(mt1, __shfl_xor_sync(0xffffffffu, mt1, 2));
        const float mn0 = fmaxf(m0, mt0), mn1 = fmaxf(m1, mt1);
        const float al0 = __expf(m0 - mn0), al1 = __expf(m1 - mn1);
        float s0 = 0.f, s1 = 0.f;
#pragma unroll
        for (int j = 0; j < 8; j++) {
            sacc[j][0] = __expf(sacc[j][0] - mn0);
            sacc[j][1] = __expf(sacc[j][1] - mn0);
            sacc[j][2] = __expf(sacc[j][2] - mn1);
            sacc[j][3] = __expf(sacc[j][3] - mn1);
            s0 += sacc[j][0] + sacc[j][1];
            s1 += sacc[j][2] + sacc[j][3];
        }
        s0 += __shfl_xor_sync(0xffffffffu, s0, 1);
        s0 += __shfl_xor_sync(0xffffffffu, s0, 2);
        s1 += __shfl_xor_sync(0xffffffffu, s1, 1);
        s1 += __shfl_xor_sync(0xffffffffu, s1, 2);
        sl0 = sl0 * al0 + s0;  sl1 = sl1 * al1 + s1;
        m0 = mn0;              m1 = mn1;
#pragma unroll
        for (int jj = 0; jj < 16; jj++) {
            o[jj][0] *= al0; o[jj][1] *= al0;
            o[jj][2] *= al1; o[jj][3] *= al1;
        }

        // ---- P fragments ----
        uint32_t ph[4][4];
#pragma unroll
        for (int kk2 = 0; kk2 < 4; kk2++) {
            const int j0 = 2 * kk2, j1 = j0 + 1;
            ph[kk2][0] = packh(sacc[j0][0], sacc[j0][1]);
            ph[kk2][1] = packh(sacc[j0][2], sacc[j0][3]);
            ph[kk2][2] = packh(sacc[j1][0], sacc[j1][1]);
            ph[kk2][3] = packh(sacc[j1][2], sacc[j1][3]);
        }

        // ---- O += P V ----
#pragma unroll
        for (int kk2 = 0; kk2 < 4; kk2++) {
#pragma unroll
            for (int p = 0; p < 8; p++) {
                const uint32_t off = ((p * 16 + laneNK) * VSTR + laneKhi + kk2 * 16) * 2;
                uint32_t fv[4];
                ldm_x4(fv, buf + AV_H + off);
                uint32_t b0[2] = {fv[0], fv[1]}, b1[2] = {fv[2], fv[3]};
                mma16816(o[2 * p],     ph[kk2], b0);
                mma16816(o[2 * p + 1], ph[kk2], b1);
            }
        }

        __syncthreads();
        if (kt + 2 < nkt) {
            attn_load_kv(Kh, Vth, sb + AKV0 + (kt & 1) * KVBUF,
                         kbase, vtbase, (kt + 2) * 64, tid);
            CP_COMMIT();
        }
    }

    // ---- epilogue: single fp16 ctx ----
    const float inv0 = 1.f / sl0, inv1 = 1.f / sl1;
#pragma unroll
    for (int jj = 0; jj < 16; jj++) {
        const int d = jj * 8 + tq * 2;
        const size_t o0 = (size_t)(b * SEQ + r0) * HIDDEN + h * HDIM + d;
        const size_t o1 = o0 + (size_t)8 * HIDDEN;
        *(uint32_t*)(Ch + o0) = packh(o[jj][0] * inv0, o[jj][1] * inv0);
        *(uint32_t*)(Ch + o1) = packh(o[jj][2] * inv1, o[jj][3] * inv1);
    }
}

// ---------------------------------------------------------------------------
// Launch
// ---------------------------------------------------------------------------
extern "C" void kernel_launch(void* const* d_in, const int* in_sizes, int n_in,
                              void* d_out, int out_size) {
    const float* X   = (const float*)d_in[0];
    const int*   pos = (const int*)  d_in[1];
    const float* Wq  = (const float*)d_in[2];
    const float* Wk  = (const float*)d_in[3];
    const float* Wv  = (const float*)d_in[4];
    const float* Wo  = (const float*)d_in[5];
    float* out = (float*)d_out;

    float* QKV;
    __half *Xh, *Xl, *Ch, *W3, *WoT;
    __half *Qbh, *Qbl, *Kbh, *Vth;
    cudaGetSymbolAddress((void**)&QKV, g_QKV);
    cudaGetSymbolAddress((void**)&Xh, g_Xh);
    cudaGetSymbolAddress((void**)&Xl, g_Xl);
    cudaGetSymbolAddress((void**)&Ch, g_Ch);
    cudaGetSymbolAddress((void**)&W3, g_W3T);
    cudaGetSymbolAddress((void**)&WoT, g_WoT);
    cudaGetSymbolAddress((void**)&Qbh, g_Qbh);
    cudaGetSymbolAddress((void**)&Qbl, g_Qbl);
    cudaGetSymbolAddress((void**)&Kbh, g_Kbh);
    cudaGetSymbolAddress((void**)&Vth, g_Vth);

    const int total8 = MROWS * KDIM / 8;
    split_a2_kernel<<<(total8 + 255) / 256, 256>>>(X, Xh, Xl, total8);
    split_w_all_kernel<<<dim3(64, 64, 4), dim3(32, 8)>>>(Wq, Wk, Wv, Wo, W3, WoT);

    cudaFuncSetAttribute(mma_gemm, cudaFuncAttributeMaxDynamicSharedMemorySize, GEMM_SMEM);
    cudaFuncSetAttribute(mma_gemm1, cudaFuncAttributeMaxDynamicSharedMemorySize, GEMM1_SMEM);

    // Fused QKV projection (2-term A)
    mma_gemm<<<dim3(N_QKV / 128, 32), 256, GEMM_SMEM>>>(Xh, Xl, W3, QKV, N_QKV);

    // RoPE + V transpose
    const int rope_total = BATCH * SEQ * (NHEADS + NKVH) * 64;
    rope_split_kernel<<<(rope_total + 255) / 256, 256>>>(QKV, pos, Qbh, Qbl, Kbh);
    vt_split_kernel<<<dim3(64, 4, 8), dim3(32, 8)>>>(QKV, Vth);

    // Flash attention (emits single-fp16 ctx)
    cudaFuncSetAttribute(attn_mma_kernel, cudaFuncAttributeMaxDynamicSharedMemorySize, ATTN_SMEM);
    attn_mma_kernel<<<dim3(SEQ / 128, NHEADS, BATCH), 256, ATTN_SMEM>>>(
        Qbh, Qbl, Kbh, Vth, Ch);

    // Output projection (1-term A)
    mma_gemm1<<<dim3(16, 32), 256, GEMM1_SMEM>>>(Ch, WoT, out, 2048);
}

// round 11
// speedup vs baseline: 7.9709x; 1.2635x over previous
#include <cuda_runtime.h>
#include <cuda_fp16.h>
#include <cstdint>
#include <math.h>

// Problem constants
constexpr int BATCH  = 2;
constexpr int SEQ    = 2048;
constexpr int HIDDEN = 2048;
constexpr int NHEADS = 16;
constexpr int NKVH   = 4;
constexpr int HDIM   = 128;
constexpr float QK_SCALE = 0.08838834764831845f; // 1/sqrt(128)

constexpr int MROWS = BATCH * SEQ;   // 4096
constexpr int KDIM  = HIDDEN;        // 2048
constexpr int N_QKV = HIDDEN + 2 * NKVH * HDIM;  // 3072

// ---------------------------------------------------------------------------
// Device-global scratch
// ---------------------------------------------------------------------------
__device__ float g_QKV[(size_t)MROWS * N_QKV];    // fused Q|K|V fp32

__device__ __align__(16) __half g_Xh[(size_t)MROWS * KDIM];   // X fp16 (single term)
__device__ __align__(16) __half g_Ch[(size_t)MROWS * KDIM];   // ctx fp16 (single term)
__device__ __align__(16) __half g_W3T[(size_t)N_QKV * KDIM];  // Wq|Wk|Wv ^T
__device__ __align__(16) __half g_WoT[(size_t)HIDDEN * KDIM]; // Wo^T

// Attention operands
__device__ __align__(16) __half g_Qbh[(size_t)BATCH * NHEADS * SEQ * HDIM];
__device__ __align__(16) __half g_Qbl[(size_t)BATCH * NHEADS * SEQ * HDIM];
__device__ __align__(16) __half g_Kbh[(size_t)BATCH * NKVH * SEQ * HDIM];
__device__ __align__(16) __half g_Vth[(size_t)BATCH * NKVH * HDIM * SEQ];

// ---------------------------------------------------------------------------
// PTX helpers
// ---------------------------------------------------------------------------
__device__ __forceinline__ uint32_t smem_u32(const void* p) {
    uint32_t a;
    asm("{ .reg .u64 t; cvta.to.shared.u64 t, %1; cvt.u32.u64 %0, t; }"
        : "=r"(a) : "l"(p));
    return a;
}

#define CP_ASYNC16(dst, src) \
    asm volatile("cp.async.cg.shared.global [%0], [%1], 16;" :: "r"(dst), "l"(src))
#define CP_COMMIT() asm volatile("cp.async.commit_group;" ::: "memory")
#define CP_WAIT(n)  asm volatile("cp.async.wait_group %0;" :: "n"(n) : "memory")

__device__ __forceinline__ void ldm_x4(uint32_t* r, uint32_t addr) {
    asm volatile("ldmatrix.sync.aligned.m8n8.x4.shared.b16 {%0,%1,%2,%3}, [%4];"
                 : "=r"(r[0]), "=r"(r[1]), "=r"(r[2]), "=r"(r[3]) : "r"(addr));
}
__device__ __forceinline__ void mma16816(float* d, const uint32_t* a, const uint32_t* b) {
    asm volatile("mma.sync.aligned.m16n8k16.row.col.f32.f16.f16.f32 "
                 "{%0,%1,%2,%3}, {%4,%5,%6,%7}, {%8,%9}, {%0,%1,%2,%3};"
                 : "+f"(d[0]), "+f"(d[1]), "+f"(d[2]), "+f"(d[3])
                 : "r"(a[0]), "r"(a[1]), "r"(a[2]), "r"(a[3]), "r"(b[0]), "r"(b[1]));
}
__device__ __forceinline__ uint32_t packh(float lo, float hi) {
    __half2 t = __floats2half2_rn(lo, hi);
    return *(uint32_t*)&t;
}

// ---------------------------------------------------------------------------
// Conversions
// ---------------------------------------------------------------------------
// fp32 -> fp16 (single term)
__global__ void conv_a_kernel(const float* __restrict__ X,
                              __half* __restrict__ H, int total8) {
    int t = blockIdx.x * blockDim.x + threadIdx.x;
    if (t >= total8) return;
    const int base = t * 8;
    float4 x0 = *(const float4*)(X + base);
    float4 x1 = *(const float4*)(X + base + 4);
    float xs[8] = {x0.x, x0.y, x0.z, x0.w, x1.x, x1.y, x1.z, x1.w};
    __half hs[8];
#pragma unroll
    for (int i = 0; i < 8; i++) hs[i] = __float2half_rn(xs[i]);
    *(uint4*)(H + base) = *(const uint4*)hs;
}

// All 4 weights: W [K][N] fp32 -> WT [N][K] fp16, one launch.
__global__ void split_w_all_kernel(const float* __restrict__ Wq, const float* __restrict__ Wk,
                                   const float* __restrict__ Wv, const float* __restrict__ Wo,
                                   __half* __restrict__ W3T, __half* __restrict__ WoT) {
    __shared__ float s[32][33];
    const int z = blockIdx.z;
    const float* W;
    __half* dst;
    int N, rowoff;
    if      (z == 0) { W = Wq; dst = W3T; N = 2048; rowoff = 0;    }
    else if (z == 1) { W = Wk; dst = W3T; N = 512;  rowoff = 2048; }
    else if (z == 2) { W = Wv; dst = W3T; N = 512;  rowoff = 2560; }
    else             { W = Wo; dst = WoT; N = 2048; rowoff = 0;    }
    const int n0 = blockIdx.y * 32;
    if (n0 >= N) return;
    const int k0 = blockIdx.x * 32;
    const int tx = threadIdx.x, ty = threadIdx.y;  // 32 x 8
#pragma unroll
    for (int i = 0; i < 4; i++)
        s[ty + 8 * i][tx] = W[(size_t)(k0 + ty + 8 * i) * N + n0 + tx];
    __syncthreads();
#pragma unroll
    for (int i = 0; i < 4; i++) {
        const int n = ty + 8 * i;
        dst[(size_t)(rowoff + n0 + n) * KDIM + k0 + tx] = __float2half_rn(s[tx][n]);
    }
}

// ---------------------------------------------------------------------------
// fp16 mma.sync GEMM, 1-term: C[M][N] = A @ Bt^T.
// CTA 128x128, BK=32, 3-stage cp.async, 8 warps (64x32 warp tile).
// ---------------------------------------------------------------------------
constexpr int GSTRIDE = 40;
constexpr int GTILE_B = 128 * GSTRIDE * 2;   // 10240 bytes
constexpr int G1STAGE_B = 2 * GTILE_B;       // 20480
constexpr int GEMM1_SMEM = 3 * G1STAGE_B;    // 61440

__device__ __forceinline__ void gemm1_load_stage(
    const __half* __restrict__ A, const __half* __restrict__ Bt,
    uint32_t stageBase, int m0, int n0, int k0, int tid) {
#pragma unroll
    for (int i = 0; i < 4; i++) {
        const int idx = tid + i * 256;      // 0..1023
        const int tile = idx >> 9;          // 0..1
        const int c = idx & 511;
        const int row = c >> 2;
        const int kc = (c & 3) * 8;
        const __half* src = (tile == 0)
            ? A  + (size_t)(m0 + row) * KDIM + k0 + kc
            : Bt + (size_t)(n0 + row) * KDIM + k0 + kc;
        const uint32_t dst = stageBase + tile * GTILE_B + (row * GSTRIDE + kc) * 2;
        CP_ASYNC16(dst, src);
    }
}

__global__ __launch_bounds__(256, 2)
void mma_gemm1(const __half* __restrict__ A, const __half* __restrict__ Bt,
               float* __restrict__ C, int N) {
    extern __shared__ __align__(16) uint8_t smg[];
    const uint32_t sb = smem_u32(smg);
    const int tid = threadIdx.x;
    const int wid = tid >> 5, lane = tid & 31;
    const int m0 = blockIdx.y * 128, n0 = blockIdx.x * 128;
    const int mw = (wid & 1) * 64;
    const int nw = (wid >> 1) * 32;

    float acc[4][4][4];
#pragma unroll
    for (int i = 0; i < 4; i++)
#pragma unroll
        for (int j = 0; j < 4; j++)
#pragma unroll
            for (int q = 0; q < 4; q++) acc[i][j][q] = 0.f;

    const uint32_t laneA = ((lane & 15) * GSTRIDE + (lane >> 4) * 8) * 2;
    const uint32_t laneB = ((((lane >> 4) << 3) + (lane & 7)) * GSTRIDE
                           + ((lane >> 3) & 1) * 8) * 2;

    const int T = KDIM / 32;
    gemm1_load_stage(A, Bt, sb, m0, n0, 0, tid);              CP_COMMIT();
    gemm1_load_stage(A, Bt, sb + G1STAGE_B, m0, n0, 32, tid); CP_COMMIT();

    for (int t = 0; t < T; t++) {
        const uint32_t stg = sb + (t % 3) * G1STAGE_B;
        if (t + 1 < T) { CP_WAIT(1); } else { CP_WAIT(0); }
        __syncthreads();

        const uint32_t aA = stg + 0 * GTILE_B + mw * GSTRIDE * 2 + laneA;
        const uint32_t bB = stg + 1 * GTILE_B + nw * GSTRIDE * 2 + laneB;

#pragma unroll
        for (int kk = 0; kk < 2; kk++) {
            const uint32_t ko = kk * 32;
            uint32_t fb[2][4];
#pragma unroll
            for (int p = 0; p < 2; p++)
                ldm_x4(fb[p], bB + p * 16 * GSTRIDE * 2 + ko);
#pragma unroll
            for (int i = 0; i < 4; i++) {
                uint32_t fa[4];
                ldm_x4(fa, aA + i * 16 * GSTRIDE * 2 + ko);
#pragma unroll
                for (int j = 0; j < 4; j++) {
                    const int p = j >> 1, h = (j & 1) * 2;
                    uint32_t bf[2] = {fb[p][h], fb[p][h + 1]};
                    mma16816(acc[i][j], fa, bf);
                }
            }
        }
        __syncthreads();
        if (t + 2 < T) {
            gemm1_load_stage(A, Bt, sb + ((t + 2) % 3) * G1STAGE_B,
                             m0, n0, (t + 2) * 32, tid);
            CP_COMMIT();
        }
    }

    const int g = lane >> 2, tq = lane & 3;
#pragma unroll
    for (int i = 0; i < 4; i++) {
        const int r0 = m0 + mw + i * 16 + g;
#pragma unroll
        for (int j = 0; j < 4; j++) {
            const int col = n0 + nw + j * 8 + tq * 2;
            *(float2*)(C + (size_t)r0 * N + col)       = make_float2(acc[i][j][0], acc[i][j][1]);
            *(float2*)(C + (size_t)(r0 + 8) * N + col) = make_float2(acc[i][j][2], acc[i][j][3]);
        }
    }
}

// ---------------------------------------------------------------------------
// RoPE + split + head-major relayout from fused QKV [4096][3072]
// ---------------------------------------------------------------------------
__global__ void rope_split_kernel(const float* __restrict__ QKV,
                                  const int* __restrict__ pos,
                                  __half* __restrict__ Qh, __half* __restrict__ Ql,
                                  __half* __restrict__ Kh) {
    const int total = BATCH * SEQ * (NHEADS + NKVH) * 64;
    int idx = blockIdx.x * blockDim.x + threadIdx.x;
    if (idx >= total) return;
    const int p = idx & 63;
    int rest = idx >> 6;
    const int hh = rest % (NHEADS + NKVH);
    const int bs = rest / (NHEADS + NKVH);
    const int b = bs >> 11, s = bs & 2047;

    const float fpos = (float)pos[bs];
    const float inv = powf(10000.f, -(float)p * (1.f / 64.f));
    const float ang = fpos * inv;
    float sn, c;
    sincosf(ang, &sn, &c);

    if (hh < NHEADS) {
        const float* src = QKV + (size_t)bs * N_QKV + hh * HDIM;
        const float x1 = src[p], x2 = src[p + 64];
        const float y1 = (x1 * c - x2 * sn) * QK_SCALE;
        const float y2 = (x2 * c + x1 * sn) * QK_SCALE;
        const size_t obase = ((size_t)(b * NHEADS + hh) * SEQ + s) * HDIM;
        __half h1 = __float2half_rn(y1);
        __half h2 = __float2half_rn(y2);
        Qh[obase + p]      = h1;
        Qh[obase + p + 64] = h2;
        Ql[obase + p]      = __float2half_rn(y1 - __half2float(h1));
        Ql[obase + p + 64] = __float2half_rn(y2 - __half2float(h2));
    } else {
        const int kv = hh - NHEADS;
        const float* src = QKV + (size_t)bs * N_QKV + HIDDEN + kv * HDIM;
        const float x1 = src[p], x2 = src[p + 64];
        const size_t obase = ((size_t)(b * NKVH + kv) * SEQ + s) * HDIM;
        Kh[obase + p]      = __float2half_rn(x1 * c - x2 * sn);
        Kh[obase + p + 64] = __float2half_rn(x2 * c + x1 * sn);
    }
}

// V -> Vth fp16 [B,kvh,D,S]
__global__ void vt_split_kernel(const float* __restrict__ QKV,
                                __half* __restrict__ TH) {
    __shared__ float s[32][33];
    const int s0 = blockIdx.x * 32, d0 = blockIdx.y * 32;
    const int b = blockIdx.z >> 2, kv = blockIdx.z & 3;
    const int tx = threadIdx.x, ty = threadIdx.y;
#pragma unroll
    for (int i = 0; i < 4; i++) {
        const int ss = s0 + ty + 8 * i;
        s[ty + 8 * i][tx] =
            QKV[(size_t)(b * SEQ + ss) * N_QKV + HIDDEN + NKVH * HDIM + kv * HDIM + d0 + tx];
    }
    __syncthreads();
#pragma unroll
    for (int i = 0; i < 4; i++) {
        const int d = ty + 8 * i;
        const size_t o = ((size_t)(b * NKVH + kv) * HDIM + d0 + d) * SEQ + s0 + tx;
        TH[o] = __float2half_rn(s[tx][d]);
    }
}

// ---------------------------------------------------------------------------
// Tensor-core flash attention (causal, GQA; Q 2-term, K/V/P 1-term fp16).
// ---------------------------------------------------------------------------
constexpr int ASTR = 136;
constexpr int VSTR = 72;
constexpr int AQ_H = 0;
constexpr int AQ_L = 128 * ASTR * 2;
constexpr int AKV0 = 2 * 128 * ASTR * 2;
constexpr int AK_H = 0;
constexpr int AV_H = 64 * ASTR * 2;
constexpr int KVBUF = AV_H + 128 * VSTR * 2;         // 35840
constexpr int ATTN_SMEM = AKV0 + 2 * KVBUF;          // 141312

__device__ __forceinline__ void attn_load_kv(
    const __half* __restrict__ Kh, const __half* __restrict__ Vth,
    uint32_t bufBase, size_t kbase, size_t vtbase, int k0, int tid) {
#pragma unroll
    for (int i = 0; i < 8; i++) {
        const int idx = tid + i * 256;
        if (idx < 1024) {
            const int row = idx >> 4, c = idx & 15;
            const __half* src = Kh + kbase + (size_t)(k0 + row) * HDIM + c * 8;
            const uint32_t dst = bufBase + AK_H + (row * ASTR + c * 8) * 2;
            CP_ASYNC16(dst, src);
        } else {
            const int v = idx - 1024;
            const int row = v >> 3, c = v & 7;
            const __half* src = Vth + vtbase + (size_t)row * SEQ + k0 + c * 8;
            const uint32_t dst = bufBase + AV_H + (row * VSTR + c * 8) * 2;
            CP_ASYNC16(dst, src);
        }
    }
}

__global__ __launch_bounds__(256, 1)
void attn_mma_kernel(const __half* __restrict__ Qh, const __half* __restrict__ Ql,
                     const __half* __restrict__ Kh, const __half* __restrict__ Vth,
                     __half* __restrict__ Ch) {
    extern __shared__ __align__(16) uint8_t smb[];
    const uint32_t sb = smem_u32(smb);
    const int tid = threadIdx.x;
    const int wid = tid >> 5, lane = tid & 31;
    const int g = lane >> 2, tq = lane & 3;

    const int qt = gridDim.x - 1 - blockIdx.x;
    const int h = blockIdx.y, b = blockIdx.z;
    const int kvh = h >> 2;
    const int q0 = qt * 128;
    const int nkt = 2 * qt + 2;

    const size_t qbase  = ((size_t)(b * NHEADS + h) * SEQ + q0) * HDIM;
    const size_t kbase  = ((size_t)(b * NKVH + kvh) * SEQ) * HDIM;
    const size_t vtbase = ((size_t)(b * NKVH + kvh) * HDIM) * SEQ;

#pragma unroll
    for (int i = 0; i < 16; i++) {
        const int idx = tid + i * 256;
        const int half_ = idx >> 11;
        const int j = idx & 2047;
        const int row = j >> 4, c = j & 15;
        const __half* src = (half_ ? Ql : Qh) + qbase + (size_t)row * HDIM + c * 8;
        const uint32_t dst = sb + (half_ ? AQ_L : AQ_H) + (row * ASTR + c * 8) * 2;
        CP_ASYNC16(dst, src);
    }
    CP_COMMIT();
    attn_load_kv(Kh, Vth, sb + AKV0,         kbase, vtbase, 0,  tid); CP_COMMIT();
    attn_load_kv(Kh, Vth, sb + AKV0 + KVBUF, kbase, vtbase, 64, tid); CP_COMMIT();

    CP_WAIT(2);
    __syncthreads();
    uint32_t qfh[8][4], qfl[8][4];
    {
        const uint32_t la = ((wid * 16 + (lane & 15)) * ASTR + (lane >> 4) * 8) * 2;
#pragma unroll
        for (int kk = 0; kk < 8; kk++) {
            ldm_x4(qfh[kk], sb + AQ_H + la + kk * 32);
            ldm_x4(qfl[kk], sb + AQ_L + la + kk * 32);
        }
    }

    float o[16][4];
#pragma unroll
    for (int jj = 0; jj < 16; jj++)
#pragma unroll
        for (int q = 0; q < 4; q++) o[jj][q] = 0.f;
    float m0 = -1e30f, m1 = -1e30f, sl0 = 0.f, sl1 = 0.f;

    const int r0 = q0 + wid * 16 + g;
    const uint32_t laneNK = ((lane >> 4) * 8 + (lane & 7));
    const uint32_t laneKhi = ((lane >> 3) & 1) * 8;

    for (int kt = 0; kt < nkt; kt++) {
        const int k0 = kt * 64;
        const uint32_t buf = sb + AKV0 + (kt & 1) * KVBUF;
        if (kt + 1 < nkt) { CP_WAIT(1); } else { CP_WAIT(0); }
        __syncthreads();

        // ---- S = Q K^T ----
        float sacc[8][4];
#pragma unroll
        for (int j = 0; j < 8; j++)
#pragma unroll
            for (int q = 0; q < 4; q++) sacc[j][q] = 0.f;

#pragma unroll
        for (int kk = 0; kk < 8; kk++) {
#pragma unroll
            for (int p = 0; p < 4; p++) {
                const uint32_t off = ((p * 16 + laneNK) * ASTR + laneKhi) * 2 + kk * 32;
                uint32_t fk[4];
                ldm_x4(fk, buf + AK_H + off);
                uint32_t b0[2] = {fk[0], fk[1]}, b1[2] = {fk[2], fk[3]};
                mma16816(sacc[2 * p],     qfh[kk], b0);
                mma16816(sacc[2 * p + 1], qfh[kk], b1);
                mma16816(sacc[2 * p],     qfl[kk], b0);
                mma16816(sacc[2 * p + 1], qfl[kk], b1);
            }
        }

        // ---- causal mask ----
        if (kt >= nkt - 2) {
#pragma unroll
            for (int j = 0; j < 8; j++) {
#pragma unroll
                for (int e = 0; e < 2; e++) {
                    const int col = k0 + j * 8 + tq * 2 + e;
                    if (col > r0)     sacc[j][e]     = -1e30f;
                    if (col > r0 + 8) sacc[j][2 + e] = -1e30f;
                }
            }
        }

        // ---- online softmax ----
        float mt0 = -1e30f, mt1 = -1e30f;
#pragma unroll
        for (int j = 0; j < 8; j++) {
            mt0 = fmaxf(mt0, fmaxf(sacc[j][0], sacc[j][1]));
            mt1 = fmaxf(mt1, fmaxf(sacc[j][2], sacc[j][3]));
        }
        mt0 = fmaxf(mt0, __shfl_xor_sync(0xffffffffu, mt0, 1));
        mt0 = fmaxf(mt0, __shfl_xor_sync(0xffffffffu, mt0, 2));
        mt1 = fmaxf(mt1, __shfl_xor_sync(0xffffffffu, mt1, 1));
        mt1 = fmaxf(mt1, __shfl_xor_sync(0xffffffffu, mt1, 2));
        const float mn0 = fmaxf(m0, mt0), mn1 = fmaxf(m1, mt1);
        const float al0 = __expf(m0 - mn0), al1 = __expf(m1 - mn1);
        float s0 = 0.f, s1 = 0.f;
#pragma unroll
        for (int j = 0; j < 8; j++) {
            sacc[j][0] = __expf(sacc[j][0] - mn0);
            sacc[j][1] = __expf(sacc[j][1] - mn0);
            sacc[j][2] = __expf(sacc[j][2] - mn1);
            sacc[j][3] = __expf(sacc[j][3] - mn1);
            s0 += sacc[j][0] + sacc[j][1];
            s1 += sacc[j][2] + sacc[j][3];
        }
        s0 += __shfl_xor_sync(0xffffffffu, s0, 1);
        s0 += __shfl_xor_sync(0xffffffffu, s0, 2);
        s1 += __shfl_xor_sync(0xffffffffu, s1, 1);
        s1 += __shfl_xor_sync(0xffffffffu, s1, 2);
        sl0 = sl0 * al0 + s0;  sl1 = sl1 * al1 + s1;
        m0 = mn0;              m1 = mn1;
#pragma unroll
        for (int jj = 0; jj < 16; jj++) {
            o[jj][0] *= al0; o[jj][1] *= al0;
            o[jj][2] *= al1; o[jj][3] *= al1;
        }

        // ---- P fragments ----
        uint32_t ph[4][4];
#pragma unroll
        for (int kk2 = 0; kk2 < 4; kk2++) {
            const int j0 = 2 * kk2, j1 = j0 + 1;
            ph[kk2][0] = packh(sacc[j0][0], sacc[j0][1]);
            ph[kk2][1] = packh(sacc[j0][2], sacc[j0][3]);
            ph[kk2][2] = packh(sacc[j1][0], sacc[j1][1]);
            ph[kk2][3] = packh(sacc[j1][2], sacc[j1][3]);
        }

        // ---- O += P V ----
#pragma unroll
        for (int kk2 = 0; kk2 < 4; kk2++) {
#pragma unroll
            for (int p = 0; p < 8; p++) {
                const uint32_t off = ((p * 16 + laneNK) * VSTR + laneKhi + kk2 * 16) * 2;
                uint32_t fv[4];
                ldm_x4(fv, buf + AV_H + off);
                uint32_t b0[2] = {fv[0], fv[1]}, b1[2] = {fv[2], fv[3]};
                mma16816(o[2 * p],     ph[kk2], b0);
                mma16816(o[2 * p + 1], ph[kk2], b1);
            }
        }

        __syncthreads();
        if (kt + 2 < nkt) {
            attn_load_kv(Kh, Vth, sb + AKV0 + (kt & 1) * KVBUF,
                         kbase, vtbase, (kt + 2) * 64, tid);
            CP_COMMIT();
        }
    }

    // ---- epilogue: single fp16 ctx ----
    const float inv0 = 1.f / sl0, inv1 = 1.f / sl1;
#pragma unroll
    for (int jj = 0; jj < 16; jj++) {
        const int d = jj * 8 + tq * 2;
        const size_t o0 = (size_t)(b * SEQ + r0) * HIDDEN + h * HDIM + d;
        const size_t o1 = o0 + (size_t)8 * HIDDEN;
        *(uint32_t*)(Ch + o0) = packh(o[jj][0] * inv0, o[jj][1] * inv0);
        *(uint32_t*)(Ch + o1) = packh(o[jj][2] * inv1, o[jj][3] * inv1);
    }
}

// ---------------------------------------------------------------------------
// Launch
// ---------------------------------------------------------------------------
extern "C" void kernel_launch(void* const* d_in, const int* in_sizes, int n_in,
                              void* d_out, int out_size) {
    const float* X   = (const float*)d_in[0];
    const int*   pos = (const int*)  d_in[1];
    const float* Wq  = (const float*)d_in[2];
    const float* Wk  = (const float*)d_in[3];
    const float* Wv  = (const float*)d_in[4];
    const float* Wo  = (const float*)d_in[5];
    float* out = (float*)d_out;

    float* QKV;
    __half *Xh, *Ch, *W3, *WoT;
    __half *Qbh, *Qbl, *Kbh, *Vth;
    cudaGetSymbolAddress((void**)&QKV, g_QKV);
    cudaGetSymbolAddress((void**)&Xh, g_Xh);
    cudaGetSymbolAddress((void**)&Ch, g_Ch);
    cudaGetSymbolAddress((void**)&W3, g_W3T);
    cudaGetSymbolAddress((void**)&WoT, g_WoT);
    cudaGetSymbolAddress((void**)&Qbh, g_Qbh);
    cudaGetSymbolAddress((void**)&Qbl, g_Qbl);
    cudaGetSymbolAddress((void**)&Kbh, g_Kbh);
    cudaGetSymbolAddress((void**)&Vth, g_Vth);

    const int total8 = MROWS * KDIM / 8;
    conv_a_kernel<<<(total8 + 255) / 256, 256>>>(X, Xh, total8);
    split_w_all_kernel<<<dim3(64, 64, 4), dim3(32, 8)>>>(Wq, Wk, Wv, Wo, W3, WoT);

    cudaFuncSetAttribute(mma_gemm1, cudaFuncAttributeMaxDynamicSharedMemorySize, GEMM1_SMEM);

    // Fused QKV projection (1-term)
    mma_gemm1<<<dim3(N_QKV / 128, 32), 256, GEMM1_SMEM>>>(Xh, W3, QKV, N_QKV);

    // RoPE + V transpose
    const int rope_total = BATCH * SEQ * (NHEADS + NKVH) * 64;
    rope_split_kernel<<<(rope_total + 255) / 256, 256>>>(QKV, pos, Qbh, Qbl, Kbh);
    vt_split_kernel<<<dim3(64, 4, 8), dim3(32, 8)>>>(QKV, Vth);

    // Flash attention
    cudaFuncSetAttribute(attn_mma_kernel, cudaFuncAttributeMaxDynamicSharedMemorySize, ATTN_SMEM);
    attn_mma_kernel<<<dim3(SEQ / 128, NHEADS, BATCH), 256, ATTN_SMEM>>>(
        Qbh, Qbl, Kbh, Vth, Ch);

    // Output projection (1-term)
    mma_gemm1<<<dim3(16, 32), 256, GEMM1_SMEM>>>(Ch, WoT, out, 2048);
}

// round 14
// speedup vs baseline: 8.5989x; 1.0788x over previous
#include <cuda_runtime.h>
#include <cuda_fp16.h>
#include <cstdint>
#include <math.h>

// Problem constants
constexpr int BATCH  = 2;
constexpr int SEQ    = 2048;
constexpr int HIDDEN = 2048;
constexpr int NHEADS = 16;
constexpr int NKVH   = 4;
constexpr int HDIM   = 128;
constexpr float QK_SCALE = 0.08838834764831845f; // 1/sqrt(128)

constexpr int MROWS = BATCH * SEQ;   // 4096
constexpr int KDIM  = HIDDEN;        // 2048
constexpr int N_QKV = HIDDEN + 2 * NKVH * HDIM;  // 3072

// ---------------------------------------------------------------------------
// Device-global scratch
// ---------------------------------------------------------------------------
__device__ float g_QKV[(size_t)MROWS * N_QKV];    // fused Q|K|V fp32

__device__ __align__(16) __half g_Xh[(size_t)MROWS * KDIM];   // X fp16
__device__ __align__(16) __half g_Ch[(size_t)MROWS * KDIM];   // ctx fp16
__device__ __align__(16) __half g_W3T[(size_t)N_QKV * KDIM];  // Wq|Wk|Wv ^T
__device__ __align__(16) __half g_WoT[(size_t)HIDDEN * KDIM]; // Wo^T

// Attention operands (all single fp16)
__device__ __align__(16) __half g_Qbh[(size_t)BATCH * NHEADS * SEQ * HDIM];
__device__ __align__(16) __half g_Kbh[(size_t)BATCH * NKVH * SEQ * HDIM];
__device__ __align__(16) __half g_Vth[(size_t)BATCH * NKVH * HDIM * SEQ];

// ---------------------------------------------------------------------------
// PTX helpers
// ---------------------------------------------------------------------------
__device__ __forceinline__ uint32_t smem_u32(const void* p) {
    uint32_t a;
    asm("{ .reg .u64 t; cvta.to.shared.u64 t, %1; cvt.u32.u64 %0, t; }"
        : "=r"(a) : "l"(p));
    return a;
}

#define CP_ASYNC16(dst, src) \
    asm volatile("cp.async.cg.shared.global [%0], [%1], 16;" :: "r"(dst), "l"(src))
#define CP_COMMIT() asm volatile("cp.async.commit_group;" ::: "memory")
#define CP_WAIT(n)  asm volatile("cp.async.wait_group %0;" :: "n"(n) : "memory")

__device__ __forceinline__ void ldm_x4(uint32_t* r, uint32_t addr) {
    asm volatile("ldmatrix.sync.aligned.m8n8.x4.shared.b16 {%0,%1,%2,%3}, [%4];"
                 : "=r"(r[0]), "=r"(r[1]), "=r"(r[2]), "=r"(r[3]) : "r"(addr));
}
__device__ __forceinline__ void mma16816(float* d, const uint32_t* a, const uint32_t* b) {
    asm volatile("mma.sync.aligned.m16n8k16.row.col.f32.f16.f16.f32 "
                 "{%0,%1,%2,%3}, {%4,%5,%6,%7}, {%8,%9}, {%0,%1,%2,%3};"
                 : "+f"(d[0]), "+f"(d[1]), "+f"(d[2]), "+f"(d[3])
                 : "r"(a[0]), "r"(a[1]), "r"(a[2]), "r"(a[3]), "r"(b[0]), "r"(b[1]));
}
__device__ __forceinline__ uint32_t packh(float lo, float hi) {
    __half2 t = __floats2half2_rn(lo, hi);
    return *(uint32_t*)&t;
}

// ---------------------------------------------------------------------------
// Conversions
// ---------------------------------------------------------------------------
__global__ void conv_a_kernel(const float* __restrict__ X,
                              __half* __restrict__ H, int total8) {
    int t = blockIdx.x * blockDim.x + threadIdx.x;
    if (t >= total8) return;
    const int base = t * 8;
    float4 x0 = *(const float4*)(X + base);
    float4 x1 = *(const float4*)(X + base + 4);
    float xs[8] = {x0.x, x0.y, x0.z, x0.w, x1.x, x1.y, x1.z, x1.w};
    __half hs[8];
#pragma unroll
    for (int i = 0; i < 8; i++) hs[i] = __float2half_rn(xs[i]);
    *(uint4*)(H + base) = *(const uint4*)hs;
}

// All 4 weights: W [K][N] fp32 -> WT [N][K] fp16, one launch.
__global__ void split_w_all_kernel(const float* __restrict__ Wq, const float* __restrict__ Wk,
                                   const float* __restrict__ Wv, const float* __restrict__ Wo,
                                   __half* __restrict__ W3T, __half* __restrict__ WoT) {
    __shared__ float s[32][33];
    const int z = blockIdx.z;
    const float* W;
    __half* dst;
    int N, rowoff;
    if      (z == 0) { W = Wq; dst = W3T; N = 2048; rowoff = 0;    }
    else if (z == 1) { W = Wk; dst = W3T; N = 512;  rowoff = 2048; }
    else if (z == 2) { W = Wv; dst = W3T; N = 512;  rowoff = 2560; }
    else             { W = Wo; dst = WoT; N = 2048; rowoff = 0;    }
    const int n0 = blockIdx.y * 32;
    if (n0 >= N) return;
    const int k0 = blockIdx.x * 32;
    const int tx = threadIdx.x, ty = threadIdx.y;  // 32 x 8
#pragma unroll
    for (int i = 0; i < 4; i++)
        s[ty + 8 * i][tx] = W[(size_t)(k0 + ty + 8 * i) * N + n0 + tx];
    __syncthreads();
#pragma unroll
    for (int i = 0; i < 4; i++) {
        const int n = ty + 8 * i;
        dst[(size_t)(rowoff + n0 + n) * KDIM + k0 + tx] = __float2half_rn(s[tx][n]);
    }
}

// ---------------------------------------------------------------------------
// fp16 mma.sync GEMM, 1-term: C[M][N] = A @ Bt^T.
// CTA 128x128, BK=32, 3-stage cp.async, 8 warps (64x32 warp tile).
// ---------------------------------------------------------------------------
constexpr int GSTRIDE = 40;
constexpr int GTILE_B = 128 * GSTRIDE * 2;   // 10240 bytes
constexpr int G1STAGE_B = 2 * GTILE_B;       // 20480
constexpr int GEMM1_SMEM = 3 * G1STAGE_B;    // 61440

__device__ __forceinline__ void gemm1_load_stage(
    const __half* __restrict__ A, const __half* __restrict__ Bt,
    uint32_t stageBase, int m0, int n0, int k0, int tid) {
#pragma unroll
    for (int i = 0; i < 4; i++) {
        const int idx = tid + i * 256;      // 0..1023
        const int tile = idx >> 9;          // 0..1
        const int c = idx & 511;
        const int row = c >> 2;
        const int kc = (c & 3) * 8;
        const __half* src = (tile == 0)
            ? A  + (size_t)(m0 + row) * KDIM + k0 + kc
            : Bt + (size_t)(n0 + row) * KDIM + k0 + kc;
        const uint32_t dst = stageBase + tile * GTILE_B + (row * GSTRIDE + kc) * 2;
        CP_ASYNC16(dst, src);
    }
}

__global__ __launch_bounds__(256, 2)
void mma_gemm1(const __half* __restrict__ A, const __half* __restrict__ Bt,
               float* __restrict__ C, int N) {
    extern __shared__ __align__(16) uint8_t smg[];
    const uint32_t sb = smem_u32(smg);
    const int tid = threadIdx.x;
    const int wid = tid >> 5, lane = tid & 31;
    const int m0 = blockIdx.y * 128, n0 = blockIdx.x * 128;
    const int mw = (wid & 1) * 64;
    const int nw = (wid >> 1) * 32;

    float acc[4][4][4];
#pragma unroll
    for (int i = 0; i < 4; i++)
#pragma unroll
        for (int j = 0; j < 4; j++)
#pragma unroll
            for (int q = 0; q < 4; q++) acc[i][j][q] = 0.f;

    const uint32_t laneA = ((lane & 15) * GSTRIDE + (lane >> 4) * 8) * 2;
    const uint32_t laneB = ((((lane >> 4) << 3) + (lane & 7)) * GSTRIDE
                           + ((lane >> 3) & 1) * 8) * 2;

    const int T = KDIM / 32;
    gemm1_load_stage(A, Bt, sb, m0, n0, 0, tid);              CP_COMMIT();
    gemm1_load_stage(A, Bt, sb + G1STAGE_B, m0, n0, 32, tid); CP_COMMIT();

    for (int t = 0; t < T; t++) {
        const uint32_t stg = sb + (t % 3) * G1STAGE_B;
        if (t + 1 < T) { CP_WAIT(1); } else { CP_WAIT(0); }
        __syncthreads();

        const uint32_t aA = stg + 0 * GTILE_B + mw * GSTRIDE * 2 + laneA;
        const uint32_t bB = stg + 1 * GTILE_B + nw * GSTRIDE * 2 + laneB;

#pragma unroll
        for (int kk = 0; kk < 2; kk++) {
            const uint32_t ko = kk * 32;
            uint32_t fb[2][4];
#pragma unroll
            for (int p = 0; p < 2; p++)
                ldm_x4(fb[p], bB + p * 16 * GSTRIDE * 2 + ko);
#pragma unroll
            for (int i = 0; i < 4; i++) {
                uint32_t fa[4];
                ldm_x4(fa, aA + i * 16 * GSTRIDE * 2 + ko);
#pragma unroll
                for (int j = 0; j < 4; j++) {
                    const int p = j >> 1, h = (j & 1) * 2;
                    uint32_t bf[2] = {fb[p][h], fb[p][h + 1]};
                    mma16816(acc[i][j], fa, bf);
                }
            }
        }
        __syncthreads();
        if (t + 2 < T) {
            gemm1_load_stage(A, Bt, sb + ((t + 2) % 3) * G1STAGE_B,
                             m0, n0, (t + 2) * 32, tid);
            CP_COMMIT();
        }
    }

    const int g = lane >> 2, tq = lane & 3;
#pragma unroll
    for (int i = 0; i < 4; i++) {
        const int r0 = m0 + mw + i * 16 + g;
#pragma unroll
        for (int j = 0; j < 4; j++) {
            const int col = n0 + nw + j * 8 + tq * 2;
            *(float2*)(C + (size_t)r0 * N + col)       = make_float2(acc[i][j][0], acc[i][j][1]);
            *(float2*)(C + (size_t)(r0 + 8) * N + col) = make_float2(acc[i][j][2], acc[i][j][3]);
        }
    }
}

// ---------------------------------------------------------------------------
// RoPE + relayout from fused QKV [4096][3072] (Q and K single fp16)
// ---------------------------------------------------------------------------
__global__ void rope_split_kernel(const float* __restrict__ QKV,
                                  const int* __restrict__ pos,
                                  __half* __restrict__ Qh, __half* __restrict__ Kh) {
    const int total = BATCH * SEQ * (NHEADS + NKVH) * 64;
    int idx = blockIdx.x * blockDim.x + threadIdx.x;
    if (idx >= total) return;
    const int p = idx & 63;
    int rest = idx >> 6;
    const int hh = rest % (NHEADS + NKVH);
    const int bs = rest / (NHEADS + NKVH);
    const int b = bs >> 11, s = bs & 2047;

    const float fpos = (float)pos[bs];
    const float inv = powf(10000.f, -(float)p * (1.f / 64.f));
    const float ang = fpos * inv;
    float sn, c;
    sincosf(ang, &sn, &c);

    if (hh < NHEADS) {
        const float* src = QKV + (size_t)bs * N_QKV + hh * HDIM;
        const float x1 = src[p], x2 = src[p + 64];
        const size_t obase = ((size_t)(b * NHEADS + hh) * SEQ + s) * HDIM;
        Qh[obase + p]      = __float2half_rn((x1 * c - x2 * sn) * QK_SCALE);
        Qh[obase + p + 64] = __float2half_rn((x2 * c + x1 * sn) * QK_SCALE);
    } else {
        const int kv = hh - NHEADS;
        const float* src = QKV + (size_t)bs * N_QKV + HIDDEN + kv * HDIM;
        const float x1 = src[p], x2 = src[p + 64];
        const size_t obase = ((size_t)(b * NKVH + kv) * SEQ + s) * HDIM;
        Kh[obase + p]      = __float2half_rn(x1 * c - x2 * sn);
        Kh[obase + p + 64] = __float2half_rn(x2 * c + x1 * sn);
    }
}

// V -> Vth fp16 [B,kvh,D,S]
__global__ void vt_split_kernel(const float* __restrict__ QKV,
                                __half* __restrict__ TH) {
    __shared__ float s[32][33];
    const int s0 = blockIdx.x * 32, d0 = blockIdx.y * 32;
    const int b = blockIdx.z >> 2, kv = blockIdx.z & 3;
    const int tx = threadIdx.x, ty = threadIdx.y;
#pragma unroll
    for (int i = 0; i < 4; i++) {
        const int ss = s0 + ty + 8 * i;
        s[ty + 8 * i][tx] =
            QKV[(size_t)(b * SEQ + ss) * N_QKV + HIDDEN + NKVH * HDIM + kv * HDIM + d0 + tx];
    }
    __syncthreads();
#pragma unroll
    for (int i = 0; i < 4; i++) {
        const int d = ty + 8 * i;
        const size_t o = ((size_t)(b * NKVH + kv) * HDIM + d0 + d) * SEQ + s0 + tx;
        TH[o] = __float2half_rn(s[tx][d]);
    }
}

// ---------------------------------------------------------------------------
// Tensor-core flash attention (causal, GQA; all operands single fp16).
// BQ=128, BK=64, 256 threads, double-buffered cp.async KV.
// ---------------------------------------------------------------------------
constexpr int ASTR = 136;
constexpr int VSTR = 72;
constexpr int AQ_H = 0;
constexpr int AKV0 = 128 * ASTR * 2;                 // 34816
constexpr int AK_H = 0;
constexpr int AV_H = 64 * ASTR * 2;                  // 17408
constexpr int KVBUF = AV_H + 128 * VSTR * 2;         // 35840
constexpr int ATTN_SMEM = AKV0 + 2 * KVBUF;          // 106496

__device__ __forceinline__ void attn_load_kv(
    const __half* __restrict__ Kh, const __half* __restrict__ Vth,
    uint32_t bufBase, size_t kbase, size_t vtbase, int k0, int tid) {
#pragma unroll
    for (int i = 0; i < 8; i++) {
        const int idx = tid + i * 256;
        if (idx < 1024) {
            const int row = idx >> 4, c = idx & 15;
            const __half* src = Kh + kbase + (size_t)(k0 + row) * HDIM + c * 8;
            const uint32_t dst = bufBase + AK_H + (row * ASTR + c * 8) * 2;
            CP_ASYNC16(dst, src);
        } else {
            const int v = idx - 1024;
            const int row = v >> 3, c = v & 7;
            const __half* src = Vth + vtbase + (size_t)row * SEQ + k0 + c * 8;
            const uint32_t dst = bufBase + AV_H + (row * VSTR + c * 8) * 2;
            CP_ASYNC16(dst, src);
        }
    }
}

__global__ __launch_bounds__(256, 1)
void attn_mma_kernel(const __half* __restrict__ Qh,
                     const __half* __restrict__ Kh, const __half* __restrict__ Vth,
                     __half* __restrict__ Ch) {
    extern __shared__ __align__(16) uint8_t smb[];
    const uint32_t sb = smem_u32(smb);
    const int tid = threadIdx.x;
    const int wid = tid >> 5, lane = tid & 31;
    const int g = lane >> 2, tq = lane & 3;

    const int qt = gridDim.x - 1 - blockIdx.x;
    const int h = blockIdx.y, b = blockIdx.z;
    const int kvh = h >> 2;
    const int q0 = qt * 128;
    const int nkt = 2 * qt + 2;

    const size_t qbase  = ((size_t)(b * NHEADS + h) * SEQ + q0) * HDIM;
    const size_t kbase  = ((size_t)(b * NKVH + kvh) * SEQ) * HDIM;
    const size_t vtbase = ((size_t)(b * NKVH + kvh) * HDIM) * SEQ;

    // Q tile load (2048 16B-chunks)
#pragma unroll
    for (int i = 0; i < 8; i++) {
        const int idx = tid + i * 256;
        const int row = idx >> 4, c = idx & 15;
        const __half* src = Qh + qbase + (size_t)row * HDIM + c * 8;
        const uint32_t dst = sb + AQ_H + (row * ASTR + c * 8) * 2;
        CP_ASYNC16(dst, src);
    }
    CP_COMMIT();
    attn_load_kv(Kh, Vth, sb + AKV0,         kbase, vtbase, 0,  tid); CP_COMMIT();
    attn_load_kv(Kh, Vth, sb + AKV0 + KVBUF, kbase, vtbase, 64, tid); CP_COMMIT();

    CP_WAIT(2);
    __syncthreads();
    uint32_t qf[8][4];
    {
        const uint32_t la = ((wid * 16 + (lane & 15)) * ASTR + (lane >> 4) * 8) * 2;
#pragma unroll
        for (int kk = 0; kk < 8; kk++)
            ldm_x4(qf[kk], sb + AQ_H + la + kk * 32);
    }

    float o[16][4];
#pragma unroll
    for (int jj = 0; jj < 16; jj++)
#pragma unroll
        for (int q = 0; q < 4; q++) o[jj][q] = 0.f;
    float m0 = -1e30f, m1 = -1e30f, sl0 = 0.f, sl1 = 0.f;

    const int r0 = q0 + wid * 16 + g;
    const uint32_t laneNK = ((lane >> 4) * 8 + (lane & 7));
    const uint32_t laneKhi = ((lane >> 3) & 1) * 8;

    for (int kt = 0; kt < nkt; kt++) {
        const int k0 = kt * 64;
        const uint32_t buf = sb + AKV0 + (kt & 1) * KVBUF;
        if (kt + 1 < nkt) { CP_WAIT(1); } else { CP_WAIT(0); }
        __syncthreads();

        // ---- S = Q K^T (single term) ----
        float sacc[8][4];
#pragma unroll
        for (int j = 0; j < 8; j++)
#pragma unroll
            for (int q = 0; q < 4; q++) sacc[j][q] = 0.f;

#pragma unroll
        for (int kk = 0; kk < 8; kk++) {
#pragma unroll
            for (int p = 0; p < 4; p++) {
                const uint32_t off = ((p * 16 + laneNK) * ASTR + laneKhi) * 2 + kk * 32;
                uint32_t fk[4];
                ldm_x4(fk, buf + AK_H + off);
                uint32_t b0[2] = {fk[0], fk[1]}, b1[2] = {fk[2], fk[3]};
                mma16816(sacc[2 * p],     qf[kk], b0);
                mma16816(sacc[2 * p + 1], qf[kk], b1);
            }
        }

        // ---- causal mask ----
        if (kt >= nkt - 2) {
#pragma unroll
            for (int j = 0; j < 8; j++) {
#pragma unroll
                for (int e = 0; e < 2; e++) {
                    const int col = k0 + j * 8 + tq * 2 + e;
                    if (col > r0)     sacc[j][e]     = -1e30f;
                    if (col > r0 + 8) sacc[j][2 + e] = -1e30f;
                }
            }
        }

        // ---- online softmax ----
        float mt0 = -1e30f, mt1 = -1e30f;
#pragma unroll
        for (int j = 0; j < 8; j++) {
            mt0 = fmaxf(mt0, fmaxf(sacc[j][0], sacc[j][1]));
            mt1 = fmaxf(mt1, fmaxf(sacc[j][2], sacc[j][3]));
        }
        mt0 = fmaxf(mt0, __shfl_xor_sync(0xffffffffu, mt0, 1));
        mt0 = fmaxf(mt0, __shfl_xor_sync(0xffffffffu, mt0, 2));
        mt1 = fmaxf(mt1, __shfl_xor_sync(0xffffffffu, mt1, 1));
        mt1 = fmaxf(mt1, __shfl_xor_sync(0xffffffffu, mt1, 2));
        const float mn0 = fmaxf(m0, mt0), mn1 = fmaxf(m1, mt1);
        const float al0 = __expf(m0 - mn0), al1 = __expf(m1 - mn1);
        float s0 = 0.f, s1 = 0.f;
#pragma unroll
        for (int j = 0; j < 8; j++) {
            sacc[j][0] = __expf(sacc[j][0] - mn0);
            sacc[j][1] = __expf(sacc[j][1] - mn0);
            sacc[j][2] = __expf(sacc[j][2] - mn1);
            sacc[j][3] = __expf(sacc[j][3] - mn1);
            s0 += sacc[j][0] + sacc[j][1];
            s1 += sacc[j][2] + sacc[j][3];
        }
        s0 += __shfl_xor_sync(0xffffffffu, s0, 1);
        s0 += __shfl_xor_sync(0xffffffffu, s0, 2);
        s1 += __shfl_xor_sync(0xffffffffu, s1, 1);
        s1 += __shfl_xor_sync(0xffffffffu, s1, 2);
        sl0 = sl0 * al0 + s0;  sl1 = sl1 * al1 + s1;
        m0 = mn0;              m1 = mn1;
#pragma unroll
        for (int jj = 0; jj < 16; jj++) {
            o[jj][0] *= al0; o[jj][1] *= al0;
            o[jj][2] *= al1; o[jj][3] *= al1;
        }

        // ---- P fragments ----
        uint32_t ph[4][4];
#pragma unroll
        for (int kk2 = 0; kk2 < 4; kk2++) {
            const int j0 = 2 * kk2, j1 = j0 + 1;
            ph[kk2][0] = packh(sacc[j0][0], sacc[j0][1]);
            ph[kk2][1] = packh(sacc[j0][2], sacc[j0][3]);
            ph[kk2][2] = packh(sacc[j1][0], sacc[j1][1]);
            ph[kk2][3] = packh(sacc[j1][2], sacc[j1][3]);
        }

        // ---- O += P V ----
#pragma unroll
        for (int kk2 = 0; kk2 < 4; kk2++) {
#pragma unroll
            for (int p = 0; p < 8; p++) {
                const uint32_t off = ((p * 16 + laneNK) * VSTR + laneKhi + kk2 * 16) * 2;
                uint32_t fv[4];
                ldm_x4(fv, buf + AV_H + off);
                uint32_t b0[2] = {fv[0], fv[1]}, b1[2] = {fv[2], fv[3]};
                mma16816(o[2 * p],     ph[kk2], b0);
                mma16816(o[2 * p + 1], ph[kk2], b1);
            }
        }

        __syncthreads();
        if (kt + 2 < nkt) {
            attn_load_kv(Kh, Vth, sb + AKV0 + (kt & 1) * KVBUF,
                         kbase, vtbase, (kt + 2) * 64, tid);
            CP_COMMIT();
        }
    }

    // ---- epilogue: single fp16 ctx ----
    const float inv0 = 1.f / sl0, inv1 = 1.f / sl1;
#pragma unroll
    for (int jj = 0; jj < 16; jj++) {
        const int d = jj * 8 + tq * 2;
        const size_t o0 = (size_t)(b * SEQ + r0) * HIDDEN + h * HDIM + d;
        const size_t o1 = o0 + (size_t)8 * HIDDEN;
        *(uint32_t*)(Ch + o0) = packh(o[jj][0] * inv0, o[jj][1] * inv0);
        *(uint32_t*)(Ch + o1) = packh(o[jj][2] * inv1, o[jj][3] * inv1);
    }
}

// ---------------------------------------------------------------------------
// Launch
// ---------------------------------------------------------------------------
extern "C" void kernel_launch(void* const* d_in, const int* in_sizes, int n_in,
                              void* d_out, int out_size) {
    const float* X   = (const float*)d_in[0];
    const int*   pos = (const int*)  d_in[1];
    const float* Wq  = (const float*)d_in[2];
    const float* Wk  = (const float*)d_in[3];
    const float* Wv  = (const float*)d_in[4];
    const float* Wo  = (const float*)d_in[5];
    float* out = (float*)d_out;

    float* QKV;
    __half *Xh, *Ch, *W3, *WoT;
    __half *Qbh, *Kbh, *Vth;
    cudaGetSymbolAddress((void**)&QKV, g_QKV);
    cudaGetSymbolAddress((void**)&Xh, g_Xh);
    cudaGetSymbolAddress((void**)&Ch, g_Ch);
    cudaGetSymbolAddress((void**)&W3, g_W3T);
    cudaGetSymbolAddress((void**)&WoT, g_WoT);
    cudaGetSymbolAddress((void**)&Qbh, g_Qbh);
    cudaGetSymbolAddress((void**)&Kbh, g_Kbh);
    cudaGetSymbolAddress((void**)&Vth, g_Vth);

    const int total8 = MROWS * KDIM / 8;
    conv_a_kernel<<<(total8 + 255) / 256, 256>>>(X, Xh, total8);
    split_w_all_kernel<<<dim3(64, 64, 4), dim3(32, 8)>>>(Wq, Wk, Wv, Wo, W3, WoT);

    cudaFuncSetAttribute(mma_gemm1, cudaFuncAttributeMaxDynamicSharedMemorySize, GEMM1_SMEM);

    // Fused QKV projection (1-term)
    mma_gemm1<<<dim3(N_QKV / 128, 32), 256, GEMM1_SMEM>>>(Xh, W3, QKV, N_QKV);

    // RoPE + V transpose
    const int rope_total = BATCH * SEQ * (NHEADS + NKVH) * 64;
    rope_split_kernel<<<(rope_total + 255) / 256, 256>>>(QKV, pos, Qbh, Kbh);
    vt_split_kernel<<<dim3(64, 4, 8), dim3(32, 8)>>>(QKV, Vth);

    // Flash attention (all single fp16)
    cudaFuncSetAttribute(attn_mma_kernel, cudaFuncAttributeMaxDynamicSharedMemorySize, ATTN_SMEM);
    attn_mma_kernel<<<dim3(SEQ / 128, NHEADS, BATCH), 256, ATTN_SMEM>>>(
        Qbh, Kbh, Vth, Ch);

    // Output projection (1-term)
    mma_gemm1<<<dim3(16, 32), 256, GEMM1_SMEM>>>(Ch, WoT, out, 2048);
}

// round 17
// speedup vs baseline: 8.9079x; 1.0359x over previous
#include <cuda_runtime.h>
#include <cuda_fp16.h>
#include <cstdint>
#include <math.h>

// Problem constants
constexpr int BATCH  = 2;
constexpr int SEQ    = 2048;
constexpr int HIDDEN = 2048;
constexpr int NHEADS = 16;
constexpr int NKVH   = 4;
constexpr int HDIM   = 128;
constexpr float QK_SCALE = 0.08838834764831845f; // 1/sqrt(128)

constexpr int MROWS = BATCH * SEQ;   // 4096
constexpr int KDIM  = HIDDEN;        // 2048
constexpr int N_QKV = HIDDEN + 2 * NKVH * HDIM;  // 3072

// ---------------------------------------------------------------------------
// Device-global scratch
// ---------------------------------------------------------------------------
__device__ __align__(16) __half g_QKVh[(size_t)MROWS * N_QKV];  // fused Q|K|V fp16

__device__ __align__(16) __half g_Xh[(size_t)MROWS * KDIM];   // X fp16
__device__ __align__(16) __half g_Ch[(size_t)MROWS * KDIM];   // ctx fp16
__device__ __align__(16) __half g_W3T[(size_t)N_QKV * KDIM];  // Wq|Wk|Wv ^T
__device__ __align__(16) __half g_WoT[(size_t)HIDDEN * KDIM]; // Wo^T

// Attention operands (all single fp16)
__device__ __align__(16) __half g_Qbh[(size_t)BATCH * NHEADS * SEQ * HDIM];
__device__ __align__(16) __half g_Kbh[(size_t)BATCH * NKVH * SEQ * HDIM];
__device__ __align__(16) __half g_Vth[(size_t)BATCH * NKVH * HDIM * SEQ];

// ---------------------------------------------------------------------------
// PTX helpers
// ---------------------------------------------------------------------------
__device__ __forceinline__ uint32_t smem_u32(const void* p) {
    uint32_t a;
    asm("{ .reg .u64 t; cvta.to.shared.u64 t, %1; cvt.u32.u64 %0, t; }"
        : "=r"(a) : "l"(p));
    return a;
}

#define CP_ASYNC16(dst, src) \
    asm volatile("cp.async.cg.shared.global [%0], [%1], 16;" :: "r"(dst), "l"(src))
#define CP_COMMIT() asm volatile("cp.async.commit_group;" ::: "memory")
#define CP_WAIT(n)  asm volatile("cp.async.wait_group %0;" :: "n"(n) : "memory")

__device__ __forceinline__ void ldm_x4(uint32_t* r, uint32_t addr) {
    asm volatile("ldmatrix.sync.aligned.m8n8.x4.shared.b16 {%0,%1,%2,%3}, [%4];"
                 : "=r"(r[0]), "=r"(r[1]), "=r"(r[2]), "=r"(r[3]) : "r"(addr));
}
__device__ __forceinline__ void mma16816(float* d, const uint32_t* a, const uint32_t* b) {
    asm volatile("mma.sync.aligned.m16n8k16.row.col.f32.f16.f16.f32 "
                 "{%0,%1,%2,%3}, {%4,%5,%6,%7}, {%8,%9}, {%0,%1,%2,%3};"
                 : "+f"(d[0]), "+f"(d[1]), "+f"(d[2]), "+f"(d[3])
                 : "r"(a[0]), "r"(a[1]), "r"(a[2]), "r"(a[3]), "r"(b[0]), "r"(b[1]));
}
__device__ __forceinline__ uint32_t packh(float lo, float hi) {
    __half2 t = __floats2half2_rn(lo, hi);
    return *(uint32_t*)&t;
}

// ---------------------------------------------------------------------------
// Conversions
// ---------------------------------------------------------------------------
__global__ void conv_a_kernel(const float* __restrict__ X,
                              __half* __restrict__ H, int total8) {
    int t = blockIdx.x * blockDim.x + threadIdx.x;
    if (t >= total8) return;
    const int base = t * 8;
    float4 x0 = *(const float4*)(X + base);
    float4 x1 = *(const float4*)(X + base + 4);
    float xs[8] = {x0.x, x0.y, x0.z, x0.w, x1.x, x1.y, x1.z, x1.w};
    __half hs[8];
#pragma unroll
    for (int i = 0; i < 8; i++) hs[i] = __float2half_rn(xs[i]);
    *(uint4*)(H + base) = *(const uint4*)hs;
}

// All 4 weights: W [K][N] fp32 -> WT [N][K] fp16, one launch.
__global__ void split_w_all_kernel(const float* __restrict__ Wq, const float* __restrict__ Wk,
                                   const float* __restrict__ Wv, const float* __restrict__ Wo,
                                   __half* __restrict__ W3T, __half* __restrict__ WoT) {
    __shared__ float s[32][33];
    const int z = blockIdx.z;
    const float* W;
    __half* dst;
    int N, rowoff;
    if      (z == 0) { W = Wq; dst = W3T; N = 2048; rowoff = 0;    }
    else if (z == 1) { W = Wk; dst = W3T; N = 512;  rowoff = 2048; }
    else if (z == 2) { W = Wv; dst = W3T; N = 512;  rowoff = 2560; }
    else             { W = Wo; dst = WoT; N = 2048; rowoff = 0;    }
    const int n0 = blockIdx.y * 32;
    if (n0 >= N) return;
    const int k0 = blockIdx.x * 32;
    const int tx = threadIdx.x, ty = threadIdx.y;  // 32 x 8
#pragma unroll
    for (int i = 0; i < 4; i++)
        s[ty + 8 * i][tx] = W[(size_t)(k0 + ty + 8 * i) * N + n0 + tx];
    __syncthreads();
#pragma unroll
    for (int i = 0; i < 4; i++) {
        const int n = ty + 8 * i;
        dst[(size_t)(rowoff + n0 + n) * KDIM + k0 + tx] = __float2half_rn(s[tx][n]);
    }
}

// ---------------------------------------------------------------------------
// fp16 mma.sync GEMM core. CTA 128x128, BK=32, 3-stage cp.async, 8 warps.
// Two epilogues: fp32 C (out-proj) and fp16 C (QKV projection).
// ---------------------------------------------------------------------------
constexpr int GSTRIDE = 40;
constexpr int GTILE_B = 128 * GSTRIDE * 2;   // 10240 bytes
constexpr int G1STAGE_B = 2 * GTILE_B;       // 20480
constexpr int GEMM1_SMEM = 3 * G1STAGE_B;    // 61440

__device__ __forceinline__ void gemm1_load_stage(
    const __half* __restrict__ A, const __half* __restrict__ Bt,
    uint32_t stageBase, int m0, int n0, int k0, int tid) {
#pragma unroll
    for (int i = 0; i < 4; i++) {
        const int idx = tid + i * 256;      // 0..1023
        const int tile = idx >> 9;          // 0..1
        const int c = idx & 511;
        const int row = c >> 2;
        const int kc = (c & 3) * 8;
        const __half* src = (tile == 0)
            ? A  + (size_t)(m0 + row) * KDIM + k0 + kc
            : Bt + (size_t)(n0 + row) * KDIM + k0 + kc;
        const uint32_t dst = stageBase + tile * GTILE_B + (row * GSTRIDE + kc) * 2;
        CP_ASYNC16(dst, src);
    }
}

__device__ __forceinline__ void gemm1_mainloop(
    const __half* __restrict__ A, const __half* __restrict__ Bt,
    uint32_t sb, int m0, int n0, int tid, int wid, int lane,
    int mw, int nw, float acc[4][4][4]) {
    const uint32_t laneA = ((lane & 15) * GSTRIDE + (lane >> 4) * 8) * 2;
    const uint32_t laneB = ((((lane >> 4) << 3) + (lane & 7)) * GSTRIDE
                           + ((lane >> 3) & 1) * 8) * 2;

    const int T = KDIM / 32;
    gemm1_load_stage(A, Bt, sb, m0, n0, 0, tid);              CP_COMMIT();
    gemm1_load_stage(A, Bt, sb + G1STAGE_B, m0, n0, 32, tid); CP_COMMIT();

    for (int t = 0; t < T; t++) {
        const uint32_t stg = sb + (t % 3) * G1STAGE_B;
        if (t + 1 < T) { CP_WAIT(1); } else { CP_WAIT(0); }
        __syncthreads();

        const uint32_t aA = stg + 0 * GTILE_B + mw * GSTRIDE * 2 + laneA;
        const uint32_t bB = stg + 1 * GTILE_B + nw * GSTRIDE * 2 + laneB;

#pragma unroll
        for (int kk = 0; kk < 2; kk++) {
            const uint32_t ko = kk * 32;
            uint32_t fb[2][4];
#pragma unroll
            for (int p = 0; p < 2; p++)
                ldm_x4(fb[p], bB + p * 16 * GSTRIDE * 2 + ko);
#pragma unroll
            for (int i = 0; i < 4; i++) {
                uint32_t fa[4];
                ldm_x4(fa, aA + i * 16 * GSTRIDE * 2 + ko);
#pragma unroll
                for (int j = 0; j < 4; j++) {
                    const int p = j >> 1, h = (j & 1) * 2;
                    uint32_t bf[2] = {fb[p][h], fb[p][h + 1]};
                    mma16816(acc[i][j], fa, bf);
                }
            }
        }
        __syncthreads();
        if (t + 2 < T) {
            gemm1_load_stage(A, Bt, sb + ((t + 2) % 3) * G1STAGE_B,
                             m0, n0, (t + 2) * 32, tid);
            CP_COMMIT();
        }
    }
}

__global__ __launch_bounds__(256, 2)
void mma_gemm1(const __half* __restrict__ A, const __half* __restrict__ Bt,
               float* __restrict__ C, int N) {
    extern __shared__ __align__(16) uint8_t smg[];
    const uint32_t sb = smem_u32(smg);
    const int tid = threadIdx.x;
    const int wid = tid >> 5, lane = tid & 31;
    const int m0 = blockIdx.y * 128, n0 = blockIdx.x * 128;
    const int mw = (wid & 1) * 64, nw = (wid >> 1) * 32;

    float acc[4][4][4];
#pragma unroll
    for (int i = 0; i < 4; i++)
#pragma unroll
        for (int j = 0; j < 4; j++)
#pragma unroll
            for (int q = 0; q < 4; q++) acc[i][j][q] = 0.f;

    gemm1_mainloop(A, Bt, sb, m0, n0, tid, wid, lane, mw, nw, acc);

    const int g = lane >> 2, tq = lane & 3;
#pragma unroll
    for (int i = 0; i < 4; i++) {
        const int r0 = m0 + mw + i * 16 + g;
#pragma unroll
        for (int j = 0; j < 4; j++) {
            const int col = n0 + nw + j * 8 + tq * 2;
            *(float2*)(C + (size_t)r0 * N + col)       = make_float2(acc[i][j][0], acc[i][j][1]);
            *(float2*)(C + (size_t)(r0 + 8) * N + col) = make_float2(acc[i][j][2], acc[i][j][3]);
        }
    }
}

__global__ __launch_bounds__(256, 2)
void mma_gemm1h(const __half* __restrict__ A, const __half* __restrict__ Bt,
                __half* __restrict__ C, int N) {
    extern __shared__ __align__(16) uint8_t smg[];
    const uint32_t sb = smem_u32(smg);
    const int tid = threadIdx.x;
    const int wid = tid >> 5, lane = tid & 31;
    const int m0 = blockIdx.y * 128, n0 = blockIdx.x * 128;
    const int mw = (wid & 1) * 64, nw = (wid >> 1) * 32;

    float acc[4][4][4];
#pragma unroll
    for (int i = 0; i < 4; i++)
#pragma unroll
        for (int j = 0; j < 4; j++)
#pragma unroll
            for (int q = 0; q < 4; q++) acc[i][j][q] = 0.f;

    gemm1_mainloop(A, Bt, sb, m0, n0, tid, wid, lane, mw, nw, acc);

    const int g = lane >> 2, tq = lane & 3;
#pragma unroll
    for (int i = 0; i < 4; i++) {
        const int r0 = m0 + mw + i * 16 + g;
#pragma unroll
        for (int j = 0; j < 4; j++) {
            const int col = n0 + nw + j * 8 + tq * 2;
            *(uint32_t*)(C + (size_t)r0 * N + col)       = packh(acc[i][j][0], acc[i][j][1]);
            *(uint32_t*)(C + (size_t)(r0 + 8) * N + col) = packh(acc[i][j][2], acc[i][j][3]);
        }
    }
}

// ---------------------------------------------------------------------------
// RoPE + relayout from fused fp16 QKV [4096][3072].
// One thread per (bs, p): trig computed ONCE, then looped over all 20 heads.
// ---------------------------------------------------------------------------
__global__ void rope_all_kernel(const __half* __restrict__ QKVh,
                                const int* __restrict__ pos,
                                __half* __restrict__ Qh, __half* __restrict__ Kh) {
    const int idx = blockIdx.x * blockDim.x + threadIdx.x;  // bs*64 + p
    if (idx >= MROWS * 64) return;
    const int p = idx & 63;
    const int bs = idx >> 6;
    const int b = bs >> 11, s = bs & 2047;

    const float fpos = (float)pos[bs];
    const float inv = powf(10000.f, -(float)p * (1.f / 64.f));
    float sn, c;
    sincosf(fpos * inv, &sn, &c);

    const __half* row = QKVh + (size_t)bs * N_QKV;

    // 16 Q heads (pre-scaled by QK_SCALE)
#pragma unroll 4
    for (int hh = 0; hh < NHEADS; hh++) {
        const float x1 = __half2float(row[hh * HDIM + p]);
        const float x2 = __half2float(row[hh * HDIM + p + 64]);
        const size_t obase = ((size_t)(b * NHEADS + hh) * SEQ + s) * HDIM;
        Qh[obase + p]      = __float2half_rn((x1 * c - x2 * sn) * QK_SCALE);
        Qh[obase + p + 64] = __float2half_rn((x2 * c + x1 * sn) * QK_SCALE);
    }
    // 4 K heads
#pragma unroll
    for (int kv = 0; kv < NKVH; kv++) {
        const float x1 = __half2float(row[HIDDEN + kv * HDIM + p]);
        const float x2 = __half2float(row[HIDDEN + kv * HDIM + p + 64]);
        const size_t obase = ((size_t)(b * NKVH + kv) * SEQ + s) * HDIM;
        Kh[obase + p]      = __float2half_rn(x1 * c - x2 * sn);
        Kh[obase + p + 64] = __float2half_rn(x2 * c + x1 * sn);
    }
}

// V (fp16 QKV cols [2560,3072)) -> Vth fp16 [B,kvh,D,S] (transpose)
__global__ void vt_split_kernel(const __half* __restrict__ QKVh,
                                __half* __restrict__ TH) {
    __shared__ __half s[32][34];
    const int s0 = blockIdx.x * 32, d0 = blockIdx.y * 32;
    const int b = blockIdx.z >> 2, kv = blockIdx.z & 3;
    const int tx = threadIdx.x, ty = threadIdx.y;
#pragma unroll
    for (int i = 0; i < 4; i++) {
        const int ss = s0 + ty + 8 * i;
        s[ty + 8 * i][tx] =
            QKVh[(size_t)(b * SEQ + ss) * N_QKV + HIDDEN + NKVH * HDIM + kv * HDIM + d0 + tx];
    }
    __syncthreads();
#pragma unroll
    for (int i = 0; i < 4; i++) {
        const int d = ty + 8 * i;
        const size_t o = ((size_t)(b * NKVH + kv) * HDIM + d0 + d) * SEQ + s0 + tx;
        TH[o] = s[tx][d];
    }
}

// ---------------------------------------------------------------------------
// Tensor-core flash attention (causal, GQA; all operands single fp16).
// BQ=128, BK=64, 256 threads, double-buffered cp.async KV.
// ---------------------------------------------------------------------------
constexpr int ASTR = 136;
constexpr int VSTR = 72;
constexpr int AQ_H = 0;
constexpr int AKV0 = 128 * ASTR * 2;                 // 34816
constexpr int AK_H = 0;
constexpr int AV_H = 64 * ASTR * 2;                  // 17408
constexpr int KVBUF = AV_H + 128 * VSTR * 2;         // 35840
constexpr int ATTN_SMEM = AKV0 + 2 * KVBUF;          // 106496

__device__ __forceinline__ void attn_load_kv(
    const __half* __restrict__ Kh, const __half* __restrict__ Vth,
    uint32_t bufBase, size_t kbase, size_t vtbase, int k0, int tid) {
#pragma unroll
    for (int i = 0; i < 8; i++) {
        const int idx = tid + i * 256;
        if (idx < 1024) {
            const int row = idx >> 4, c = idx & 15;
            const __half* src = Kh + kbase + (size_t)(k0 + row) * HDIM + c * 8;
            const uint32_t dst = bufBase + AK_H + (row * ASTR + c * 8) * 2;
            CP_ASYNC16(dst, src);
        } else {
            const int v = idx - 1024;
            const int row = v >> 3, c = v & 7;
            const __half* src = Vth + vtbase + (size_t)row * SEQ + k0 + c * 8;
            const uint32_t dst = bufBase + AV_H + (row * VSTR + c * 8) * 2;
            CP_ASYNC16(dst, src);
        }
    }
}

__global__ __launch_bounds__(256, 1)
void attn_mma_kernel(const __half* __restrict__ Qh,
                     const __half* __restrict__ Kh, const __half* __restrict__ Vth,
                     __half* __restrict__ Ch) {
    extern __shared__ __align__(16) uint8_t smb[];
    const uint32_t sb = smem_u32(smb);
    const int tid = threadIdx.x;
    const int wid = tid >> 5, lane = tid & 31;
    const int g = lane >> 2, tq = lane & 3;

    const int qt = gridDim.x - 1 - blockIdx.x;
    const int h = blockIdx.y, b = blockIdx.z;
    const int kvh = h >> 2;
    const int q0 = qt * 128;
    const int nkt = 2 * qt + 2;

    const size_t qbase  = ((size_t)(b * NHEADS + h) * SEQ + q0) * HDIM;
    const size_t kbase  = ((size_t)(b * NKVH + kvh) * SEQ) * HDIM;
    const size_t vtbase = ((size_t)(b * NKVH + kvh) * HDIM) * SEQ;

#pragma unroll
    for (int i = 0; i < 8; i++) {
        const int idx = tid + i * 256;
        const int row = idx >> 4, c = idx & 15;
        const __half* src = Qh + qbase + (size_t)row * HDIM + c * 8;
        const uint32_t dst = sb + AQ_H + (row * ASTR + c * 8) * 2;
        CP_ASYNC16(dst, src);
    }
    CP_COMMIT();
    attn_load_kv(Kh, Vth, sb + AKV0,         kbase, vtbase, 0,  tid); CP_COMMIT();
    attn_load_kv(Kh, Vth, sb + AKV0 + KVBUF, kbase, vtbase, 64, tid); CP_COMMIT();

    CP_WAIT(2);
    __syncthreads();
    uint32_t qf[8][4];
    {
        const uint32_t la = ((wid * 16 + (lane & 15)) * ASTR + (lane >> 4) * 8) * 2;
#pragma unroll
        for (int kk = 0; kk < 8; kk++)
            ldm_x4(qf[kk], sb + AQ_H + la + kk * 32);
    }

    float o[16][4];
#pragma unroll
    for (int jj = 0; jj < 16; jj++)
#pragma unroll
        for (int q = 0; q < 4; q++) o[jj][q] = 0.f;
    float m0 = -1e30f, m1 = -1e30f, sl0 = 0.f, sl1 = 0.f;

    const int r0 = q0 + wid * 16 + g;
    const uint32_t laneNK = ((lane >> 4) * 8 + (lane & 7));
    const uint32_t laneKhi = ((lane >> 3) & 1) * 8;

    for (int kt = 0; kt < nkt; kt++) {
        const int k0 = kt * 64;
        const uint32_t buf = sb + AKV0 + (kt & 1) * KVBUF;
        if (kt + 1 < nkt) { CP_WAIT(1); } else { CP_WAIT(0); }
        __syncthreads();

        // ---- S = Q K^T ----
        float sacc[8][4];
#pragma unroll
        for (int j = 0; j < 8; j++)
#pragma unroll
            for (int q = 0; q < 4; q++) sacc[j][q] = 0.f;

#pragma unroll
        for (int kk = 0; kk < 8; kk++) {
#pragma unroll
            for (int p = 0; p < 4; p++) {
                const uint32_t off = ((p * 16 + laneNK) * ASTR + laneKhi) * 2 + kk * 32;
                uint32_t fk[4];
                ldm_x4(fk, buf + AK_H + off);
                uint32_t b0[2] = {fk[0], fk[1]}, b1[2] = {fk[2], fk[3]};
                mma16816(sacc[2 * p],     qf[kk], b0);
                mma16816(sacc[2 * p + 1], qf[kk], b1);
            }
        }

        // ---- causal mask ----
        if (kt >= nkt - 2) {
#pragma unroll
            for (int j = 0; j < 8; j++) {
#pragma unroll
                for (int e = 0; e < 2; e++) {
                    const int col = k0 + j * 8 + tq * 2 + e;
                    if (col > r0)     sacc[j][e]     = -1e30f;
                    if (col > r0 + 8) sacc[j][2 + e] = -1e30f;
                }
            }
        }

        // ---- online softmax ----
        float mt0 = -1e30f, mt1 = -1e30f;
#pragma unroll
        for (int j = 0; j < 8; j++) {
            mt0 = fmaxf(mt0, fmaxf(sacc[j][0], sacc[j][1]));
            mt1 = fmaxf(mt1, fmaxf(sacc[j][2], sacc[j][3]));
        }
        mt0 = fmaxf(mt0, __shfl_xor_sync(0xffffffffu, mt0, 1));
        mt0 = fmaxf(mt0, __shfl_xor_sync(0xffffffffu, mt0, 2));
        mt1 = fmaxf(mt1, __shfl_xor_sync(0xffffffffu, mt1, 1));
        mt1 = fmaxf(mt1, __shfl_xor_sync(0xffffffffu, mt1, 2));
        const float mn0 = fmaxf(m0, mt0), mn1 = fmaxf(m1, mt1);
        const float al0 = __expf(m0 - mn0), al1 = __expf(m1 - mn1);
        float s0 = 0.f, s1 = 0.f;
#pragma unroll
        for (int j = 0; j < 8; j++) {
            sacc[j][0] = __expf(sacc[j][0] - mn0);
            sacc[j][1] = __expf(sacc[j][1] - mn0);
            sacc[j][2] = __expf(sacc[j][2] - mn1);
            sacc[j][3] = __expf(sacc[j][3] - mn1);
            s0 += sacc[j][0] + sacc[j][1];
            s1 += sacc[j][2] + sacc[j][3];
        }
        s0 += __shfl_xor_sync(0xffffffffu, s0, 1);
        s0 += __shfl_xor_sync(0xffffffffu, s0, 2);
        s1 += __shfl_xor_sync(0xffffffffu, s1, 1);
        s1 += __shfl_xor_sync(0xffffffffu, s1, 2);
        sl0 = sl0 * al0 + s0;  sl1 = sl1 * al1 + s1;
        m0 = mn0;              m1 = mn1;
#pragma unroll
        for (int jj = 0; jj < 16; jj++) {
            o[jj][0] *= al0; o[jj][1] *= al0;
            o[jj][2] *= al1; o[jj][3] *= al1;
        }

        // ---- P fragments ----
        uint32_t ph[4][4];
#pragma unroll
        for (int kk2 = 0; kk2 < 4; kk2++) {
            const int j0 = 2 * kk2, j1 = j0 + 1;
            ph[kk2][0] = packh(sacc[j0][0], sacc[j0][1]);
            ph[kk2][1] = packh(sacc[j0][2], sacc[j0][3]);
            ph[kk2][2] = packh(sacc[j1][0], sacc[j1][1]);
            ph[kk2][3] = packh(sacc[j1][2], sacc[j1][3]);
        }

        // ---- O += P V ----
#pragma unroll
        for (int kk2 = 0; kk2 < 4; kk2++) {
#pragma unroll
            for (int p = 0; p < 8; p++) {
                const uint32_t off = ((p * 16 + laneNK) * VSTR + laneKhi + kk2 * 16) * 2;
                uint32_t fv[4];
                ldm_x4(fv, buf + AV_H + off);
                uint32_t b0[2] = {fv[0], fv[1]}, b1[2] = {fv[2], fv[3]};
                mma16816(o[2 * p],     ph[kk2], b0);
                mma16816(o[2 * p + 1], ph[kk2], b1);
            }
        }

        __syncthreads();
        if (kt + 2 < nkt) {
            attn_load_kv(Kh, Vth, sb + AKV0 + (kt & 1) * KVBUF,
                         kbase, vtbase, (kt + 2) * 64, tid);
            CP_COMMIT();
        }
    }

    // ---- epilogue: single fp16 ctx ----
    const float inv0 = 1.f / sl0, inv1 = 1.f / sl1;
#pragma unroll
    for (int jj = 0; jj < 16; jj++) {
        const int d = jj * 8 + tq * 2;
        const size_t o0 = (size_t)(b * SEQ + r0) * HIDDEN + h * HDIM + d;
        const size_t o1 = o0 + (size_t)8 * HIDDEN;
        *(uint32_t*)(Ch + o0) = packh(o[jj][0] * inv0, o[jj][1] * inv0);
        *(uint32_t*)(Ch + o1) = packh(o[jj][2] * inv1, o[jj][3] * inv1);
    }
}

// ---------------------------------------------------------------------------
// Launch
// ---------------------------------------------------------------------------
extern "C" void kernel_launch(void* const* d_in, const int* in_sizes, int n_in,
                              void* d_out, int out_size) {
    const float* X   = (const float*)d_in[0];
    const int*   pos = (const int*)  d_in[1];
    const float* Wq  = (const float*)d_in[2];
    const float* Wk  = (const float*)d_in[3];
    const float* Wv  = (const float*)d_in[4];
    const float* Wo  = (const float*)d_in[5];
    float* out = (float*)d_out;

    __half *QKVh, *Xh, *Ch, *W3, *WoT;
    __half *Qbh, *Kbh, *Vth;
    cudaGetSymbolAddress((void**)&QKVh, g_QKVh);
    cudaGetSymbolAddress((void**)&Xh, g_Xh);
    cudaGetSymbolAddress((void**)&Ch, g_Ch);
    cudaGetSymbolAddress((void**)&W3, g_W3T);
    cudaGetSymbolAddress((void**)&WoT, g_WoT);
    cudaGetSymbolAddress((void**)&Qbh, g_Qbh);
    cudaGetSymbolAddress((void**)&Kbh, g_Kbh);
    cudaGetSymbolAddress((void**)&Vth, g_Vth);

    const int total8 = MROWS * KDIM / 8;
    conv_a_kernel<<<(total8 + 255) / 256, 256>>>(X, Xh, total8);
    split_w_all_kernel<<<dim3(64, 64, 4), dim3(32, 8)>>>(Wq, Wk, Wv, Wo, W3, WoT);

    cudaFuncSetAttribute(mma_gemm1, cudaFuncAttributeMaxDynamicSharedMemorySize, GEMM1_SMEM);
    cudaFuncSetAttribute(mma_gemm1h, cudaFuncAttributeMaxDynamicSharedMemorySize, GEMM1_SMEM);

    // Fused QKV projection -> fp16 directly
    mma_gemm1h<<<dim3(N_QKV / 128, 32), 256, GEMM1_SMEM>>>(Xh, W3, QKVh, N_QKV);

    // RoPE (trig hoisted across heads) + V transpose
    rope_all_kernel<<<(MROWS * 64 + 255) / 256, 256>>>(QKVh, pos, Qbh, Kbh);
    vt_split_kernel<<<dim3(64, 4, 8), dim3(32, 8)>>>(QKVh, Vth);

    // Flash attention
    cudaFuncSetAttribute(attn_mma_kernel, cudaFuncAttributeMaxDynamicSharedMemorySize, ATTN_SMEM);
    attn_mma_kernel<<<dim3(SEQ / 128, NHEADS, BATCH), 256, ATTN_SMEM>>>(
        Qbh, Kbh, Vth, Ch);

    // Output projection (fp32 out)
    mma_gemm1<<<dim3(16, 32), 256, GEMM1_SMEM>>>(Ch, WoT, out, 2048);
}